// round 8
// baseline (speedup 1.0000x reference)
#include <cuda_runtime.h>
#include <cstdint>

#define DI __device__ __forceinline__

DI unsigned f2t(float x) { unsigned u; asm("cvt.rna.tf32.f32 %0, %1;" : "=r"(u) : "f"(x)); return u; }

DI void mma8(float c[4], const unsigned a[4], const unsigned b[2]) {
    asm("mma.sync.aligned.m16n8k8.row.col.f32.tf32.tf32.f32 "
        "{%0,%1,%2,%3}, {%4,%5,%6,%7}, {%8,%9}, {%0,%1,%2,%3};"
        : "+f"(c[0]), "+f"(c[1]), "+f"(c[2]), "+f"(c[3])
        : "r"(a[0]), "r"(a[1]), "r"(a[2]), "r"(a[3]), "r"(b[0]), "r"(b[1]));
}

DI uint32_t smem_u32(const void* p) {
    uint32_t a;
    asm("{ .reg .u64 t; cvta.to.shared.u64 t, %1; cvt.u32.u64 %0, t; }" : "=r"(a) : "l"(p));
    return a;
}

DI void cp_async16(uint32_t dst, const void* src) {
    asm volatile("cp.async.ca.shared.global [%0], [%1], 16;" :: "r"(dst), "l"(src) : "memory");
}
#define CP_COMMIT() asm volatile("cp.async.commit_group;" ::: "memory")
#define CP_WAIT0()  asm volatile("cp.async.wait_group 0;" ::: "memory")
#define CP_WAIT1()  asm volatile("cp.async.wait_group 1;" ::: "memory")

// ---- scratch (device globals; no allocations allowed) ----
#define KC 8
__device__ float g_fc1[2][4096 * 256];
__device__ float g_fc2[2][4096 * 128];
__device__ float g_h  [2][4096 * 64];
__device__ float g_ht [2][64 * 4096];
__device__ float g_aggp[2][KC][4096 * 64];
__device__ int   g_degp[2][KC][4096];
__device__ float g_part[512];
__device__ float g_w1cv[2][256 * 4096];

// ============================================================================
// Pre-pass: w1 -> RNA tf32 (stored as fp32 bits). fc1 loads B raw via cp.async.
// ============================================================================
__global__ void cvt_w1(const float* __restrict__ w0, const float* __restrict__ w1,
                       float* __restrict__ out)
{
    int idx = blockIdx.x * blockDim.x + threadIdx.x;      // float4 id, 2*262144 total
    int z = idx >= 262144;
    int li = idx - z * 262144;
    float4 v = ((const float4*)(z ? w1 : w0))[li];
    float4 o;
    o.x = __uint_as_float(f2t(v.x));
    o.y = __uint_as_float(f2t(v.y));
    o.z = __uint_as_float(f2t(v.z));
    o.w = __uint_as_float(f2t(v.w));
    ((float4*)out)[(size_t)z * 262144 + li] = o;
}

// ============================================================================
// fc1: C[4096,256] = X @ W1cv^T + b.
// BM=128, BN=64, BK=32, 128 thr (4 warps, each 32x64 warp tile).
// A: LDG->f2t->STS, dual-stage smem, register prefetch 2 chunks ahead.
// B: cp.async TRIPLE-stage smem, 2 groups in flight, wait_group 1
//    (depth-2 pipeline: overlap ~2 chunks > DRAM latency).
// grid (nt=4, mt=32, z=2) = 256 CTAs.
// ============================================================================
#define LD1 36
#define AS1(s, r, c) dsm[(s) * (128 * LD1) + (r) * LD1 + (c)]
#define BS1(s, r, c) dsm[2 * 128 * LD1 + (s) * (64 * LD1) + (r) * LD1 + (c)]

__global__ void __launch_bounds__(128, 3)
fc1_tf(const float* __restrict__ A0, const float* __restrict__ A1,
       const float* __restrict__ Bcv,
       const float* __restrict__ bias0, const float* __restrict__ bias1,
       float* __restrict__ C)
{
    extern __shared__ unsigned dsm[];
    constexpr int K = 4096, BK = 32;
    const int tid = threadIdx.x, warp = tid >> 5, lane = tid & 31;
    const int wm = warp;                               // 4 m-warps, 1 n-warp
    const int gid = lane >> 2, tig = lane & 3;
    const int z = blockIdx.z;
    const size_t m0 = (size_t)blockIdx.y * 128;
    const size_t n0 = (size_t)blockIdx.x * 64;
    const int ax = tid & 7, ay = tid >> 3;             // 8 float4/row, 16 rows/pass

    const float* A = (z ? A1 : A0) + (m0 + ay) * (size_t)K + ax * 4;
    const float* B = Bcv + (size_t)z * 256 * 4096 + (n0 + ay) * (size_t)K + ax * 4;
    const float* bias = z ? bias1 : bias0;
    float* Cb = C + (size_t)z * 4096 * 256;

    const uint32_t bsm = smem_u32(dsm) + (2 * 128 * LD1) * 4;

    float acc[2][8][4];
#pragma unroll
    for (int i = 0; i < 2; i++)
#pragma unroll
        for (int j = 0; j < 8; j++)
#pragma unroll
            for (int e = 0; e < 4; e++) acc[i][j][e] = 0.f;

    float4 ra[8];
    const int nIter = K / BK;                          // 128

    auto ldA = [&](int it) {
        const size_t ko = (size_t)it * BK;
#pragma unroll
        for (int p = 0; p < 8; p++)
            ra[p] = *(const float4*)(A + (size_t)p * 16 * K + ko);
    };
    auto stA = [&](int s) {
#pragma unroll
        for (int p = 0; p < 8; p++) {
            uint4 t;
            t.x = f2t(ra[p].x); t.y = f2t(ra[p].y);
            t.z = f2t(ra[p].z); t.w = f2t(ra[p].w);
            *(uint4*)&AS1(s, p * 16 + ay, ax * 4) = t;
        }
    };
    auto cpB = [&](int it) {
        const size_t ko = (size_t)it * BK;
        const int s = it % 3;
#pragma unroll
        for (int p = 0; p < 4; p++) {
            uint32_t dst = bsm + (uint32_t)(s * 64 * LD1 + (p * 16 + ay) * LD1 + ax * 4) * 4;
            cp_async16(dst, B + (size_t)p * 16 * K + ko);
        }
    };

    // prologue: B groups 0 and 1 in flight; A chunk0 staged, chunk1 in regs
    ldA(0);
    cpB(0); CP_COMMIT();
    cpB(1); CP_COMMIT();
    stA(0);
    ldA(1);
    CP_WAIT1();                     // group 0 done
    __syncthreads();

    for (int it = 0; it < nIter; it++) {
        const int curA = it & 1;
        const int curB = it % 3;
        if (it + 2 < nIter) { cpB(it + 2); CP_COMMIT(); }
        if (it + 1 < nIter) stA(curA ^ 1);
        if (it + 2 < nIter) ldA(it + 2);
#pragma unroll
        for (int ks = 0; ks < BK / 8; ks++) {
            unsigned af[2][4], bf[8][2];
#pragma unroll
            for (int mt = 0; mt < 2; mt++) {
                int rr = wm * 32 + mt * 16 + gid;
                af[mt][0] = AS1(curA, rr,     ks * 8 + tig);
                af[mt][1] = AS1(curA, rr + 8, ks * 8 + tig);
                af[mt][2] = AS1(curA, rr,     ks * 8 + tig + 4);
                af[mt][3] = AS1(curA, rr + 8, ks * 8 + tig + 4);
            }
#pragma unroll
            for (int nt = 0; nt < 8; nt++) {
                int cc = nt * 8 + gid;
                bf[nt][0] = BS1(curB, cc, ks * 8 + tig);
                bf[nt][1] = BS1(curB, cc, ks * 8 + tig + 4);
            }
#pragma unroll
            for (int mt = 0; mt < 2; mt++)
#pragma unroll
                for (int nt = 0; nt < 8; nt++)
                    mma8(acc[mt][nt], af[mt], bf[nt]);
        }
        // ensure group it+1 is complete before next iteration reads it
        if (it + 2 < nIter) CP_WAIT1(); else CP_WAIT0();
        __syncthreads();
    }

#pragma unroll
    for (int mt = 0; mt < 2; mt++)
#pragma unroll
        for (int nt = 0; nt < 8; nt++) {
            size_t row = m0 + wm * 32 + mt * 16 + gid;
            size_t col = n0 + nt * 8 + tig * 2;
#pragma unroll
            for (int e = 0; e < 4; e++) {
                size_t r = row + (size_t)(e >> 1) * 8;
                size_t c = col + (size_t)(e & 1);
                Cb[r * 256 + c] = acc[mt][nt][e] + bias[c];
            }
        }
}

// ============================================================================
// Single-buffered split-tf32 GEMM for fc2/fc3 (cheap layers, fp32-class acc).
// WT path stores the transposed copy pre-rounded to tf32 (feeds agg raw path).
// ============================================================================
template<int BM, int BN, int BK, int NS, bool RELU, bool WT>
__global__ void __launch_bounds__((BM / 32) * (BN / 32) * 32)
gemm_tn(const float* __restrict__ A0, const float* __restrict__ A1,
        const float* __restrict__ B0, const float* __restrict__ B1,
        const float* __restrict__ bias0, const float* __restrict__ bias1,
        float* __restrict__ C0, float* __restrict__ C1,
        float* __restrict__ T0, float* __restrict__ T1,
        int M, int N, int K)
{
    constexpr int WM = BM / 32, WN = BN / 32, NW = WM * WN, NT = NW * 32;
    constexpr int LD = BK + 4;
    constexpr int F4 = BK / 4, RA = NT / F4, PA = BM / RA, PB = BN / RA;

    const int z = blockIdx.z;
    const float* A = z ? A1 : A0;
    const float* B = z ? B1 : B0;
    const float* bias = z ? bias1 : bias0;
    float* C = z ? C1 : C0;
    float* T = z ? T1 : T0;

    __shared__ unsigned As[NS][BM][LD];
    __shared__ unsigned Bs[NS][BN][LD];

    const int tid = threadIdx.x, warp = tid >> 5, lane = tid & 31;
    const int wm = warp % WM, wn = warp / WM;
    const int gid = lane >> 2, tig = lane & 3;
    const size_t m0 = (size_t)blockIdx.x * BM;
    const size_t n0 = (size_t)blockIdx.y * BN;
    const int ax = tid % F4, ay = tid / F4;

    float acc[2][4][4];
#pragma unroll
    for (int i = 0; i < 2; i++)
#pragma unroll
        for (int j = 0; j < 4; j++)
#pragma unroll
            for (int e = 0; e < 4; e++) acc[i][j][e] = 0.f;

    float4 ra[PA], rb[PB];
#pragma unroll
    for (int p = 0; p < PA; p++)
        ra[p] = *(const float4*)(A + (m0 + p * RA + ay) * K + ax * 4);
#pragma unroll
    for (int p = 0; p < PB; p++)
        rb[p] = *(const float4*)(B + (n0 + p * RA + ay) * K + ax * 4);

    for (int k0 = 0; k0 < K; k0 += BK) {
#pragma unroll
        for (int p = 0; p < PA; p++) {
            int row = p * RA + ay;
            unsigned h0 = f2t(ra[p].x), h1 = f2t(ra[p].y), h2 = f2t(ra[p].z), h3 = f2t(ra[p].w);
            As[0][row][ax * 4 + 0] = h0; As[0][row][ax * 4 + 1] = h1;
            As[0][row][ax * 4 + 2] = h2; As[0][row][ax * 4 + 3] = h3;
            if (NS == 2) {
                As[NS - 1][row][ax * 4 + 0] = f2t(ra[p].x - __uint_as_float(h0));
                As[NS - 1][row][ax * 4 + 1] = f2t(ra[p].y - __uint_as_float(h1));
                As[NS - 1][row][ax * 4 + 2] = f2t(ra[p].z - __uint_as_float(h2));
                As[NS - 1][row][ax * 4 + 3] = f2t(ra[p].w - __uint_as_float(h3));
            }
        }
#pragma unroll
        for (int p = 0; p < PB; p++) {
            int row = p * RA + ay;
            unsigned h0 = f2t(rb[p].x), h1 = f2t(rb[p].y), h2 = f2t(rb[p].z), h3 = f2t(rb[p].w);
            Bs[0][row][ax * 4 + 0] = h0; Bs[0][row][ax * 4 + 1] = h1;
            Bs[0][row][ax * 4 + 2] = h2; Bs[0][row][ax * 4 + 3] = h3;
            if (NS == 2) {
                Bs[NS - 1][row][ax * 4 + 0] = f2t(rb[p].x - __uint_as_float(h0));
                Bs[NS - 1][row][ax * 4 + 1] = f2t(rb[p].y - __uint_as_float(h1));
                Bs[NS - 1][row][ax * 4 + 2] = f2t(rb[p].z - __uint_as_float(h2));
                Bs[NS - 1][row][ax * 4 + 3] = f2t(rb[p].w - __uint_as_float(h3));
            }
        }
        __syncthreads();

        if (k0 + BK < K) {
#pragma unroll
            for (int p = 0; p < PA; p++)
                ra[p] = *(const float4*)(A + (m0 + p * RA + ay) * K + (k0 + BK) + ax * 4);
#pragma unroll
            for (int p = 0; p < PB; p++)
                rb[p] = *(const float4*)(B + (n0 + p * RA + ay) * K + (k0 + BK) + ax * 4);
        }

#pragma unroll
        for (int ks = 0; ks < BK / 8; ks++) {
            unsigned af[NS][2][4], bf[NS][4][2];
#pragma unroll
            for (int s = 0; s < NS; s++) {
#pragma unroll
                for (int mt = 0; mt < 2; mt++) {
                    int rr = wm * 32 + mt * 16 + gid;
                    af[s][mt][0] = As[s][rr    ][ks * 8 + tig];
                    af[s][mt][1] = As[s][rr + 8][ks * 8 + tig];
                    af[s][mt][2] = As[s][rr    ][ks * 8 + tig + 4];
                    af[s][mt][3] = As[s][rr + 8][ks * 8 + tig + 4];
                }
#pragma unroll
                for (int nt = 0; nt < 4; nt++) {
                    int cc = wn * 32 + nt * 8 + gid;
                    bf[s][nt][0] = Bs[s][cc][ks * 8 + tig];
                    bf[s][nt][1] = Bs[s][cc][ks * 8 + tig + 4];
                }
            }
#pragma unroll
            for (int mt = 0; mt < 2; mt++)
#pragma unroll
                for (int nt = 0; nt < 4; nt++) {
                    mma8(acc[mt][nt], af[0][mt], bf[0][nt]);
                    if (NS == 2) {
                        mma8(acc[mt][nt], af[0][mt], bf[NS - 1][nt]);
                        mma8(acc[mt][nt], af[NS - 1][mt], bf[0][nt]);
                    }
                }
        }
        __syncthreads();
    }

#pragma unroll
    for (int mt = 0; mt < 2; mt++) {
#pragma unroll
        for (int nt = 0; nt < 4; nt++) {
            size_t row = m0 + wm * 32 + mt * 16 + gid;
            size_t col = n0 + wn * 32 + nt * 8 + tig * 2;
#pragma unroll
            for (int e = 0; e < 4; e++) {
                size_t r = row + (size_t)(e >> 1) * 8;
                size_t c = col + (size_t)(e & 1);
                float v = acc[mt][nt][e] + bias[c];
                if (RELU) v = fmaxf(v, 0.f);
                C[r * N + c] = v;
                if (WT) T[c * (size_t)M + r] = __uint_as_float(f2t(v));
            }
        }
    }
}

// ============================================================================
// Split-K masked aggregation partial — RNA cvt on masked alpha, B raw
// (Ht pre-rounded by fc3 epilogue).
// ============================================================================
template<int BM, int BN, int BK>
__global__ void __launch_bounds__(128)
agg_part(const int* __restrict__ adjA, const int* __restrict__ adjB,
         const float* __restrict__ alpha,
         const float* __restrict__ HtA, const float* __restrict__ HtB,
         float* __restrict__ aggp, int* __restrict__ degp, int K)
{
    constexpr int WM = BM / 32, WN = BN / 32, NT = WM * WN * 32;
    constexpr int LD = BK + 4;
    constexpr int F4 = BK / 4, RA = NT / F4, PA = BM / RA, PB = BN / RA;

    const int z = blockIdx.z;
    const int kc = blockIdx.y;
    const int* adj = z ? adjB : adjA;
    const float* Ht = z ? HtB : HtA;
    const int KCH = K / KC;
    const size_t kbase = (size_t)kc * KCH;

    __shared__ unsigned As[2][BM][LD];
    __shared__ unsigned Bs[2][BN][LD];
    __shared__ int sdeg[BM];

    const int tid = threadIdx.x, warp = tid >> 5, lane = tid & 31;
    const int wm = warp % WM, wn = warp / WM;
    const int gid = lane >> 2, tig = lane & 3;
    const size_t m0 = (size_t)blockIdx.x * BM;
    const int ax = tid % F4, ay = tid / F4;

    if (tid < BM) sdeg[tid] = 0;

    float acc[WM][WN * 2][4];
#pragma unroll
    for (int i = 0; i < WM; i++)
#pragma unroll
        for (int j = 0; j < WN * 2; j++)
#pragma unroll
            for (int e = 0; e < 4; e++) acc[i][j][e] = 0.f;

    int cnt[PA];
#pragma unroll
    for (int p = 0; p < PA; p++) cnt[p] = 0;

    int4 rma[PA]; float4 rva[PA]; uint4 rb[PB];
    const int nIter = KCH / BK;

    auto ldA = [&](int it) {
#pragma unroll
        for (int p = 0; p < PA; p++) {
            size_t g = (m0 + p * RA + ay) * (size_t)K + kbase + (size_t)it * BK + ax * 4;
            rma[p] = *(const int4*)(adj + g);
            rva[p] = *(const float4*)(alpha + g);
        }
#pragma unroll
        for (int p = 0; p < PB; p++)
            rb[p] = *(const uint4*)(Ht + (size_t)(p * RA + ay) * K + kbase + (size_t)it * BK + ax * 4);
    };
    auto stA = [&](int buf) {
#pragma unroll
        for (int p = 0; p < PA; p++) {
            int row = p * RA + ay;
            int mx = (rma[p].x == 1), my = (rma[p].y == 1);
            int mz = (rma[p].z == 1), mw = (rma[p].w == 1);
            cnt[p] += mx + my + mz + mw;
            As[buf][row][ax * 4 + 0] = f2t(mx ? rva[p].x : 0.f);
            As[buf][row][ax * 4 + 1] = f2t(my ? rva[p].y : 0.f);
            As[buf][row][ax * 4 + 2] = f2t(mz ? rva[p].z : 0.f);
            As[buf][row][ax * 4 + 3] = f2t(mw ? rva[p].w : 0.f);
        }
#pragma unroll
        for (int p = 0; p < PB; p++)
            *(uint4*)&Bs[buf][p * RA + ay][ax * 4] = rb[p];
    };

    ldA(0); stA(0);
    if (nIter > 1) ldA(1);
    __syncthreads();

    for (int it = 0; it < nIter; it++) {
        const int cur = it & 1;
        if (it + 1 < nIter) stA(cur ^ 1);
        if (it + 2 < nIter) ldA(it + 2);
#pragma unroll
        for (int ks = 0; ks < BK / 8; ks++) {
            unsigned af[WM][4], bf[WN * 2][2];
#pragma unroll
            for (int mt = 0; mt < WM; mt++) {
                int rr = wm * 32 + mt * 16 + gid;
                af[mt][0] = As[cur][rr    ][ks * 8 + tig];
                af[mt][1] = As[cur][rr + 8][ks * 8 + tig];
                af[mt][2] = As[cur][rr    ][ks * 8 + tig + 4];
                af[mt][3] = As[cur][rr + 8][ks * 8 + tig + 4];
            }
#pragma unroll
            for (int nt = 0; nt < WN * 2; nt++) {
                int cc = wn * 32 + nt * 8 + gid;
                bf[nt][0] = Bs[cur][cc][ks * 8 + tig];
                bf[nt][1] = Bs[cur][cc][ks * 8 + tig + 4];
            }
#pragma unroll
            for (int mt = 0; mt < WM; mt++)
#pragma unroll
                for (int nt = 0; nt < WN * 2; nt++)
                    mma8(acc[mt][nt], af[mt], bf[nt]);
        }
        __syncthreads();
    }

#pragma unroll
    for (int p = 0; p < PA; p++) atomicAdd(&sdeg[p * RA + ay], cnt[p]);
    __syncthreads();

    float* aout = aggp + ((size_t)z * KC + kc) * 4096 * 64;
    int*   dout = degp + ((size_t)z * KC + kc) * 4096;
    if (tid < BM) dout[m0 + tid] = sdeg[tid];
#pragma unroll
    for (int mt = 0; mt < WM; mt++)
#pragma unroll
        for (int nt = 0; nt < WN * 2; nt++) {
            size_t row = m0 + wm * 32 + mt * 16 + gid;
            size_t col = wn * 32 + nt * 8 + tig * 2;
#pragma unroll
            for (int e = 0; e < 4; e++) {
                size_t r = row + (size_t)(e >> 1) * 8;
                size_t c = col + (size_t)(e & 1);
                aout[r * 64 + c] = acc[mt][nt][e];
            }
        }
}

// ============================================================================
// Classifier stage 1, FUSED with aggregation finish:
//   v_i = deg ? (sum_kc aggp)*W00/deg + h : 0 ;  s_c += v_i * clf_w[c,i]
// Deterministic (fixed order), no intermediate g_new materialization.
// ============================================================================
__global__ void clf_partial(const float* __restrict__ aggp, const int* __restrict__ degp,
                            const float* __restrict__ HA, const float* __restrict__ HB,
                            const float* __restrict__ Wp,
                            const float* __restrict__ w, float* __restrict__ part)
{
    const int L = 4096 * 64;
    const int TOT = 2 * L;
    const int chunk = 2048;
    int base = blockIdx.x * chunk;
    const float W00 = Wp[0];
    float s0 = 0.f, s1 = 0.f;
    for (int i = base + threadIdx.x; i < base + chunk; i += blockDim.x) {
        int z = i >= L;
        int li = i - z * L;
        int r = li >> 6;
        const float* ap = aggp + (size_t)z * KC * L;
        const int* dp = degp + (size_t)z * KC * 4096;
        float s = 0.f; int d = 0;
#pragma unroll
        for (int kc = 0; kc < KC; kc++) {
            s += ap[(size_t)kc * L + li];
            d += dp[kc * 4096 + r];
        }
        const float* H = z ? HB : HA;
        float v = d ? s * W00 / (float)d + H[li] : 0.f;
        s0 += v * w[i];
        s1 += v * w[TOT + i];
    }
    __shared__ float sm[8][2];
#pragma unroll
    for (int o = 16; o; o >>= 1) {
        s0 += __shfl_down_sync(0xffffffffu, s0, o);
        s1 += __shfl_down_sync(0xffffffffu, s1, o);
    }
    if ((threadIdx.x & 31) == 0) { sm[threadIdx.x >> 5][0] = s0; sm[threadIdx.x >> 5][1] = s1; }
    __syncthreads();
    if (threadIdx.x == 0) {
        float a = 0.f, b = 0.f;
        for (int i = 0; i < (int)(blockDim.x >> 5); i++) { a += sm[i][0]; b += sm[i][1]; }
        part[blockIdx.x * 2 + 0] = a;
        part[blockIdx.x * 2 + 1] = b;
    }
}

__global__ void clf_final(const float* __restrict__ part, const float* __restrict__ bias,
                          float* __restrict__ out, int nb)
{
    float s0 = 0.f, s1 = 0.f;
    for (int i = threadIdx.x; i < nb; i += blockDim.x) { s0 += part[i * 2]; s1 += part[i * 2 + 1]; }
    __shared__ float sm[8][2];
#pragma unroll
    for (int o = 16; o; o >>= 1) {
        s0 += __shfl_down_sync(0xffffffffu, s0, o);
        s1 += __shfl_down_sync(0xffffffffu, s1, o);
    }
    if ((threadIdx.x & 31) == 0) { sm[threadIdx.x >> 5][0] = s0; sm[threadIdx.x >> 5][1] = s1; }
    __syncthreads();
    if (threadIdx.x == 0) {
        float a = 0.f, b = 0.f;
        for (int i = 0; i < (int)(blockDim.x >> 5); i++) { a += sm[i][0]; b += sm[i][1]; }
        out[0] = a + bias[0];
        out[1] = b + bias[1];
    }
}

// ============================================================================
extern "C" void kernel_launch(void* const* d_in, const int* in_sizes, int n_in,
                              void* d_out, int out_size)
{
    const float* x1    = (const float*)d_in[0];
    const float* x2    = (const float*)d_in[1];
    const int*   adj1  = (const int*)d_in[2];
    const int*   adj2  = (const int*)d_in[3];
    const float* e1_w1 = (const float*)d_in[4];
    const float* e1_b1 = (const float*)d_in[5];
    const float* e1_w2 = (const float*)d_in[6];
    const float* e1_b2 = (const float*)d_in[7];
    const float* e1_w3 = (const float*)d_in[8];
    const float* e1_b3 = (const float*)d_in[9];
    const float* e2_w1 = (const float*)d_in[10];
    const float* e2_b1 = (const float*)d_in[11];
    const float* e2_w2 = (const float*)d_in[12];
    const float* e2_b2 = (const float*)d_in[13];
    const float* e2_w3 = (const float*)d_in[14];
    const float* e2_b3 = (const float*)d_in[15];
    const float* W     = (const float*)d_in[16];
    const float* alpha = (const float*)d_in[17];
    const float* clf_w = (const float*)d_in[18];
    const float* clf_b = (const float*)d_in[19];

    float *fc1p, *fc2p, *hp, *htp, *partp, *aggpp, *w1cvp;
    int *degpp;
    cudaGetSymbolAddress((void**)&fc1p,  g_fc1);
    cudaGetSymbolAddress((void**)&fc2p,  g_fc2);
    cudaGetSymbolAddress((void**)&hp,    g_h);
    cudaGetSymbolAddress((void**)&htp,   g_ht);
    cudaGetSymbolAddress((void**)&partp, g_part);
    cudaGetSymbolAddress((void**)&aggpp, g_aggp);
    cudaGetSymbolAddress((void**)&degpp, g_degp);
    cudaGetSymbolAddress((void**)&w1cvp, g_w1cv);

    const int FC1_SMEM = (2 * 128 * LD1 + 3 * 64 * LD1) * 4;   // 64512 B
    cudaFuncSetAttribute(fc1_tf, cudaFuncAttributeMaxDynamicSharedMemorySize, FC1_SMEM);

    // pre-pass: w1 -> RNA tf32
    cvt_w1<<<2048, 256>>>(e1_w1, e2_w1, w1cvp);

    // fc1: grid (nt=4, mt=32, z=2) = 256 CTAs
    fc1_tf<<<dim3(4, 32, 2), 128, FC1_SMEM>>>(
        x1, x2, w1cvp, e1_b1, e2_b1, fc1p);

    // fc2: [4096,256] x [128,256]^T -> [4096,128]     (split-tf32)
    gemm_tn<64, 64, 32, 2, false, false><<<dim3(64, 2, 2), 128>>>(
        fc1p, fc1p + 4096 * 256, e1_w2, e2_w2, e1_b2, e2_b2,
        fc2p, fc2p + 4096 * 128, nullptr, nullptr, 4096, 128, 256);

    // fc3+relu: [4096,128] x [64,128]^T -> [4096,64] (+ tf32-rounded transpose)
    gemm_tn<64, 64, 32, 2, true, true><<<dim3(64, 1, 2), 128>>>(
        fc2p, fc2p + 4096 * 128, e1_w3, e2_w3, e1_b3, e2_b3,
        hp, hp + 4096 * 64, htp, htp + 64 * 4096, 4096, 64, 128);

    // split-K masked aggregation
    agg_part<64, 64, 32><<<dim3(64, KC, 2), 128>>>(
        adj1, adj2, alpha, htp, htp + 64 * 4096, aggpp, degpp, 4096);

    // classifier stage 1 (fused with aggregation finish) + final
    clf_partial<<<256, 256>>>(aggpp, degpp, hp, hp + 4096 * 64, W, clf_w, partp);
    clf_final<<<1, 256>>>(partp, clf_b, (float*)d_out, 256);

    (void)in_sizes; (void)n_in; (void)out_size;
}

// round 9
// speedup vs baseline: 1.0519x; 1.0519x over previous
#include <cuda_runtime.h>
#include <cstdint>

#define DI __device__ __forceinline__

DI unsigned f2t(float x) { unsigned u; asm("cvt.rna.tf32.f32 %0, %1;" : "=r"(u) : "f"(x)); return u; }

DI void mma8(float c[4], const unsigned a[4], const unsigned b[2]) {
    asm("mma.sync.aligned.m16n8k8.row.col.f32.tf32.tf32.f32 "
        "{%0,%1,%2,%3}, {%4,%5,%6,%7}, {%8,%9}, {%0,%1,%2,%3};"
        : "+f"(c[0]), "+f"(c[1]), "+f"(c[2]), "+f"(c[3])
        : "r"(a[0]), "r"(a[1]), "r"(a[2]), "r"(a[3]), "r"(b[0]), "r"(b[1]));
}

// ---- scratch (device globals; no allocations allowed) ----
#define KC 8
__device__ float g_fc1[2][4096 * 256];
__device__ float g_fc2[2][4096 * 128];
__device__ float g_h  [2][4096 * 64];
__device__ float g_ht [2][64 * 4096];
__device__ float g_aggp[2][KC][4096 * 64];
__device__ int   g_degp[2][KC][4096];
__device__ float g_part[4096];
__device__ float g_w1cv[2][256 * 4096];

// ============================================================================
// Pre-pass: w1 -> RNA tf32 (stored as fp32 bits). fc1 loads B raw.
// ============================================================================
__global__ void cvt_w1(const float* __restrict__ w0, const float* __restrict__ w1,
                       float* __restrict__ out)
{
    int idx = blockIdx.x * blockDim.x + threadIdx.x;      // float4 id, 2*262144 total
    int z = idx >= 262144;
    int li = idx - z * 262144;
    float4 v = ((const float4*)(z ? w1 : w0))[li];
    float4 o;
    o.x = __uint_as_float(f2t(v.x));
    o.y = __uint_as_float(f2t(v.y));
    o.z = __uint_as_float(f2t(v.z));
    o.w = __uint_as_float(f2t(v.w));
    ((float4*)out)[(size_t)z * 262144 + li] = o;
}

// ============================================================================
// fc1 (R6 config — best measured): C[4096,256] = X @ W1cv^T + b.
// BM=128, BN=128, BK=32, 256 thr; 8 warps as 4m x 2n, warp tile 32x64.
// A: RNA cvt in STS path; B raw (pre-rounded w1cv).
// Double-buffered smem + register prefetch. grid (nt=2, mt=32, z=2) = 128 CTAs.
// ============================================================================
#define LD1 36
#define AS1(s, r, c) dsm[(s) * (128 * LD1) + (r) * LD1 + (c)]
#define BS1(s, r, c) dsm[2 * 128 * LD1 + (s) * (128 * LD1) + (r) * LD1 + (c)]

__global__ void __launch_bounds__(256)
fc1_tf(const float* __restrict__ A0, const float* __restrict__ A1,
       const float* __restrict__ Bcv,
       const float* __restrict__ bias0, const float* __restrict__ bias1,
       float* __restrict__ C)
{
    extern __shared__ unsigned dsm[];
    constexpr int K = 4096, BK = 32;
    const int tid = threadIdx.x, warp = tid >> 5, lane = tid & 31;
    const int wm = warp & 3, wn = warp >> 2;          // 4 m-warps x 2 n-warps
    const int gid = lane >> 2, tig = lane & 3;
    const int z = blockIdx.z;
    const size_t m0 = (size_t)blockIdx.y * 128;
    const size_t n0 = (size_t)blockIdx.x * 128;
    const int ax = tid & 7, ay = tid >> 3;            // 8 float4 per 32-wide row, 32 rows/pass

    const float* A = (z ? A1 : A0) + (m0 + ay) * (size_t)K + ax * 4;
    const float* B = Bcv + (size_t)z * 256 * 4096 + (n0 + ay) * (size_t)K + ax * 4;
    const float* bias = z ? bias1 : bias0;
    float* Cb = C + (size_t)z * 4096 * 256;

    float acc[2][8][4];
#pragma unroll
    for (int i = 0; i < 2; i++)
#pragma unroll
        for (int j = 0; j < 8; j++)
#pragma unroll
            for (int e = 0; e < 4; e++) acc[i][j][e] = 0.f;

    float4 ra[4]; uint4 rb[4];
    const int nIter = K / BK;                          // 128

    auto ldT = [&](int it) {
        const size_t ko = (size_t)it * BK;
#pragma unroll
        for (int p = 0; p < 4; p++)
            ra[p] = *(const float4*)(A + (size_t)p * 32 * K + ko);
#pragma unroll
        for (int p = 0; p < 4; p++)
            rb[p] = *(const uint4*)(B + (size_t)p * 32 * K + ko);
    };
    auto stT = [&](int s) {
#pragma unroll
        for (int p = 0; p < 4; p++) {
            uint4 t;
            t.x = f2t(ra[p].x); t.y = f2t(ra[p].y);
            t.z = f2t(ra[p].z); t.w = f2t(ra[p].w);
            *(uint4*)&AS1(s, p * 32 + ay, ax * 4) = t;
        }
#pragma unroll
        for (int p = 0; p < 4; p++)
            *(uint4*)&BS1(s, p * 32 + ay, ax * 4) = rb[p];
    };

    ldT(0); stT(0);
    ldT(1);
    __syncthreads();

    for (int it = 0; it < nIter; it++) {
        const int cur = it & 1;
        if (it + 1 < nIter) stT(cur ^ 1);
        if (it + 2 < nIter) ldT(it + 2);
#pragma unroll
        for (int ks = 0; ks < BK / 8; ks++) {
            unsigned af[2][4], bf[8][2];
#pragma unroll
            for (int mt = 0; mt < 2; mt++) {
                int rr = wm * 32 + mt * 16 + gid;
                af[mt][0] = AS1(cur, rr,     ks * 8 + tig);
                af[mt][1] = AS1(cur, rr + 8, ks * 8 + tig);
                af[mt][2] = AS1(cur, rr,     ks * 8 + tig + 4);
                af[mt][3] = AS1(cur, rr + 8, ks * 8 + tig + 4);
            }
#pragma unroll
            for (int nt = 0; nt < 8; nt++) {
                int cc = wn * 64 + nt * 8 + gid;
                bf[nt][0] = BS1(cur, cc, ks * 8 + tig);
                bf[nt][1] = BS1(cur, cc, ks * 8 + tig + 4);
            }
#pragma unroll
            for (int mt = 0; mt < 2; mt++)
#pragma unroll
                for (int nt = 0; nt < 8; nt++)
                    mma8(acc[mt][nt], af[mt], bf[nt]);
        }
        __syncthreads();
    }

#pragma unroll
    for (int mt = 0; mt < 2; mt++)
#pragma unroll
        for (int nt = 0; nt < 8; nt++) {
            size_t row = m0 + wm * 32 + mt * 16 + gid;
            size_t col = n0 + wn * 64 + nt * 8 + tig * 2;
#pragma unroll
            for (int e = 0; e < 4; e++) {
                size_t r = row + (size_t)(e >> 1) * 8;
                size_t c = col + (size_t)(e & 1);
                Cb[r * 256 + c] = acc[mt][nt][e] + bias[c];
            }
        }
}

// ============================================================================
// Single-buffered split-tf32 GEMM for fc2/fc3 (cheap layers, fp32-class acc).
// WT path stores the transposed copy pre-rounded to tf32 (feeds agg raw path).
// ============================================================================
template<int BM, int BN, int BK, int NS, bool RELU, bool WT>
__global__ void __launch_bounds__((BM / 32) * (BN / 32) * 32)
gemm_tn(const float* __restrict__ A0, const float* __restrict__ A1,
        const float* __restrict__ B0, const float* __restrict__ B1,
        const float* __restrict__ bias0, const float* __restrict__ bias1,
        float* __restrict__ C0, float* __restrict__ C1,
        float* __restrict__ T0, float* __restrict__ T1,
        int M, int N, int K)
{
    constexpr int WM = BM / 32, WN = BN / 32, NW = WM * WN, NT = NW * 32;
    constexpr int LD = BK + 4;
    constexpr int F4 = BK / 4, RA = NT / F4, PA = BM / RA, PB = BN / RA;

    const int z = blockIdx.z;
    const float* A = z ? A1 : A0;
    const float* B = z ? B1 : B0;
    const float* bias = z ? bias1 : bias0;
    float* C = z ? C1 : C0;
    float* T = z ? T1 : T0;

    __shared__ unsigned As[NS][BM][LD];
    __shared__ unsigned Bs[NS][BN][LD];

    const int tid = threadIdx.x, warp = tid >> 5, lane = tid & 31;
    const int wm = warp % WM, wn = warp / WM;
    const int gid = lane >> 2, tig = lane & 3;
    const size_t m0 = (size_t)blockIdx.x * BM;
    const size_t n0 = (size_t)blockIdx.y * BN;
    const int ax = tid % F4, ay = tid / F4;

    float acc[2][4][4];
#pragma unroll
    for (int i = 0; i < 2; i++)
#pragma unroll
        for (int j = 0; j < 4; j++)
#pragma unroll
            for (int e = 0; e < 4; e++) acc[i][j][e] = 0.f;

    float4 ra[PA], rb[PB];
#pragma unroll
    for (int p = 0; p < PA; p++)
        ra[p] = *(const float4*)(A + (m0 + p * RA + ay) * K + ax * 4);
#pragma unroll
    for (int p = 0; p < PB; p++)
        rb[p] = *(const float4*)(B + (n0 + p * RA + ay) * K + ax * 4);

    for (int k0 = 0; k0 < K; k0 += BK) {
#pragma unroll
        for (int p = 0; p < PA; p++) {
            int row = p * RA + ay;
            unsigned h0 = f2t(ra[p].x), h1 = f2t(ra[p].y), h2 = f2t(ra[p].z), h3 = f2t(ra[p].w);
            As[0][row][ax * 4 + 0] = h0; As[0][row][ax * 4 + 1] = h1;
            As[0][row][ax * 4 + 2] = h2; As[0][row][ax * 4 + 3] = h3;
            if (NS == 2) {
                As[NS - 1][row][ax * 4 + 0] = f2t(ra[p].x - __uint_as_float(h0));
                As[NS - 1][row][ax * 4 + 1] = f2t(ra[p].y - __uint_as_float(h1));
                As[NS - 1][row][ax * 4 + 2] = f2t(ra[p].z - __uint_as_float(h2));
                As[NS - 1][row][ax * 4 + 3] = f2t(ra[p].w - __uint_as_float(h3));
            }
        }
#pragma unroll
        for (int p = 0; p < PB; p++) {
            int row = p * RA + ay;
            unsigned h0 = f2t(rb[p].x), h1 = f2t(rb[p].y), h2 = f2t(rb[p].z), h3 = f2t(rb[p].w);
            Bs[0][row][ax * 4 + 0] = h0; Bs[0][row][ax * 4 + 1] = h1;
            Bs[0][row][ax * 4 + 2] = h2; Bs[0][row][ax * 4 + 3] = h3;
            if (NS == 2) {
                Bs[NS - 1][row][ax * 4 + 0] = f2t(rb[p].x - __uint_as_float(h0));
                Bs[NS - 1][row][ax * 4 + 1] = f2t(rb[p].y - __uint_as_float(h1));
                Bs[NS - 1][row][ax * 4 + 2] = f2t(rb[p].z - __uint_as_float(h2));
                Bs[NS - 1][row][ax * 4 + 3] = f2t(rb[p].w - __uint_as_float(h3));
            }
        }
        __syncthreads();

        if (k0 + BK < K) {
#pragma unroll
            for (int p = 0; p < PA; p++)
                ra[p] = *(const float4*)(A + (m0 + p * RA + ay) * K + (k0 + BK) + ax * 4);
#pragma unroll
            for (int p = 0; p < PB; p++)
                rb[p] = *(const float4*)(B + (n0 + p * RA + ay) * K + (k0 + BK) + ax * 4);
        }

#pragma unroll
        for (int ks = 0; ks < BK / 8; ks++) {
            unsigned af[NS][2][4], bf[NS][4][2];
#pragma unroll
            for (int s = 0; s < NS; s++) {
#pragma unroll
                for (int mt = 0; mt < 2; mt++) {
                    int rr = wm * 32 + mt * 16 + gid;
                    af[s][mt][0] = As[s][rr    ][ks * 8 + tig];
                    af[s][mt][1] = As[s][rr + 8][ks * 8 + tig];
                    af[s][mt][2] = As[s][rr    ][ks * 8 + tig + 4];
                    af[s][mt][3] = As[s][rr + 8][ks * 8 + tig + 4];
                }
#pragma unroll
                for (int nt = 0; nt < 4; nt++) {
                    int cc = wn * 32 + nt * 8 + gid;
                    bf[s][nt][0] = Bs[s][cc][ks * 8 + tig];
                    bf[s][nt][1] = Bs[s][cc][ks * 8 + tig + 4];
                }
            }
#pragma unroll
            for (int mt = 0; mt < 2; mt++)
#pragma unroll
                for (int nt = 0; nt < 4; nt++) {
                    mma8(acc[mt][nt], af[0][mt], bf[0][nt]);
                    if (NS == 2) {
                        mma8(acc[mt][nt], af[0][mt], bf[NS - 1][nt]);
                        mma8(acc[mt][nt], af[NS - 1][mt], bf[0][nt]);
                    }
                }
        }
        __syncthreads();
    }

#pragma unroll
    for (int mt = 0; mt < 2; mt++) {
#pragma unroll
        for (int nt = 0; nt < 4; nt++) {
            size_t row = m0 + wm * 32 + mt * 16 + gid;
            size_t col = n0 + wn * 32 + nt * 8 + tig * 2;
#pragma unroll
            for (int e = 0; e < 4; e++) {
                size_t r = row + (size_t)(e >> 1) * 8;
                size_t c = col + (size_t)(e & 1);
                float v = acc[mt][nt][e] + bias[c];
                if (RELU) v = fmaxf(v, 0.f);
                C[r * N + c] = v;
                if (WT) T[c * (size_t)M + r] = __uint_as_float(f2t(v));
            }
        }
    }
}

// ============================================================================
// Split-K masked aggregation partial — RNA cvt on masked alpha, B raw
// (Ht pre-rounded by fc3 epilogue).
// ============================================================================
template<int BM, int BN, int BK>
__global__ void __launch_bounds__(128)
agg_part(const int* __restrict__ adjA, const int* __restrict__ adjB,
         const float* __restrict__ alpha,
         const float* __restrict__ HtA, const float* __restrict__ HtB,
         float* __restrict__ aggp, int* __restrict__ degp, int K)
{
    constexpr int WM = BM / 32, WN = BN / 32, NT = WM * WN * 32;
    constexpr int LD = BK + 4;
    constexpr int F4 = BK / 4, RA = NT / F4, PA = BM / RA, PB = BN / RA;

    const int z = blockIdx.z;
    const int kc = blockIdx.y;
    const int* adj = z ? adjB : adjA;
    const float* Ht = z ? HtB : HtA;
    const int KCH = K / KC;
    const size_t kbase = (size_t)kc * KCH;

    __shared__ unsigned As[2][BM][LD];
    __shared__ unsigned Bs[2][BN][LD];
    __shared__ int sdeg[BM];

    const int tid = threadIdx.x, warp = tid >> 5, lane = tid & 31;
    const int wm = warp % WM, wn = warp / WM;
    const int gid = lane >> 2, tig = lane & 3;
    const size_t m0 = (size_t)blockIdx.x * BM;
    const int ax = tid % F4, ay = tid / F4;

    if (tid < BM) sdeg[tid] = 0;

    float acc[WM][WN * 2][4];
#pragma unroll
    for (int i = 0; i < WM; i++)
#pragma unroll
        for (int j = 0; j < WN * 2; j++)
#pragma unroll
            for (int e = 0; e < 4; e++) acc[i][j][e] = 0.f;

    int cnt[PA];
#pragma unroll
    for (int p = 0; p < PA; p++) cnt[p] = 0;

    int4 rma[PA]; float4 rva[PA]; uint4 rb[PB];
    const int nIter = KCH / BK;

    auto ldA = [&](int it) {
#pragma unroll
        for (int p = 0; p < PA; p++) {
            size_t g = (m0 + p * RA + ay) * (size_t)K + kbase + (size_t)it * BK + ax * 4;
            rma[p] = *(const int4*)(adj + g);
            rva[p] = *(const float4*)(alpha + g);
        }
#pragma unroll
        for (int p = 0; p < PB; p++)
            rb[p] = *(const uint4*)(Ht + (size_t)(p * RA + ay) * K + kbase + (size_t)it * BK + ax * 4);
    };
    auto stA = [&](int buf) {
#pragma unroll
        for (int p = 0; p < PA; p++) {
            int row = p * RA + ay;
            int mx = (rma[p].x == 1), my = (rma[p].y == 1);
            int mz = (rma[p].z == 1), mw = (rma[p].w == 1);
            cnt[p] += mx + my + mz + mw;
            As[buf][row][ax * 4 + 0] = f2t(mx ? rva[p].x : 0.f);
            As[buf][row][ax * 4 + 1] = f2t(my ? rva[p].y : 0.f);
            As[buf][row][ax * 4 + 2] = f2t(mz ? rva[p].z : 0.f);
            As[buf][row][ax * 4 + 3] = f2t(mw ? rva[p].w : 0.f);
        }
#pragma unroll
        for (int p = 0; p < PB; p++)
            *(uint4*)&Bs[buf][p * RA + ay][ax * 4] = rb[p];
    };

    ldA(0); stA(0);
    if (nIter > 1) ldA(1);
    __syncthreads();

    for (int it = 0; it < nIter; it++) {
        const int cur = it & 1;
        if (it + 1 < nIter) stA(cur ^ 1);
        if (it + 2 < nIter) ldA(it + 2);
#pragma unroll
        for (int ks = 0; ks < BK / 8; ks++) {
            unsigned af[WM][4], bf[WN * 2][2];
#pragma unroll
            for (int mt = 0; mt < WM; mt++) {
                int rr = wm * 32 + mt * 16 + gid;
                af[mt][0] = As[cur][rr    ][ks * 8 + tig];
                af[mt][1] = As[cur][rr + 8][ks * 8 + tig];
                af[mt][2] = As[cur][rr    ][ks * 8 + tig + 4];
                af[mt][3] = As[cur][rr + 8][ks * 8 + tig + 4];
            }
#pragma unroll
            for (int nt = 0; nt < WN * 2; nt++) {
                int cc = wn * 32 + nt * 8 + gid;
                bf[nt][0] = Bs[cur][cc][ks * 8 + tig];
                bf[nt][1] = Bs[cur][cc][ks * 8 + tig + 4];
            }
#pragma unroll
            for (int mt = 0; mt < WM; mt++)
#pragma unroll
                for (int nt = 0; nt < WN * 2; nt++)
                    mma8(acc[mt][nt], af[mt], bf[nt]);
        }
        __syncthreads();
    }

#pragma unroll
    for (int p = 0; p < PA; p++) atomicAdd(&sdeg[p * RA + ay], cnt[p]);
    __syncthreads();

    float* aout = aggp + ((size_t)z * KC + kc) * 4096 * 64;
    int*   dout = degp + ((size_t)z * KC + kc) * 4096;
    if (tid < BM) dout[m0 + tid] = sdeg[tid];
#pragma unroll
    for (int mt = 0; mt < WM; mt++)
#pragma unroll
        for (int nt = 0; nt < WN * 2; nt++) {
            size_t row = m0 + wm * 32 + mt * 16 + gid;
            size_t col = wn * 32 + nt * 8 + tig * 2;
#pragma unroll
            for (int e = 0; e < 4; e++) {
                size_t r = row + (size_t)(e >> 1) * 8;
                size_t c = col + (size_t)(e & 1);
                aout[r * 64 + c] = acc[mt][nt][e];
            }
        }
}

// ============================================================================
// Classifier stage 1, fused with aggregation finish — WIDE grid (2048 blocks
// x 128 thr) so the 24MB gather keeps agg_finish-level parallelism.
//   v_i = deg ? (sum_kc aggp)*W00/deg + h : 0 ;  s_c += v_i * clf_w[c,i]
// ============================================================================
__global__ void __launch_bounds__(128)
clf_partial(const float* __restrict__ aggp, const int* __restrict__ degp,
            const float* __restrict__ HA, const float* __restrict__ HB,
            const float* __restrict__ Wp,
            const float* __restrict__ w, float* __restrict__ part)
{
    const int L = 4096 * 64;
    const int TOT = 2 * L;
    const int chunk = 256;                 // TOT / 2048 blocks
    int base = blockIdx.x * chunk;
    const float W00 = Wp[0];
    float s0 = 0.f, s1 = 0.f;
#pragma unroll
    for (int q = 0; q < 2; q++) {
        int i = base + threadIdx.x + q * 128;
        int z = i >= L;
        int li = i - z * L;
        int r = li >> 6;
        const float* ap = aggp + (size_t)z * KC * L;
        const int* dp = degp + (size_t)z * KC * 4096;
        float s = 0.f; int d = 0;
#pragma unroll
        for (int kc = 0; kc < KC; kc++) {
            s += ap[(size_t)kc * L + li];
            d += dp[kc * 4096 + r];
        }
        const float* H = z ? HB : HA;
        float v = d ? s * W00 / (float)d + H[li] : 0.f;
        s0 += v * w[i];
        s1 += v * w[TOT + i];
    }
    __shared__ float sm[4][2];
#pragma unroll
    for (int o = 16; o; o >>= 1) {
        s0 += __shfl_down_sync(0xffffffffu, s0, o);
        s1 += __shfl_down_sync(0xffffffffu, s1, o);
    }
    if ((threadIdx.x & 31) == 0) { sm[threadIdx.x >> 5][0] = s0; sm[threadIdx.x >> 5][1] = s1; }
    __syncthreads();
    if (threadIdx.x == 0) {
        float a = 0.f, b = 0.f;
        for (int i = 0; i < 4; i++) { a += sm[i][0]; b += sm[i][1]; }
        part[blockIdx.x * 2 + 0] = a;
        part[blockIdx.x * 2 + 1] = b;
    }
}

__global__ void clf_final(const float* __restrict__ part, const float* __restrict__ bias,
                          float* __restrict__ out, int nb)
{
    float s0 = 0.f, s1 = 0.f;
    for (int i = threadIdx.x; i < nb; i += blockDim.x) { s0 += part[i * 2]; s1 += part[i * 2 + 1]; }
    __shared__ float sm[8][2];
#pragma unroll
    for (int o = 16; o; o >>= 1) {
        s0 += __shfl_down_sync(0xffffffffu, s0, o);
        s1 += __shfl_down_sync(0xffffffffu, s1, o);
    }
    if ((threadIdx.x & 31) == 0) { sm[threadIdx.x >> 5][0] = s0; sm[threadIdx.x >> 5][1] = s1; }
    __syncthreads();
    if (threadIdx.x == 0) {
        float a = 0.f, b = 0.f;
        for (int i = 0; i < (int)(blockDim.x >> 5); i++) { a += sm[i][0]; b += sm[i][1]; }
        out[0] = a + bias[0];
        out[1] = b + bias[1];
    }
}

// ============================================================================
extern "C" void kernel_launch(void* const* d_in, const int* in_sizes, int n_in,
                              void* d_out, int out_size)
{
    const float* x1    = (const float*)d_in[0];
    const float* x2    = (const float*)d_in[1];
    const int*   adj1  = (const int*)d_in[2];
    const int*   adj2  = (const int*)d_in[3];
    const float* e1_w1 = (const float*)d_in[4];
    const float* e1_b1 = (const float*)d_in[5];
    const float* e1_w2 = (const float*)d_in[6];
    const float* e1_b2 = (const float*)d_in[7];
    const float* e1_w3 = (const float*)d_in[8];
    const float* e1_b3 = (const float*)d_in[9];
    const float* e2_w1 = (const float*)d_in[10];
    const float* e2_b1 = (const float*)d_in[11];
    const float* e2_w2 = (const float*)d_in[12];
    const float* e2_b2 = (const float*)d_in[13];
    const float* e2_w3 = (const float*)d_in[14];
    const float* e2_b3 = (const float*)d_in[15];
    const float* W     = (const float*)d_in[16];
    const float* alpha = (const float*)d_in[17];
    const float* clf_w = (const float*)d_in[18];
    const float* clf_b = (const float*)d_in[19];

    float *fc1p, *fc2p, *hp, *htp, *partp, *aggpp, *w1cvp;
    int *degpp;
    cudaGetSymbolAddress((void**)&fc1p,  g_fc1);
    cudaGetSymbolAddress((void**)&fc2p,  g_fc2);
    cudaGetSymbolAddress((void**)&hp,    g_h);
    cudaGetSymbolAddress((void**)&htp,   g_ht);
    cudaGetSymbolAddress((void**)&partp, g_part);
    cudaGetSymbolAddress((void**)&aggpp, g_aggp);
    cudaGetSymbolAddress((void**)&degpp, g_degp);
    cudaGetSymbolAddress((void**)&w1cvp, g_w1cv);

    const int FC1_SMEM = (2 * 128 * LD1 + 2 * 128 * LD1) * 4;   // 73728 B
    cudaFuncSetAttribute(fc1_tf, cudaFuncAttributeMaxDynamicSharedMemorySize, FC1_SMEM);

    // pre-pass: w1 -> RNA tf32
    cvt_w1<<<2048, 256>>>(e1_w1, e2_w1, w1cvp);

    // fc1: grid (nt=2, mt=32, z=2) = 128 CTAs, one wave (R6 best config)
    fc1_tf<<<dim3(2, 32, 2), 256, FC1_SMEM>>>(
        x1, x2, w1cvp, e1_b1, e2_b1, fc1p);

    // fc2: [4096,256] x [128,256]^T -> [4096,128]     (split-tf32)
    gemm_tn<64, 64, 32, 2, false, false><<<dim3(64, 2, 2), 128>>>(
        fc1p, fc1p + 4096 * 256, e1_w2, e2_w2, e1_b2, e2_b2,
        fc2p, fc2p + 4096 * 128, nullptr, nullptr, 4096, 128, 256);

    // fc3+relu: [4096,128] x [64,128]^T -> [4096,64] (+ tf32-rounded transpose)
    gemm_tn<64, 64, 32, 2, true, true><<<dim3(64, 1, 2), 128>>>(
        fc2p, fc2p + 4096 * 128, e1_w3, e2_w3, e1_b3, e2_b3,
        hp, hp + 4096 * 64, htp, htp + 64 * 4096, 4096, 64, 128);

    // split-K masked aggregation
    agg_part<64, 64, 32><<<dim3(64, KC, 2), 128>>>(
        adj1, adj2, alpha, htp, htp + 64 * 4096, aggpp, degpp, 4096);

    // classifier stage 1 (fused agg-finish, wide grid) + final
    clf_partial<<<2048, 128>>>(aggpp, degpp, hp, hp + 4096 * 64, W, clf_w, partp);
    clf_final<<<1, 256>>>(partp, clf_b, (float*)d_out, 2048);

    (void)in_sizes; (void)n_in; (void)out_size;
}

// round 10
// speedup vs baseline: 1.2455x; 1.1840x over previous
#include <cuda_runtime.h>
#include <cuda_fp16.h>
#include <cstdint>

#define DI __device__ __forceinline__

DI unsigned f2t(float x) { unsigned u; asm("cvt.rna.tf32.f32 %0, %1;" : "=r"(u) : "f"(x)); return u; }

DI void mma8(float c[4], const unsigned a[4], const unsigned b[2]) {
    asm("mma.sync.aligned.m16n8k8.row.col.f32.tf32.tf32.f32 "
        "{%0,%1,%2,%3}, {%4,%5,%6,%7}, {%8,%9}, {%0,%1,%2,%3};"
        : "+f"(c[0]), "+f"(c[1]), "+f"(c[2]), "+f"(c[3])
        : "r"(a[0]), "r"(a[1]), "r"(a[2]), "r"(a[3]), "r"(b[0]), "r"(b[1]));
}

DI void mma16h(float c[4], const unsigned a[4], const unsigned b[2]) {
    asm("mma.sync.aligned.m16n8k16.row.col.f32.f16.f16.f32 "
        "{%0,%1,%2,%3}, {%4,%5,%6,%7}, {%8,%9}, {%0,%1,%2,%3};"
        : "+f"(c[0]), "+f"(c[1]), "+f"(c[2]), "+f"(c[3])
        : "r"(a[0]), "r"(a[1]), "r"(a[2]), "r"(a[3]), "r"(b[0]), "r"(b[1]));
}

DI unsigned packh2(float lo, float hi) {
    __half2 h = __floats2half2_rn(lo, hi);
    return *(unsigned*)&h;
}

// ---- scratch (device globals; no allocations allowed) ----
#define KC 8
__device__ float  g_fc1[2][4096 * 256];
__device__ float  g_fc2[2][4096 * 128];
__device__ float  g_h  [2][4096 * 64];
__device__ float  g_ht [2][64 * 4096];
__device__ float  g_aggp[2][KC][4096 * 64];
__device__ int    g_degp[2][KC][4096];
__device__ float  g_part[4096];
__device__ __half g_w1h[2 * 256 * 4096];

// ============================================================================
// Pre-pass: w1 -> RNE fp16 (10 mantissa bits, same as tf32). fc1 loads raw.
// ============================================================================
__global__ void cvt_w1h(const float* __restrict__ w0, const float* __restrict__ w1,
                        __half* __restrict__ out)
{
    int idx = blockIdx.x * blockDim.x + threadIdx.x;      // float4 id, 2*262144 total
    int z = idx >= 262144;
    int li = idx - z * 262144;
    float4 v = ((const float4*)(z ? w1 : w0))[li];
    uint2 u;
    u.x = packh2(v.x, v.y);
    u.y = packh2(v.z, v.w);
    ((uint2*)out)[idx] = u;
}

// ============================================================================
// fc1 via FP16 HMMA (m16n8k16, fp32 acc): C[4096,256] = X @ W1h^T + b.
// BM=128, BN=128, BK=32, 256 thr; 8 warps as 4m x 2n, warp tile 32x64.
// A: LDG fp32 -> RNE half2 pack -> STS. B: raw halves (pre-rounded w1h).
// Dual-buffered smem + register prefetch. grid (nt=2, mt=32, z=2) = 128 CTAs.
// smem element = half2 (uint). 16 units/row + pad -> LDH=20, conflict-free.
// ============================================================================
#define LDH 20
#define ASH(s, r, c) hsm[(s) * (128 * LDH) + (r) * LDH + (c)]
#define BSH(s, r, c) hsm[2 * 128 * LDH + (s) * (128 * LDH) + (r) * LDH + (c)]

__global__ void __launch_bounds__(256)
fc1_h(const float* __restrict__ A0, const float* __restrict__ A1,
      const __half* __restrict__ Bh,
      const float* __restrict__ bias0, const float* __restrict__ bias1,
      float* __restrict__ C)
{
    extern __shared__ unsigned hsm[];
    constexpr int K = 4096, BK = 32;
    const int tid = threadIdx.x, warp = tid >> 5, lane = tid & 31;
    const int wm = warp & 3, wn = warp >> 2;          // 4 m-warps x 2 n-warps
    const int gid = lane >> 2, tig = lane & 3;
    const int z = blockIdx.z;
    const size_t m0 = (size_t)blockIdx.y * 128;
    const size_t n0 = (size_t)blockIdx.x * 128;
    const int ax = tid & 7, ay = tid >> 3;            // A: 8 float4/row, 32 rows/pass
    const int bx = tid & 3, by = tid >> 2;            // B: 4 uint4/row (32 halves), 64 rows/pass

    const float*  A = (z ? A1 : A0) + (m0 + ay) * (size_t)K + ax * 4;
    const __half* B = Bh + (size_t)z * 256 * 4096 + (n0 + by) * (size_t)K + bx * 8;
    const float* bias = z ? bias1 : bias0;
    float* Cb = C + (size_t)z * 4096 * 256;

    float acc[2][8][4];
#pragma unroll
    for (int i = 0; i < 2; i++)
#pragma unroll
        for (int j = 0; j < 8; j++)
#pragma unroll
            for (int e = 0; e < 4; e++) acc[i][j][e] = 0.f;

    float4 ra[4]; uint4 rb[2];
    const int nIter = K / BK;                          // 128

    auto ldT = [&](int it) {
        const size_t ko = (size_t)it * BK;
#pragma unroll
        for (int p = 0; p < 4; p++)
            ra[p] = *(const float4*)(A + (size_t)p * 32 * K + ko);
#pragma unroll
        for (int p = 0; p < 2; p++)
            rb[p] = *(const uint4*)(B + (size_t)p * 64 * K + ko);
    };
    auto stT = [&](int s) {
#pragma unroll
        for (int p = 0; p < 4; p++) {
            uint2 t;
            t.x = packh2(ra[p].x, ra[p].y);
            t.y = packh2(ra[p].z, ra[p].w);
            *(uint2*)&ASH(s, p * 32 + ay, ax * 2) = t;
        }
#pragma unroll
        for (int p = 0; p < 2; p++)
            *(uint4*)&BSH(s, p * 64 + by, bx * 4) = rb[p];
    };

    ldT(0); stT(0);
    ldT(1);
    __syncthreads();

    for (int it = 0; it < nIter; it++) {
        const int cur = it & 1;
        if (it + 1 < nIter) stT(cur ^ 1);
        if (it + 2 < nIter) ldT(it + 2);
#pragma unroll
        for (int ks = 0; ks < BK / 16; ks++) {         // 2 k16 steps per chunk
            unsigned af[2][4], bf[8][2];
#pragma unroll
            for (int mt = 0; mt < 2; mt++) {
                int rr = wm * 32 + mt * 16 + gid;
                af[mt][0] = ASH(cur, rr,     ks * 8 + tig);
                af[mt][1] = ASH(cur, rr + 8, ks * 8 + tig);
                af[mt][2] = ASH(cur, rr,     ks * 8 + tig + 4);
                af[mt][3] = ASH(cur, rr + 8, ks * 8 + tig + 4);
            }
#pragma unroll
            for (int nt = 0; nt < 8; nt++) {
                int cc = wn * 64 + nt * 8 + gid;
                bf[nt][0] = BSH(cur, cc, ks * 8 + tig);
                bf[nt][1] = BSH(cur, cc, ks * 8 + tig + 4);
            }
#pragma unroll
            for (int mt = 0; mt < 2; mt++)
#pragma unroll
                for (int nt = 0; nt < 8; nt++)
                    mma16h(acc[mt][nt], af[mt], bf[nt]);
        }
        __syncthreads();
    }

#pragma unroll
    for (int mt = 0; mt < 2; mt++)
#pragma unroll
        for (int nt = 0; nt < 8; nt++) {
            size_t row = m0 + wm * 32 + mt * 16 + gid;
            size_t col = n0 + wn * 64 + nt * 8 + tig * 2;
#pragma unroll
            for (int e = 0; e < 4; e++) {
                size_t r = row + (size_t)(e >> 1) * 8;
                size_t c = col + (size_t)(e & 1);
                Cb[r * 256 + c] = acc[mt][nt][e] + bias[c];
            }
        }
}

// ============================================================================
// Single-buffered split-tf32 GEMM for fc2/fc3 (cheap layers, fp32-class acc).
// WT path stores the transposed copy pre-rounded to tf32 (feeds agg raw path).
// ============================================================================
template<int BM, int BN, int BK, int NS, bool RELU, bool WT>
__global__ void __launch_bounds__((BM / 32) * (BN / 32) * 32)
gemm_tn(const float* __restrict__ A0, const float* __restrict__ A1,
        const float* __restrict__ B0, const float* __restrict__ B1,
        const float* __restrict__ bias0, const float* __restrict__ bias1,
        float* __restrict__ C0, float* __restrict__ C1,
        float* __restrict__ T0, float* __restrict__ T1,
        int M, int N, int K)
{
    constexpr int WM = BM / 32, WN = BN / 32, NW = WM * WN, NT = NW * 32;
    constexpr int LD = BK + 4;
    constexpr int F4 = BK / 4, RA = NT / F4, PA = BM / RA, PB = BN / RA;

    const int z = blockIdx.z;
    const float* A = z ? A1 : A0;
    const float* B = z ? B1 : B0;
    const float* bias = z ? bias1 : bias0;
    float* C = z ? C1 : C0;
    float* T = z ? T1 : T0;

    __shared__ unsigned As[NS][BM][LD];
    __shared__ unsigned Bs[NS][BN][LD];

    const int tid = threadIdx.x, warp = tid >> 5, lane = tid & 31;
    const int wm = warp % WM, wn = warp / WM;
    const int gid = lane >> 2, tig = lane & 3;
    const size_t m0 = (size_t)blockIdx.x * BM;
    const size_t n0 = (size_t)blockIdx.y * BN;
    const int ax = tid % F4, ay = tid / F4;

    float acc[2][4][4];
#pragma unroll
    for (int i = 0; i < 2; i++)
#pragma unroll
        for (int j = 0; j < 4; j++)
#pragma unroll
            for (int e = 0; e < 4; e++) acc[i][j][e] = 0.f;

    float4 ra[PA], rb[PB];
#pragma unroll
    for (int p = 0; p < PA; p++)
        ra[p] = *(const float4*)(A + (m0 + p * RA + ay) * K + ax * 4);
#pragma unroll
    for (int p = 0; p < PB; p++)
        rb[p] = *(const float4*)(B + (n0 + p * RA + ay) * K + ax * 4);

    for (int k0 = 0; k0 < K; k0 += BK) {
#pragma unroll
        for (int p = 0; p < PA; p++) {
            int row = p * RA + ay;
            unsigned h0 = f2t(ra[p].x), h1 = f2t(ra[p].y), h2 = f2t(ra[p].z), h3 = f2t(ra[p].w);
            As[0][row][ax * 4 + 0] = h0; As[0][row][ax * 4 + 1] = h1;
            As[0][row][ax * 4 + 2] = h2; As[0][row][ax * 4 + 3] = h3;
            if (NS == 2) {
                As[NS - 1][row][ax * 4 + 0] = f2t(ra[p].x - __uint_as_float(h0));
                As[NS - 1][row][ax * 4 + 1] = f2t(ra[p].y - __uint_as_float(h1));
                As[NS - 1][row][ax * 4 + 2] = f2t(ra[p].z - __uint_as_float(h2));
                As[NS - 1][row][ax * 4 + 3] = f2t(ra[p].w - __uint_as_float(h3));
            }
        }
#pragma unroll
        for (int p = 0; p < PB; p++) {
            int row = p * RA + ay;
            unsigned h0 = f2t(rb[p].x), h1 = f2t(rb[p].y), h2 = f2t(rb[p].z), h3 = f2t(rb[p].w);
            Bs[0][row][ax * 4 + 0] = h0; Bs[0][row][ax * 4 + 1] = h1;
            Bs[0][row][ax * 4 + 2] = h2; Bs[0][row][ax * 4 + 3] = h3;
            if (NS == 2) {
                Bs[NS - 1][row][ax * 4 + 0] = f2t(rb[p].x - __uint_as_float(h0));
                Bs[NS - 1][row][ax * 4 + 1] = f2t(rb[p].y - __uint_as_float(h1));
                Bs[NS - 1][row][ax * 4 + 2] = f2t(rb[p].z - __uint_as_float(h2));
                Bs[NS - 1][row][ax * 4 + 3] = f2t(rb[p].w - __uint_as_float(h3));
            }
        }
        __syncthreads();

        if (k0 + BK < K) {
#pragma unroll
            for (int p = 0; p < PA; p++)
                ra[p] = *(const float4*)(A + (m0 + p * RA + ay) * K + (k0 + BK) + ax * 4);
#pragma unroll
            for (int p = 0; p < PB; p++)
                rb[p] = *(const float4*)(B + (n0 + p * RA + ay) * K + (k0 + BK) + ax * 4);
        }

#pragma unroll
        for (int ks = 0; ks < BK / 8; ks++) {
            unsigned af[NS][2][4], bf[NS][4][2];
#pragma unroll
            for (int s = 0; s < NS; s++) {
#pragma unroll
                for (int mt = 0; mt < 2; mt++) {
                    int rr = wm * 32 + mt * 16 + gid;
                    af[s][mt][0] = As[s][rr    ][ks * 8 + tig];
                    af[s][mt][1] = As[s][rr + 8][ks * 8 + tig];
                    af[s][mt][2] = As[s][rr    ][ks * 8 + tig + 4];
                    af[s][mt][3] = As[s][rr + 8][ks * 8 + tig + 4];
                }
#pragma unroll
                for (int nt = 0; nt < 4; nt++) {
                    int cc = wn * 32 + nt * 8 + gid;
                    bf[s][nt][0] = Bs[s][cc][ks * 8 + tig];
                    bf[s][nt][1] = Bs[s][cc][ks * 8 + tig + 4];
                }
            }
#pragma unroll
            for (int mt = 0; mt < 2; mt++)
#pragma unroll
                for (int nt = 0; nt < 4; nt++) {
                    mma8(acc[mt][nt], af[0][mt], bf[0][nt]);
                    if (NS == 2) {
                        mma8(acc[mt][nt], af[0][mt], bf[NS - 1][nt]);
                        mma8(acc[mt][nt], af[NS - 1][mt], bf[0][nt]);
                    }
                }
        }
        __syncthreads();
    }

#pragma unroll
    for (int mt = 0; mt < 2; mt++) {
#pragma unroll
        for (int nt = 0; nt < 4; nt++) {
            size_t row = m0 + wm * 32 + mt * 16 + gid;
            size_t col = n0 + wn * 32 + nt * 8 + tig * 2;
#pragma unroll
            for (int e = 0; e < 4; e++) {
                size_t r = row + (size_t)(e >> 1) * 8;
                size_t c = col + (size_t)(e & 1);
                float v = acc[mt][nt][e] + bias[c];
                if (RELU) v = fmaxf(v, 0.f);
                C[r * N + c] = v;
                if (WT) T[c * (size_t)M + r] = __uint_as_float(f2t(v));
            }
        }
    }
}

// ============================================================================
// Split-K masked aggregation partial — RNA cvt on masked alpha, B raw
// (Ht pre-rounded by fc3 epilogue).
// ============================================================================
template<int BM, int BN, int BK>
__global__ void __launch_bounds__(128)
agg_part(const int* __restrict__ adjA, const int* __restrict__ adjB,
         const float* __restrict__ alpha,
         const float* __restrict__ HtA, const float* __restrict__ HtB,
         float* __restrict__ aggp, int* __restrict__ degp, int K)
{
    constexpr int WM = BM / 32, WN = BN / 32, NT = WM * WN * 32;
    constexpr int LD = BK + 4;
    constexpr int F4 = BK / 4, RA = NT / F4, PA = BM / RA, PB = BN / RA;

    const int z = blockIdx.z;
    const int kc = blockIdx.y;
    const int* adj = z ? adjB : adjA;
    const float* Ht = z ? HtB : HtA;
    const int KCH = K / KC;
    const size_t kbase = (size_t)kc * KCH;

    __shared__ unsigned As[2][BM][LD];
    __shared__ unsigned Bs[2][BN][LD];
    __shared__ int sdeg[BM];

    const int tid = threadIdx.x, warp = tid >> 5, lane = tid & 31;
    const int wm = warp % WM, wn = warp / WM;
    const int gid = lane >> 2, tig = lane & 3;
    const size_t m0 = (size_t)blockIdx.x * BM;
    const int ax = tid % F4, ay = tid / F4;

    if (tid < BM) sdeg[tid] = 0;

    float acc[WM][WN * 2][4];
#pragma unroll
    for (int i = 0; i < WM; i++)
#pragma unroll
        for (int j = 0; j < WN * 2; j++)
#pragma unroll
            for (int e = 0; e < 4; e++) acc[i][j][e] = 0.f;

    int cnt[PA];
#pragma unroll
    for (int p = 0; p < PA; p++) cnt[p] = 0;

    int4 rma[PA]; float4 rva[PA]; uint4 rb[PB];
    const int nIter = KCH / BK;

    auto ldA = [&](int it) {
#pragma unroll
        for (int p = 0; p < PA; p++) {
            size_t g = (m0 + p * RA + ay) * (size_t)K + kbase + (size_t)it * BK + ax * 4;
            rma[p] = *(const int4*)(adj + g);
            rva[p] = *(const float4*)(alpha + g);
        }
#pragma unroll
        for (int p = 0; p < PB; p++)
            rb[p] = *(const uint4*)(Ht + (size_t)(p * RA + ay) * K + kbase + (size_t)it * BK + ax * 4);
    };
    auto stA = [&](int buf) {
#pragma unroll
        for (int p = 0; p < PA; p++) {
            int row = p * RA + ay;
            int mx = (rma[p].x == 1), my = (rma[p].y == 1);
            int mz = (rma[p].z == 1), mw = (rma[p].w == 1);
            cnt[p] += mx + my + mz + mw;
            As[buf][row][ax * 4 + 0] = f2t(mx ? rva[p].x : 0.f);
            As[buf][row][ax * 4 + 1] = f2t(my ? rva[p].y : 0.f);
            As[buf][row][ax * 4 + 2] = f2t(mz ? rva[p].z : 0.f);
            As[buf][row][ax * 4 + 3] = f2t(mw ? rva[p].w : 0.f);
        }
#pragma unroll
        for (int p = 0; p < PB; p++)
            *(uint4*)&Bs[buf][p * RA + ay][ax * 4] = rb[p];
    };

    ldA(0); stA(0);
    if (nIter > 1) ldA(1);
    __syncthreads();

    for (int it = 0; it < nIter; it++) {
        const int cur = it & 1;
        if (it + 1 < nIter) stA(cur ^ 1);
        if (it + 2 < nIter) ldA(it + 2);
#pragma unroll
        for (int ks = 0; ks < BK / 8; ks++) {
            unsigned af[WM][4], bf[WN * 2][2];
#pragma unroll
            for (int mt = 0; mt < WM; mt++) {
                int rr = wm * 32 + mt * 16 + gid;
                af[mt][0] = As[cur][rr    ][ks * 8 + tig];
                af[mt][1] = As[cur][rr + 8][ks * 8 + tig];
                af[mt][2] = As[cur][rr    ][ks * 8 + tig + 4];
                af[mt][3] = As[cur][rr + 8][ks * 8 + tig + 4];
            }
#pragma unroll
            for (int nt = 0; nt < WN * 2; nt++) {
                int cc = wn * 32 + nt * 8 + gid;
                bf[nt][0] = Bs[cur][cc][ks * 8 + tig];
                bf[nt][1] = Bs[cur][cc][ks * 8 + tig + 4];
            }
#pragma unroll
            for (int mt = 0; mt < WM; mt++)
#pragma unroll
                for (int nt = 0; nt < WN * 2; nt++)
                    mma8(acc[mt][nt], af[mt], bf[nt]);
        }
        __syncthreads();
    }

#pragma unroll
    for (int p = 0; p < PA; p++) atomicAdd(&sdeg[p * RA + ay], cnt[p]);
    __syncthreads();

    float* aout = aggp + ((size_t)z * KC + kc) * 4096 * 64;
    int*   dout = degp + ((size_t)z * KC + kc) * 4096;
    if (tid < BM) dout[m0 + tid] = sdeg[tid];
#pragma unroll
    for (int mt = 0; mt < WM; mt++)
#pragma unroll
        for (int nt = 0; nt < WN * 2; nt++) {
            size_t row = m0 + wm * 32 + mt * 16 + gid;
            size_t col = wn * 32 + nt * 8 + tig * 2;
#pragma unroll
            for (int e = 0; e < 4; e++) {
                size_t r = row + (size_t)(e >> 1) * 8;
                size_t c = col + (size_t)(e & 1);
                aout[r * 64 + c] = acc[mt][nt][e];
            }
        }
}

// ============================================================================
// Classifier stage 1, fused with aggregation finish — WIDE grid (2048 blocks
// x 128 thr).
// ============================================================================
__global__ void __launch_bounds__(128)
clf_partial(const float* __restrict__ aggp, const int* __restrict__ degp,
            const float* __restrict__ HA, const float* __restrict__ HB,
            const float* __restrict__ Wp,
            const float* __restrict__ w, float* __restrict__ part)
{
    const int L = 4096 * 64;
    const int TOT = 2 * L;
    const int chunk = 256;                 // TOT / 2048 blocks
    int base = blockIdx.x * chunk;
    const float W00 = Wp[0];
    float s0 = 0.f, s1 = 0.f;
#pragma unroll
    for (int q = 0; q < 2; q++) {
        int i = base + threadIdx.x + q * 128;
        int z = i >= L;
        int li = i - z * L;
        int r = li >> 6;
        const float* ap = aggp + (size_t)z * KC * L;
        const int* dp = degp + (size_t)z * KC * 4096;
        float s = 0.f; int d = 0;
#pragma unroll
        for (int kc = 0; kc < KC; kc++) {
            s += ap[(size_t)kc * L + li];
            d += dp[kc * 4096 + r];
        }
        const float* H = z ? HB : HA;
        float v = d ? s * W00 / (float)d + H[li] : 0.f;
        s0 += v * w[i];
        s1 += v * w[TOT + i];
    }
    __shared__ float sm[4][2];
#pragma unroll
    for (int o = 16; o; o >>= 1) {
        s0 += __shfl_down_sync(0xffffffffu, s0, o);
        s1 += __shfl_down_sync(0xffffffffu, s1, o);
    }
    if ((threadIdx.x & 31) == 0) { sm[threadIdx.x >> 5][0] = s0; sm[threadIdx.x >> 5][1] = s1; }
    __syncthreads();
    if (threadIdx.x == 0) {
        float a = 0.f, b = 0.f;
        for (int i = 0; i < 4; i++) { a += sm[i][0]; b += sm[i][1]; }
        part[blockIdx.x * 2 + 0] = a;
        part[blockIdx.x * 2 + 1] = b;
    }
}

__global__ void clf_final(const float* __restrict__ part, const float* __restrict__ bias,
                          float* __restrict__ out, int nb)
{
    float s0 = 0.f, s1 = 0.f;
    for (int i = threadIdx.x; i < nb; i += blockDim.x) { s0 += part[i * 2]; s1 += part[i * 2 + 1]; }
    __shared__ float sm[8][2];
#pragma unroll
    for (int o = 16; o; o >>= 1) {
        s0 += __shfl_down_sync(0xffffffffu, s0, o);
        s1 += __shfl_down_sync(0xffffffffu, s1, o);
    }
    if ((threadIdx.x & 31) == 0) { sm[threadIdx.x >> 5][0] = s0; sm[threadIdx.x >> 5][1] = s1; }
    __syncthreads();
    if (threadIdx.x == 0) {
        float a = 0.f, b = 0.f;
        for (int i = 0; i < (int)(blockDim.x >> 5); i++) { a += sm[i][0]; b += sm[i][1]; }
        out[0] = a + bias[0];
        out[1] = b + bias[1];
    }
}

// ============================================================================
extern "C" void kernel_launch(void* const* d_in, const int* in_sizes, int n_in,
                              void* d_out, int out_size)
{
    const float* x1    = (const float*)d_in[0];
    const float* x2    = (const float*)d_in[1];
    const int*   adj1  = (const int*)d_in[2];
    const int*   adj2  = (const int*)d_in[3];
    const float* e1_w1 = (const float*)d_in[4];
    const float* e1_b1 = (const float*)d_in[5];
    const float* e1_w2 = (const float*)d_in[6];
    const float* e1_b2 = (const float*)d_in[7];
    const float* e1_w3 = (const float*)d_in[8];
    const float* e1_b3 = (const float*)d_in[9];
    const float* e2_w1 = (const float*)d_in[10];
    const float* e2_b1 = (const float*)d_in[11];
    const float* e2_w2 = (const float*)d_in[12];
    const float* e2_b2 = (const float*)d_in[13];
    const float* e2_w3 = (const float*)d_in[14];
    const float* e2_b3 = (const float*)d_in[15];
    const float* W     = (const float*)d_in[16];
    const float* alpha = (const float*)d_in[17];
    const float* clf_w = (const float*)d_in[18];
    const float* clf_b = (const float*)d_in[19];

    float *fc1p, *fc2p, *hp, *htp, *partp, *aggpp;
    __half *w1hp;
    int *degpp;
    cudaGetSymbolAddress((void**)&fc1p,  g_fc1);
    cudaGetSymbolAddress((void**)&fc2p,  g_fc2);
    cudaGetSymbolAddress((void**)&hp,    g_h);
    cudaGetSymbolAddress((void**)&htp,   g_ht);
    cudaGetSymbolAddress((void**)&partp, g_part);
    cudaGetSymbolAddress((void**)&aggpp, g_aggp);
    cudaGetSymbolAddress((void**)&degpp, g_degp);
    cudaGetSymbolAddress((void**)&w1hp,  g_w1h);

    const int FC1_SMEM = (2 * 128 * LDH + 2 * 128 * LDH) * 4;   // 40960 B
    cudaFuncSetAttribute(fc1_h, cudaFuncAttributeMaxDynamicSharedMemorySize, FC1_SMEM);

    // pre-pass: w1 -> RNE fp16
    cvt_w1h<<<2048, 256>>>(e1_w1, e2_w1, w1hp);

    // fc1 (fp16 HMMA): grid (nt=2, mt=32, z=2) = 128 CTAs, one wave
    fc1_h<<<dim3(2, 32, 2), 256, FC1_SMEM>>>(
        x1, x2, w1hp, e1_b1, e2_b1, fc1p);

    // fc2: [4096,256] x [128,256]^T -> [4096,128]     (split-tf32)
    gemm_tn<64, 64, 32, 2, false, false><<<dim3(64, 2, 2), 128>>>(
        fc1p, fc1p + 4096 * 256, e1_w2, e2_w2, e1_b2, e2_b2,
        fc2p, fc2p + 4096 * 128, nullptr, nullptr, 4096, 128, 256);

    // fc3+relu: [4096,128] x [64,128]^T -> [4096,64] (+ tf32-rounded transpose)
    gemm_tn<64, 64, 32, 2, true, true><<<dim3(64, 1, 2), 128>>>(
        fc2p, fc2p + 4096 * 128, e1_w3, e2_w3, e1_b3, e2_b3,
        hp, hp + 4096 * 64, htp, htp + 64 * 4096, 4096, 64, 128);

    // split-K masked aggregation
    agg_part<64, 64, 32><<<dim3(64, KC, 2), 128>>>(
        adj1, adj2, alpha, htp, htp + 64 * 4096, aggpp, degpp, 4096);

    // classifier stage 1 (fused agg-finish, wide grid) + final
    clf_partial<<<2048, 128>>>(aggpp, degpp, hp, hp + 4096 * 64, W, clf_w, partp);
    clf_final<<<1, 256>>>(partp, clf_b, (float*)d_out, 2048);

    (void)in_sizes; (void)n_in; (void)out_size;
}

// round 11
// speedup vs baseline: 1.2759x; 1.0244x over previous
#include <cuda_runtime.h>
#include <cuda_fp16.h>
#include <cstdint>

#define DI __device__ __forceinline__

DI unsigned f2t(float x) { unsigned u; asm("cvt.rna.tf32.f32 %0, %1;" : "=r"(u) : "f"(x)); return u; }

DI void mma8(float c[4], const unsigned a[4], const unsigned b[2]) {
    asm("mma.sync.aligned.m16n8k8.row.col.f32.tf32.tf32.f32 "
        "{%0,%1,%2,%3}, {%4,%5,%6,%7}, {%8,%9}, {%0,%1,%2,%3};"
        : "+f"(c[0]), "+f"(c[1]), "+f"(c[2]), "+f"(c[3])
        : "r"(a[0]), "r"(a[1]), "r"(a[2]), "r"(a[3]), "r"(b[0]), "r"(b[1]));
}

DI void mma16h(float c[4], const unsigned a[4], const unsigned b[2]) {
    asm("mma.sync.aligned.m16n8k16.row.col.f32.f16.f16.f32 "
        "{%0,%1,%2,%3}, {%4,%5,%6,%7}, {%8,%9}, {%0,%1,%2,%3};"
        : "+f"(c[0]), "+f"(c[1]), "+f"(c[2]), "+f"(c[3])
        : "r"(a[0]), "r"(a[1]), "r"(a[2]), "r"(a[3]), "r"(b[0]), "r"(b[1]));
}

DI unsigned packh2(float lo, float hi) {
    __half2 h = __floats2half2_rn(lo, hi);
    return *(unsigned*)&h;
}

// ---- scratch (device globals; no allocations allowed) ----
#define KC 8
__device__ float  g_fc1[2][4096 * 256];
__device__ float  g_fc2[2][4096 * 128];
__device__ float  g_h  [2][4096 * 64];
__device__ __half g_hth[2 * 64 * 4096];
__device__ float  g_aggp[2][KC][4096 * 64];
__device__ int    g_degp[2][KC][4096];
__device__ float  g_part[4096];
__device__ __half g_w1h[2 * 256 * 4096];

// ============================================================================
// Pre-pass: w1 -> RNE fp16 (10 mantissa bits, same as tf32). fc1 loads raw.
// ============================================================================
__global__ void cvt_w1h(const float* __restrict__ w0, const float* __restrict__ w1,
                        __half* __restrict__ out)
{
    int idx = blockIdx.x * blockDim.x + threadIdx.x;      // float4 id, 2*262144 total
    int z = idx >= 262144;
    int li = idx - z * 262144;
    float4 v = ((const float4*)(z ? w1 : w0))[li];
    uint2 u;
    u.x = packh2(v.x, v.y);
    u.y = packh2(v.z, v.w);
    ((uint2*)out)[idx] = u;
}

// ============================================================================
// fc1 via FP16 HMMA (m16n8k16, fp32 acc): C[4096,256] = X @ W1h^T + b.
// (R10 config — best measured.)
// ============================================================================
#define LDH 20
#define ASH(s, r, c) hsm[(s) * (128 * LDH) + (r) * LDH + (c)]
#define BSH(s, r, c) hsm[2 * 128 * LDH + (s) * (128 * LDH) + (r) * LDH + (c)]

__global__ void __launch_bounds__(256)
fc1_h(const float* __restrict__ A0, const float* __restrict__ A1,
      const __half* __restrict__ Bh,
      const float* __restrict__ bias0, const float* __restrict__ bias1,
      float* __restrict__ C)
{
    extern __shared__ unsigned hsm[];
    constexpr int K = 4096, BK = 32;
    const int tid = threadIdx.x, warp = tid >> 5, lane = tid & 31;
    const int wm = warp & 3, wn = warp >> 2;
    const int gid = lane >> 2, tig = lane & 3;
    const int z = blockIdx.z;
    const size_t m0 = (size_t)blockIdx.y * 128;
    const size_t n0 = (size_t)blockIdx.x * 128;
    const int ax = tid & 7, ay = tid >> 3;
    const int bx = tid & 3, by = tid >> 2;

    const float*  A = (z ? A1 : A0) + (m0 + ay) * (size_t)K + ax * 4;
    const __half* B = Bh + (size_t)z * 256 * 4096 + (n0 + by) * (size_t)K + bx * 8;
    const float* bias = z ? bias1 : bias0;
    float* Cb = C + (size_t)z * 4096 * 256;

    float acc[2][8][4];
#pragma unroll
    for (int i = 0; i < 2; i++)
#pragma unroll
        for (int j = 0; j < 8; j++)
#pragma unroll
            for (int e = 0; e < 4; e++) acc[i][j][e] = 0.f;

    float4 ra[4]; uint4 rb[2];
    const int nIter = K / BK;

    auto ldT = [&](int it) {
        const size_t ko = (size_t)it * BK;
#pragma unroll
        for (int p = 0; p < 4; p++)
            ra[p] = *(const float4*)(A + (size_t)p * 32 * K + ko);
#pragma unroll
        for (int p = 0; p < 2; p++)
            rb[p] = *(const uint4*)(B + (size_t)p * 64 * K + ko);
    };
    auto stT = [&](int s) {
#pragma unroll
        for (int p = 0; p < 4; p++) {
            uint2 t;
            t.x = packh2(ra[p].x, ra[p].y);
            t.y = packh2(ra[p].z, ra[p].w);
            *(uint2*)&ASH(s, p * 32 + ay, ax * 2) = t;
        }
#pragma unroll
        for (int p = 0; p < 2; p++)
            *(uint4*)&BSH(s, p * 64 + by, bx * 4) = rb[p];
    };

    ldT(0); stT(0);
    ldT(1);
    __syncthreads();

    for (int it = 0; it < nIter; it++) {
        const int cur = it & 1;
        if (it + 1 < nIter) stT(cur ^ 1);
        if (it + 2 < nIter) ldT(it + 2);
#pragma unroll
        for (int ks = 0; ks < BK / 16; ks++) {
            unsigned af[2][4], bf[8][2];
#pragma unroll
            for (int mt = 0; mt < 2; mt++) {
                int rr = wm * 32 + mt * 16 + gid;
                af[mt][0] = ASH(cur, rr,     ks * 8 + tig);
                af[mt][1] = ASH(cur, rr + 8, ks * 8 + tig);
                af[mt][2] = ASH(cur, rr,     ks * 8 + tig + 4);
                af[mt][3] = ASH(cur, rr + 8, ks * 8 + tig + 4);
            }
#pragma unroll
            for (int nt = 0; nt < 8; nt++) {
                int cc = wn * 64 + nt * 8 + gid;
                bf[nt][0] = BSH(cur, cc, ks * 8 + tig);
                bf[nt][1] = BSH(cur, cc, ks * 8 + tig + 4);
            }
#pragma unroll
            for (int mt = 0; mt < 2; mt++)
#pragma unroll
                for (int nt = 0; nt < 8; nt++)
                    mma16h(acc[mt][nt], af[mt], bf[nt]);
        }
        __syncthreads();
    }

#pragma unroll
    for (int mt = 0; mt < 2; mt++)
#pragma unroll
        for (int nt = 0; nt < 8; nt++) {
            size_t row = m0 + wm * 32 + mt * 16 + gid;
            size_t col = n0 + wn * 64 + nt * 8 + tig * 2;
#pragma unroll
            for (int e = 0; e < 4; e++) {
                size_t r = row + (size_t)(e >> 1) * 8;
                size_t c = col + (size_t)(e & 1);
                Cb[r * 256 + c] = acc[mt][nt][e] + bias[c];
            }
        }
}

// ============================================================================
// Single-buffered split-tf32 GEMM for fc2/fc3 (cheap layers, fp32-class acc).
// WT path stores the transposed copy as RNE fp16 (feeds fp16 agg).
// ============================================================================
template<int BM, int BN, int BK, int NS, bool RELU, bool WT>
__global__ void __launch_bounds__((BM / 32) * (BN / 32) * 32)
gemm_tn(const float* __restrict__ A0, const float* __restrict__ A1,
        const float* __restrict__ B0, const float* __restrict__ B1,
        const float* __restrict__ bias0, const float* __restrict__ bias1,
        float* __restrict__ C0, float* __restrict__ C1,
        __half* __restrict__ T0, __half* __restrict__ T1,
        int M, int N, int K)
{
    constexpr int WM = BM / 32, WN = BN / 32, NW = WM * WN, NT = NW * 32;
    constexpr int LD = BK + 4;
    constexpr int F4 = BK / 4, RA = NT / F4, PA = BM / RA, PB = BN / RA;

    const int z = blockIdx.z;
    const float* A = z ? A1 : A0;
    const float* B = z ? B1 : B0;
    const float* bias = z ? bias1 : bias0;
    float* C = z ? C1 : C0;
    __half* T = z ? T1 : T0;

    __shared__ unsigned As[NS][BM][LD];
    __shared__ unsigned Bs[NS][BN][LD];

    const int tid = threadIdx.x, warp = tid >> 5, lane = tid & 31;
    const int wm = warp % WM, wn = warp / WM;
    const int gid = lane >> 2, tig = lane & 3;
    const size_t m0 = (size_t)blockIdx.x * BM;
    const size_t n0 = (size_t)blockIdx.y * BN;
    const int ax = tid % F4, ay = tid / F4;

    float acc[2][4][4];
#pragma unroll
    for (int i = 0; i < 2; i++)
#pragma unroll
        for (int j = 0; j < 4; j++)
#pragma unroll
            for (int e = 0; e < 4; e++) acc[i][j][e] = 0.f;

    float4 ra[PA], rb[PB];
#pragma unroll
    for (int p = 0; p < PA; p++)
        ra[p] = *(const float4*)(A + (m0 + p * RA + ay) * K + ax * 4);
#pragma unroll
    for (int p = 0; p < PB; p++)
        rb[p] = *(const float4*)(B + (n0 + p * RA + ay) * K + ax * 4);

    for (int k0 = 0; k0 < K; k0 += BK) {
#pragma unroll
        for (int p = 0; p < PA; p++) {
            int row = p * RA + ay;
            unsigned h0 = f2t(ra[p].x), h1 = f2t(ra[p].y), h2 = f2t(ra[p].z), h3 = f2t(ra[p].w);
            As[0][row][ax * 4 + 0] = h0; As[0][row][ax * 4 + 1] = h1;
            As[0][row][ax * 4 + 2] = h2; As[0][row][ax * 4 + 3] = h3;
            if (NS == 2) {
                As[NS - 1][row][ax * 4 + 0] = f2t(ra[p].x - __uint_as_float(h0));
                As[NS - 1][row][ax * 4 + 1] = f2t(ra[p].y - __uint_as_float(h1));
                As[NS - 1][row][ax * 4 + 2] = f2t(ra[p].z - __uint_as_float(h2));
                As[NS - 1][row][ax * 4 + 3] = f2t(ra[p].w - __uint_as_float(h3));
            }
        }
#pragma unroll
        for (int p = 0; p < PB; p++) {
            int row = p * RA + ay;
            unsigned h0 = f2t(rb[p].x), h1 = f2t(rb[p].y), h2 = f2t(rb[p].z), h3 = f2t(rb[p].w);
            Bs[0][row][ax * 4 + 0] = h0; Bs[0][row][ax * 4 + 1] = h1;
            Bs[0][row][ax * 4 + 2] = h2; Bs[0][row][ax * 4 + 3] = h3;
            if (NS == 2) {
                Bs[NS - 1][row][ax * 4 + 0] = f2t(rb[p].x - __uint_as_float(h0));
                Bs[NS - 1][row][ax * 4 + 1] = f2t(rb[p].y - __uint_as_float(h1));
                Bs[NS - 1][row][ax * 4 + 2] = f2t(rb[p].z - __uint_as_float(h2));
                Bs[NS - 1][row][ax * 4 + 3] = f2t(rb[p].w - __uint_as_float(h3));
            }
        }
        __syncthreads();

        if (k0 + BK < K) {
#pragma unroll
            for (int p = 0; p < PA; p++)
                ra[p] = *(const float4*)(A + (m0 + p * RA + ay) * K + (k0 + BK) + ax * 4);
#pragma unroll
            for (int p = 0; p < PB; p++)
                rb[p] = *(const float4*)(B + (n0 + p * RA + ay) * K + (k0 + BK) + ax * 4);
        }

#pragma unroll
        for (int ks = 0; ks < BK / 8; ks++) {
            unsigned af[NS][2][4], bf[NS][4][2];
#pragma unroll
            for (int s = 0; s < NS; s++) {
#pragma unroll
                for (int mt = 0; mt < 2; mt++) {
                    int rr = wm * 32 + mt * 16 + gid;
                    af[s][mt][0] = As[s][rr    ][ks * 8 + tig];
                    af[s][mt][1] = As[s][rr + 8][ks * 8 + tig];
                    af[s][mt][2] = As[s][rr    ][ks * 8 + tig + 4];
                    af[s][mt][3] = As[s][rr + 8][ks * 8 + tig + 4];
                }
#pragma unroll
                for (int nt = 0; nt < 4; nt++) {
                    int cc = wn * 32 + nt * 8 + gid;
                    bf[s][nt][0] = Bs[s][cc][ks * 8 + tig];
                    bf[s][nt][1] = Bs[s][cc][ks * 8 + tig + 4];
                }
            }
#pragma unroll
            for (int mt = 0; mt < 2; mt++)
#pragma unroll
                for (int nt = 0; nt < 4; nt++) {
                    mma8(acc[mt][nt], af[0][mt], bf[0][nt]);
                    if (NS == 2) {
                        mma8(acc[mt][nt], af[0][mt], bf[NS - 1][nt]);
                        mma8(acc[mt][nt], af[NS - 1][mt], bf[0][nt]);
                    }
                }
        }
        __syncthreads();
    }

#pragma unroll
    for (int mt = 0; mt < 2; mt++) {
#pragma unroll
        for (int nt = 0; nt < 4; nt++) {
            size_t row = m0 + wm * 32 + mt * 16 + gid;
            size_t col = n0 + wn * 32 + nt * 8 + tig * 2;
#pragma unroll
            for (int e = 0; e < 4; e++) {
                size_t r = row + (size_t)(e >> 1) * 8;
                size_t c = col + (size_t)(e & 1);
                float v = acc[mt][nt][e] + bias[c];
                if (RELU) v = fmaxf(v, 0.f);
                C[r * N + c] = v;
                if (WT) T[c * (size_t)M + r] = __float2half_rn(v);
            }
        }
    }
}

// ============================================================================
// Split-K masked aggregation partial — FP16 HMMA (m16n8k16):
// A = masked alpha packed RNE half2; B = Ht halves (from fc3 epilogue).
// BM=BN=64, BK=32, 128 thr, dual-buffered. grid (64, KC, 2).
// ============================================================================
#define LDA 20
__global__ void __launch_bounds__(128)
agg_part_h(const int* __restrict__ adjA, const int* __restrict__ adjB,
           const float* __restrict__ alpha,
           const __half* __restrict__ HtA, const __half* __restrict__ HtB,
           float* __restrict__ aggp, int* __restrict__ degp, int K)
{
    constexpr int BK = 32;
    __shared__ unsigned Ash[2][64][LDA];
    __shared__ unsigned Bsh[2][64][LDA];
    __shared__ int sdeg[64];

    const int tid = threadIdx.x, warp = tid >> 5, lane = tid & 31;
    const int wm = warp & 1, wn = warp >> 1;          // 2 m-warps x 2 n-warps
    const int gid = lane >> 2, tig = lane & 3;
    const int z = blockIdx.z, kc = blockIdx.y;
    const int* adj = z ? adjB : adjA;
    const __half* Ht = z ? HtB : HtA;
    const int KCH = K / KC;
    const size_t kbase = (size_t)kc * KCH;
    const size_t m0 = (size_t)blockIdx.x * 64;
    const int ax = tid & 7, ay = tid >> 3;            // A: 8 float4/row, 16 rows/pass
    const int bx = tid & 3, by = tid >> 2;            // B: 4 uint4/row (32 halves), 32 rows/pass

    if (tid < 64) sdeg[tid] = 0;

    float acc[2][4][4];
#pragma unroll
    for (int i = 0; i < 2; i++)
#pragma unroll
        for (int j = 0; j < 4; j++)
#pragma unroll
            for (int e = 0; e < 4; e++) acc[i][j][e] = 0.f;

    int cnt[4];
#pragma unroll
    for (int p = 0; p < 4; p++) cnt[p] = 0;

    int4 rma[4]; float4 rva[4]; uint4 rb[2];
    const int nIter = KCH / BK;                        // 16

    auto ldA = [&](int it) {
        const size_t ko = kbase + (size_t)it * BK;
#pragma unroll
        for (int p = 0; p < 4; p++) {
            size_t g = (m0 + p * 16 + ay) * (size_t)K + ko + ax * 4;
            rma[p] = *(const int4*)(adj + g);
            rva[p] = *(const float4*)(alpha + g);
        }
#pragma unroll
        for (int p = 0; p < 2; p++)
            rb[p] = *(const uint4*)(Ht + (size_t)(p * 32 + by) * K + ko + bx * 8);
    };
    auto stA = [&](int buf) {
#pragma unroll
        for (int p = 0; p < 4; p++) {
            int row = p * 16 + ay;
            int mx = (rma[p].x == 1), my = (rma[p].y == 1);
            int mz = (rma[p].z == 1), mw = (rma[p].w == 1);
            cnt[p] += mx + my + mz + mw;
            uint2 t;
            t.x = packh2(mx ? rva[p].x : 0.f, my ? rva[p].y : 0.f);
            t.y = packh2(mz ? rva[p].z : 0.f, mw ? rva[p].w : 0.f);
            *(uint2*)&Ash[buf][row][ax * 2] = t;
        }
#pragma unroll
        for (int p = 0; p < 2; p++)
            *(uint4*)&Bsh[buf][p * 32 + by][bx * 4] = rb[p];
    };

    ldA(0); stA(0);
    if (nIter > 1) ldA(1);
    __syncthreads();

    for (int it = 0; it < nIter; it++) {
        const int cur = it & 1;
        if (it + 1 < nIter) stA(cur ^ 1);
        if (it + 2 < nIter) ldA(it + 2);
#pragma unroll
        for (int ks = 0; ks < BK / 16; ks++) {         // 2 k16 steps
            unsigned af[2][4], bf[4][2];
#pragma unroll
            for (int mt = 0; mt < 2; mt++) {
                int rr = wm * 32 + mt * 16 + gid;
                af[mt][0] = Ash[cur][rr    ][ks * 8 + tig];
                af[mt][1] = Ash[cur][rr + 8][ks * 8 + tig];
                af[mt][2] = Ash[cur][rr    ][ks * 8 + tig + 4];
                af[mt][3] = Ash[cur][rr + 8][ks * 8 + tig + 4];
            }
#pragma unroll
            for (int nt = 0; nt < 4; nt++) {
                int cc = wn * 32 + nt * 8 + gid;
                bf[nt][0] = Bsh[cur][cc][ks * 8 + tig];
                bf[nt][1] = Bsh[cur][cc][ks * 8 + tig + 4];
            }
#pragma unroll
            for (int mt = 0; mt < 2; mt++)
#pragma unroll
                for (int nt = 0; nt < 4; nt++)
                    mma16h(acc[mt][nt], af[mt], bf[nt]);
        }
        __syncthreads();
    }

#pragma unroll
    for (int p = 0; p < 4; p++) atomicAdd(&sdeg[p * 16 + ay], cnt[p]);
    __syncthreads();

    float* aout = aggp + ((size_t)z * KC + kc) * 4096 * 64;
    int*   dout = degp + ((size_t)z * KC + kc) * 4096;
    if (tid < 64) dout[m0 + tid] = sdeg[tid];
#pragma unroll
    for (int mt = 0; mt < 2; mt++)
#pragma unroll
        for (int nt = 0; nt < 4; nt++) {
            size_t row = m0 + wm * 32 + mt * 16 + gid;
            size_t col = wn * 32 + nt * 8 + tig * 2;
#pragma unroll
            for (int e = 0; e < 4; e++) {
                size_t r = row + (size_t)(e >> 1) * 8;
                size_t c = col + (size_t)(e & 1);
                aout[r * 64 + c] = acc[mt][nt][e];
            }
        }
}

// ============================================================================
// Classifier stage 1, fused with aggregation finish — WIDE grid (2048 blocks
// x 128 thr).
// ============================================================================
__global__ void __launch_bounds__(128)
clf_partial(const float* __restrict__ aggp, const int* __restrict__ degp,
            const float* __restrict__ HA, const float* __restrict__ HB,
            const float* __restrict__ Wp,
            const float* __restrict__ w, float* __restrict__ part)
{
    const int L = 4096 * 64;
    const int TOT = 2 * L;
    const int chunk = 256;
    int base = blockIdx.x * chunk;
    const float W00 = Wp[0];
    float s0 = 0.f, s1 = 0.f;
#pragma unroll
    for (int q = 0; q < 2; q++) {
        int i = base + threadIdx.x + q * 128;
        int z = i >= L;
        int li = i - z * L;
        int r = li >> 6;
        const float* ap = aggp + (size_t)z * KC * L;
        const int* dp = degp + (size_t)z * KC * 4096;
        float s = 0.f; int d = 0;
#pragma unroll
        for (int kc = 0; kc < KC; kc++) {
            s += ap[(size_t)kc * L + li];
            d += dp[kc * 4096 + r];
        }
        const float* H = z ? HB : HA;
        float v = d ? s * W00 / (float)d + H[li] : 0.f;
        s0 += v * w[i];
        s1 += v * w[TOT + i];
    }
    __shared__ float sm[4][2];
#pragma unroll
    for (int o = 16; o; o >>= 1) {
        s0 += __shfl_down_sync(0xffffffffu, s0, o);
        s1 += __shfl_down_sync(0xffffffffu, s1, o);
    }
    if ((threadIdx.x & 31) == 0) { sm[threadIdx.x >> 5][0] = s0; sm[threadIdx.x >> 5][1] = s1; }
    __syncthreads();
    if (threadIdx.x == 0) {
        float a = 0.f, b = 0.f;
        for (int i = 0; i < 4; i++) { a += sm[i][0]; b += sm[i][1]; }
        part[blockIdx.x * 2 + 0] = a;
        part[blockIdx.x * 2 + 1] = b;
    }
}

__global__ void clf_final(const float* __restrict__ part, const float* __restrict__ bias,
                          float* __restrict__ out, int nb)
{
    float s0 = 0.f, s1 = 0.f;
    for (int i = threadIdx.x; i < nb; i += blockDim.x) { s0 += part[i * 2]; s1 += part[i * 2 + 1]; }
    __shared__ float sm[8][2];
#pragma unroll
    for (int o = 16; o; o >>= 1) {
        s0 += __shfl_down_sync(0xffffffffu, s0, o);
        s1 += __shfl_down_sync(0xffffffffu, s1, o);
    }
    if ((threadIdx.x & 31) == 0) { sm[threadIdx.x >> 5][0] = s0; sm[threadIdx.x >> 5][1] = s1; }
    __syncthreads();
    if (threadIdx.x == 0) {
        float a = 0.f, b = 0.f;
        for (int i = 0; i < (int)(blockDim.x >> 5); i++) { a += sm[i][0]; b += sm[i][1]; }
        out[0] = a + bias[0];
        out[1] = b + bias[1];
    }
}

// ============================================================================
extern "C" void kernel_launch(void* const* d_in, const int* in_sizes, int n_in,
                              void* d_out, int out_size)
{
    const float* x1    = (const float*)d_in[0];
    const float* x2    = (const float*)d_in[1];
    const int*   adj1  = (const int*)d_in[2];
    const int*   adj2  = (const int*)d_in[3];
    const float* e1_w1 = (const float*)d_in[4];
    const float* e1_b1 = (const float*)d_in[5];
    const float* e1_w2 = (const float*)d_in[6];
    const float* e1_b2 = (const float*)d_in[7];
    const float* e1_w3 = (const float*)d_in[8];
    const float* e1_b3 = (const float*)d_in[9];
    const float* e2_w1 = (const float*)d_in[10];
    const float* e2_b1 = (const float*)d_in[11];
    const float* e2_w2 = (const float*)d_in[12];
    const float* e2_b2 = (const float*)d_in[13];
    const float* e2_w3 = (const float*)d_in[14];
    const float* e2_b3 = (const float*)d_in[15];
    const float* W     = (const float*)d_in[16];
    const float* alpha = (const float*)d_in[17];
    const float* clf_w = (const float*)d_in[18];
    const float* clf_b = (const float*)d_in[19];

    float *fc1p, *fc2p, *hp, *partp, *aggpp;
    __half *w1hp, *hthp;
    int *degpp;
    cudaGetSymbolAddress((void**)&fc1p,  g_fc1);
    cudaGetSymbolAddress((void**)&fc2p,  g_fc2);
    cudaGetSymbolAddress((void**)&hp,    g_h);
    cudaGetSymbolAddress((void**)&hthp,  g_hth);
    cudaGetSymbolAddress((void**)&partp, g_part);
    cudaGetSymbolAddress((void**)&aggpp, g_aggp);
    cudaGetSymbolAddress((void**)&degpp, g_degp);
    cudaGetSymbolAddress((void**)&w1hp,  g_w1h);

    const int FC1_SMEM = (2 * 128 * LDH + 2 * 128 * LDH) * 4;   // 40960 B
    cudaFuncSetAttribute(fc1_h, cudaFuncAttributeMaxDynamicSharedMemorySize, FC1_SMEM);

    // pre-pass: w1 -> RNE fp16
    cvt_w1h<<<2048, 256>>>(e1_w1, e2_w1, w1hp);

    // fc1 (fp16 HMMA): grid (nt=2, mt=32, z=2) = 128 CTAs
    fc1_h<<<dim3(2, 32, 2), 256, FC1_SMEM>>>(
        x1, x2, w1hp, e1_b1, e2_b1, fc1p);

    // fc2: [4096,256] x [128,256]^T -> [4096,128]     (split-tf32)
    gemm_tn<64, 64, 32, 2, false, false><<<dim3(64, 2, 2), 128>>>(
        fc1p, fc1p + 4096 * 256, e1_w2, e2_w2, e1_b2, e2_b2,
        fc2p, fc2p + 4096 * 128, nullptr, nullptr, 4096, 128, 256);

    // fc3+relu: [4096,128] x [64,128]^T -> [4096,64] (+ fp16 transpose for agg)
    gemm_tn<64, 64, 32, 2, true, true><<<dim3(64, 1, 2), 128>>>(
        fc2p, fc2p + 4096 * 128, e1_w3, e2_w3, e1_b3, e2_b3,
        hp, hp + 4096 * 64, hthp, hthp + 64 * 4096, 4096, 64, 128);

    // split-K masked aggregation (fp16 HMMA)
    agg_part_h<<<dim3(64, KC, 2), 128>>>(
        adj1, adj2, alpha, hthp, hthp + 64 * 4096, aggpp, degpp, 4096);

    // classifier stage 1 (fused agg-finish, wide grid) + final
    clf_partial<<<2048, 128>>>(aggpp, degpp, hp, hp + 4096 * 64, W, clf_w, partp);
    clf_final<<<1, 256>>>(partp, clf_b, (float*)d_out, 2048);

    (void)in_sizes; (void)n_in; (void)out_size;
}

// round 12
// speedup vs baseline: 1.3995x; 1.0969x over previous
#include <cuda_runtime.h>
#include <cuda_fp16.h>
#include <cstdint>

#define DI __device__ __forceinline__

DI unsigned f2t(float x) { unsigned u; asm("cvt.rna.tf32.f32 %0, %1;" : "=r"(u) : "f"(x)); return u; }

DI void mma8(float c[4], const unsigned a[4], const unsigned b[2]) {
    asm("mma.sync.aligned.m16n8k8.row.col.f32.tf32.tf32.f32 "
        "{%0,%1,%2,%3}, {%4,%5,%6,%7}, {%8,%9}, {%0,%1,%2,%3};"
        : "+f"(c[0]), "+f"(c[1]), "+f"(c[2]), "+f"(c[3])
        : "r"(a[0]), "r"(a[1]), "r"(a[2]), "r"(a[3]), "r"(b[0]), "r"(b[1]));
}

DI void mma16h(float c[4], const unsigned a[4], const unsigned b[2]) {
    asm("mma.sync.aligned.m16n8k16.row.col.f32.f16.f16.f32 "
        "{%0,%1,%2,%3}, {%4,%5,%6,%7}, {%8,%9}, {%0,%1,%2,%3};"
        : "+f"(c[0]), "+f"(c[1]), "+f"(c[2]), "+f"(c[3])
        : "r"(a[0]), "r"(a[1]), "r"(a[2]), "r"(a[3]), "r"(b[0]), "r"(b[1]));
}

DI unsigned packh2(float lo, float hi) {
    __half2 h = __floats2half2_rn(lo, hi);
    return *(unsigned*)&h;
}

// ---- scratch (device globals; no allocations allowed) ----
#define KC 8
__device__ float  g_fc1[2][4096 * 256];
__device__ float  g_fc2[2][4096 * 128];
__device__ float  g_h  [2][4096 * 64];
__device__ __half g_hth[2 * 64 * 4096];
__device__ float  g_aggp[2][KC][4096 * 64];
__device__ int    g_degp[2][KC][4096];
__device__ float  g_part[4096];
__device__ __half g_w1h[2 * 256 * 4096];

// ============================================================================
// Pre-pass: w1 -> RNE fp16.
// ============================================================================
__global__ void cvt_w1h(const float* __restrict__ w0, const float* __restrict__ w1,
                        __half* __restrict__ out)
{
    int idx = blockIdx.x * blockDim.x + threadIdx.x;
    int z = idx >= 262144;
    int li = idx - z * 262144;
    float4 v = ((const float4*)(z ? w1 : w0))[li];
    uint2 u;
    u.x = packh2(v.x, v.y);
    u.y = packh2(v.z, v.w);
    ((uint2*)out)[idx] = u;
}

// ============================================================================
// fc1 via FP16 HMMA, BK=64 (half the barriers, double the MLP):
// C[4096,256] = X @ W1h^T + b.  BM=128, BN=128, 256 thr, 4m x 2n warps,
// warp tile 32x64.  A: LDG fp32 -> RNE half2 -> STS.  B: raw halves.
// Dual-buffered.  grid (nt=2, mt=32, z=2) = 128 CTAs.
// ============================================================================
#define LDH 36
#define ASH(s, r, c) hsm[(s) * (128 * LDH) + (r) * LDH + (c)]
#define BSH(s, r, c) hsm[2 * 128 * LDH + (s) * (128 * LDH) + (r) * LDH + (c)]

__global__ void __launch_bounds__(256)
fc1_h(const float* __restrict__ A0, const float* __restrict__ A1,
      const __half* __restrict__ Bh,
      const float* __restrict__ bias0, const float* __restrict__ bias1,
      float* __restrict__ C)
{
    extern __shared__ unsigned hsm[];
    constexpr int K = 4096, BK = 64;
    const int tid = threadIdx.x, warp = tid >> 5, lane = tid & 31;
    const int wm = warp & 3, wn = warp >> 2;
    const int gid = lane >> 2, tig = lane & 3;
    const int z = blockIdx.z;
    const size_t m0 = (size_t)blockIdx.y * 128;
    const size_t n0 = (size_t)blockIdx.x * 128;
    const int ax = tid & 15, ay = tid >> 4;           // A: 16 float4/row, 16 rows/pass
    const int bx = tid & 7,  by = tid >> 3;           // B: 8 uint4/row, 32 rows/pass

    const float*  A = (z ? A1 : A0) + (m0 + ay) * (size_t)K + ax * 4;
    const __half* B = Bh + (size_t)z * 256 * 4096 + (n0 + by) * (size_t)K + bx * 8;
    const float* bias = z ? bias1 : bias0;
    float* Cb = C + (size_t)z * 4096 * 256;

    float acc[2][8][4];
#pragma unroll
    for (int i = 0; i < 2; i++)
#pragma unroll
        for (int j = 0; j < 8; j++)
#pragma unroll
            for (int e = 0; e < 4; e++) acc[i][j][e] = 0.f;

    float4 ra[8]; uint4 rb[4];
    const int nIter = K / BK;                          // 64

    auto ldT = [&](int it) {
        const size_t ko = (size_t)it * BK;
#pragma unroll
        for (int p = 0; p < 8; p++)
            ra[p] = *(const float4*)(A + (size_t)p * 16 * K + ko);
#pragma unroll
        for (int p = 0; p < 4; p++)
            rb[p] = *(const uint4*)(B + (size_t)p * 32 * K + ko);
    };
    auto stT = [&](int s) {
#pragma unroll
        for (int p = 0; p < 8; p++) {
            uint2 t;
            t.x = packh2(ra[p].x, ra[p].y);
            t.y = packh2(ra[p].z, ra[p].w);
            *(uint2*)&ASH(s, p * 16 + ay, ax * 2) = t;
        }
#pragma unroll
        for (int p = 0; p < 4; p++)
            *(uint4*)&BSH(s, p * 32 + by, bx * 4) = rb[p];
    };

    ldT(0); stT(0);
    ldT(1);
    __syncthreads();

    for (int it = 0; it < nIter; it++) {
        const int cur = it & 1;
        if (it + 1 < nIter) stT(cur ^ 1);
        if (it + 2 < nIter) ldT(it + 2);
#pragma unroll
        for (int ks = 0; ks < BK / 16; ks++) {         // 4 k16 steps
            unsigned af[2][4], bf[8][2];
#pragma unroll
            for (int mt = 0; mt < 2; mt++) {
                int rr = wm * 32 + mt * 16 + gid;
                af[mt][0] = ASH(cur, rr,     ks * 8 + tig);
                af[mt][1] = ASH(cur, rr + 8, ks * 8 + tig);
                af[mt][2] = ASH(cur, rr,     ks * 8 + tig + 4);
                af[mt][3] = ASH(cur, rr + 8, ks * 8 + tig + 4);
            }
#pragma unroll
            for (int nt = 0; nt < 8; nt++) {
                int cc = wn * 64 + nt * 8 + gid;
                bf[nt][0] = BSH(cur, cc, ks * 8 + tig);
                bf[nt][1] = BSH(cur, cc, ks * 8 + tig + 4);
            }
#pragma unroll
            for (int mt = 0; mt < 2; mt++)
#pragma unroll
                for (int nt = 0; nt < 8; nt++)
                    mma16h(acc[mt][nt], af[mt], bf[nt]);
        }
        __syncthreads();
    }

#pragma unroll
    for (int mt = 0; mt < 2; mt++)
#pragma unroll
        for (int nt = 0; nt < 8; nt++) {
            size_t row = m0 + wm * 32 + mt * 16 + gid;
            size_t col = n0 + wn * 64 + nt * 8 + tig * 2;
#pragma unroll
            for (int e = 0; e < 4; e++) {
                size_t r = row + (size_t)(e >> 1) * 8;
                size_t c = col + (size_t)(e & 1);
                Cb[r * 256 + c] = acc[mt][nt][e] + bias[c];
            }
        }
}

// ============================================================================
// Single-buffered split-tf32 GEMM for fc2/fc3 (cheap layers, fp32-class acc).
// WT path stores the transposed copy as RNE fp16 (feeds fp16 agg).
// ============================================================================
template<int BM, int BN, int BK, int NS, bool RELU, bool WT>
__global__ void __launch_bounds__((BM / 32) * (BN / 32) * 32)
gemm_tn(const float* __restrict__ A0, const float* __restrict__ A1,
        const float* __restrict__ B0, const float* __restrict__ B1,
        const float* __restrict__ bias0, const float* __restrict__ bias1,
        float* __restrict__ C0, float* __restrict__ C1,
        __half* __restrict__ T0, __half* __restrict__ T1,
        int M, int N, int K)
{
    constexpr int WM = BM / 32, WN = BN / 32, NW = WM * WN, NT = NW * 32;
    constexpr int LD = BK + 4;
    constexpr int F4 = BK / 4, RA = NT / F4, PA = BM / RA, PB = BN / RA;

    const int z = blockIdx.z;
    const float* A = z ? A1 : A0;
    const float* B = z ? B1 : B0;
    const float* bias = z ? bias1 : bias0;
    float* C = z ? C1 : C0;
    __half* T = z ? T1 : T0;

    __shared__ unsigned As[NS][BM][LD];
    __shared__ unsigned Bs[NS][BN][LD];

    const int tid = threadIdx.x, warp = tid >> 5, lane = tid & 31;
    const int wm = warp % WM, wn = warp / WM;
    const int gid = lane >> 2, tig = lane & 3;
    const size_t m0 = (size_t)blockIdx.x * BM;
    const size_t n0 = (size_t)blockIdx.y * BN;
    const int ax = tid % F4, ay = tid / F4;

    float acc[2][4][4];
#pragma unroll
    for (int i = 0; i < 2; i++)
#pragma unroll
        for (int j = 0; j < 4; j++)
#pragma unroll
            for (int e = 0; e < 4; e++) acc[i][j][e] = 0.f;

    float4 ra[PA], rb[PB];
#pragma unroll
    for (int p = 0; p < PA; p++)
        ra[p] = *(const float4*)(A + (m0 + p * RA + ay) * K + ax * 4);
#pragma unroll
    for (int p = 0; p < PB; p++)
        rb[p] = *(const float4*)(B + (n0 + p * RA + ay) * K + ax * 4);

    for (int k0 = 0; k0 < K; k0 += BK) {
#pragma unroll
        for (int p = 0; p < PA; p++) {
            int row = p * RA + ay;
            unsigned h0 = f2t(ra[p].x), h1 = f2t(ra[p].y), h2 = f2t(ra[p].z), h3 = f2t(ra[p].w);
            As[0][row][ax * 4 + 0] = h0; As[0][row][ax * 4 + 1] = h1;
            As[0][row][ax * 4 + 2] = h2; As[0][row][ax * 4 + 3] = h3;
            if (NS == 2) {
                As[NS - 1][row][ax * 4 + 0] = f2t(ra[p].x - __uint_as_float(h0));
                As[NS - 1][row][ax * 4 + 1] = f2t(ra[p].y - __uint_as_float(h1));
                As[NS - 1][row][ax * 4 + 2] = f2t(ra[p].z - __uint_as_float(h2));
                As[NS - 1][row][ax * 4 + 3] = f2t(ra[p].w - __uint_as_float(h3));
            }
        }
#pragma unroll
        for (int p = 0; p < PB; p++) {
            int row = p * RA + ay;
            unsigned h0 = f2t(rb[p].x), h1 = f2t(rb[p].y), h2 = f2t(rb[p].z), h3 = f2t(rb[p].w);
            Bs[0][row][ax * 4 + 0] = h0; Bs[0][row][ax * 4 + 1] = h1;
            Bs[0][row][ax * 4 + 2] = h2; Bs[0][row][ax * 4 + 3] = h3;
            if (NS == 2) {
                Bs[NS - 1][row][ax * 4 + 0] = f2t(rb[p].x - __uint_as_float(h0));
                Bs[NS - 1][row][ax * 4 + 1] = f2t(rb[p].y - __uint_as_float(h1));
                Bs[NS - 1][row][ax * 4 + 2] = f2t(rb[p].z - __uint_as_float(h2));
                Bs[NS - 1][row][ax * 4 + 3] = f2t(rb[p].w - __uint_as_float(h3));
            }
        }
        __syncthreads();

        if (k0 + BK < K) {
#pragma unroll
            for (int p = 0; p < PA; p++)
                ra[p] = *(const float4*)(A + (m0 + p * RA + ay) * K + (k0 + BK) + ax * 4);
#pragma unroll
            for (int p = 0; p < PB; p++)
                rb[p] = *(const float4*)(B + (n0 + p * RA + ay) * K + (k0 + BK) + ax * 4);
        }

#pragma unroll
        for (int ks = 0; ks < BK / 8; ks++) {
            unsigned af[NS][2][4], bf[NS][4][2];
#pragma unroll
            for (int s = 0; s < NS; s++) {
#pragma unroll
                for (int mt = 0; mt < 2; mt++) {
                    int rr = wm * 32 + mt * 16 + gid;
                    af[s][mt][0] = As[s][rr    ][ks * 8 + tig];
                    af[s][mt][1] = As[s][rr + 8][ks * 8 + tig];
                    af[s][mt][2] = As[s][rr    ][ks * 8 + tig + 4];
                    af[s][mt][3] = As[s][rr + 8][ks * 8 + tig + 4];
                }
#pragma unroll
                for (int nt = 0; nt < 4; nt++) {
                    int cc = wn * 32 + nt * 8 + gid;
                    bf[s][nt][0] = Bs[s][cc][ks * 8 + tig];
                    bf[s][nt][1] = Bs[s][cc][ks * 8 + tig + 4];
                }
            }
#pragma unroll
            for (int mt = 0; mt < 2; mt++)
#pragma unroll
                for (int nt = 0; nt < 4; nt++) {
                    mma8(acc[mt][nt], af[0][mt], bf[0][nt]);
                    if (NS == 2) {
                        mma8(acc[mt][nt], af[0][mt], bf[NS - 1][nt]);
                        mma8(acc[mt][nt], af[NS - 1][mt], bf[0][nt]);
                    }
                }
        }
        __syncthreads();
    }

#pragma unroll
    for (int mt = 0; mt < 2; mt++) {
#pragma unroll
        for (int nt = 0; nt < 4; nt++) {
            size_t row = m0 + wm * 32 + mt * 16 + gid;
            size_t col = n0 + wn * 32 + nt * 8 + tig * 2;
#pragma unroll
            for (int e = 0; e < 4; e++) {
                size_t r = row + (size_t)(e >> 1) * 8;
                size_t c = col + (size_t)(e & 1);
                float v = acc[mt][nt][e] + bias[c];
                if (RELU) v = fmaxf(v, 0.f);
                C[r * N + c] = v;
                if (WT) T[c * (size_t)M + r] = __float2half_rn(v);
            }
        }
    }
}

// ============================================================================
// Split-K masked aggregation partial — FP16 HMMA, BK=64 (double MLP, half
// the barriers).  BM=BN=64, 128 thr, dual-buffered.  grid (64, KC, 2).
// ============================================================================
#define LDA 36
__global__ void __launch_bounds__(128)
agg_part_h(const int* __restrict__ adjA, const int* __restrict__ adjB,
           const float* __restrict__ alpha,
           const __half* __restrict__ HtA, const __half* __restrict__ HtB,
           float* __restrict__ aggp, int* __restrict__ degp, int K)
{
    constexpr int BK = 64;
    __shared__ unsigned Ash[2][64][LDA];
    __shared__ unsigned Bsh[2][64][LDA];
    __shared__ int sdeg[64];

    const int tid = threadIdx.x, warp = tid >> 5, lane = tid & 31;
    const int wm = warp & 1, wn = warp >> 1;          // 2 m-warps x 2 n-warps
    const int gid = lane >> 2, tig = lane & 3;
    const int z = blockIdx.z, kc = blockIdx.y;
    const int* adj = z ? adjB : adjA;
    const __half* Ht = z ? HtB : HtA;
    const int KCH = K / KC;                            // 512
    const size_t kbase = (size_t)kc * KCH;
    const size_t m0 = (size_t)blockIdx.x * 64;
    const int ax = tid & 15, ay = tid >> 4;            // A: 16 float4/row, 8 rows/pass
    const int bx = tid & 7,  by = tid >> 3;            // B: 8 uint4/row, 16 rows/pass

    if (tid < 64) sdeg[tid] = 0;

    float acc[2][4][4];
#pragma unroll
    for (int i = 0; i < 2; i++)
#pragma unroll
        for (int j = 0; j < 4; j++)
#pragma unroll
            for (int e = 0; e < 4; e++) acc[i][j][e] = 0.f;

    int cnt[8];
#pragma unroll
    for (int p = 0; p < 8; p++) cnt[p] = 0;

    int4 rma[8]; float4 rva[8]; uint4 rb[4];
    const int nIter = KCH / BK;                        // 8

    auto ldA = [&](int it) {
        const size_t ko = kbase + (size_t)it * BK;
#pragma unroll
        for (int p = 0; p < 8; p++) {
            size_t g = (m0 + p * 8 + ay) * (size_t)K + ko + ax * 4;
            rma[p] = *(const int4*)(adj + g);
            rva[p] = *(const float4*)(alpha + g);
        }
#pragma unroll
        for (int p = 0; p < 4; p++)
            rb[p] = *(const uint4*)(Ht + (size_t)(p * 16 + by) * K + ko + bx * 8);
    };
    auto stA = [&](int buf) {
#pragma unroll
        for (int p = 0; p < 8; p++) {
            int row = p * 8 + ay;
            int mx = (rma[p].x == 1), my = (rma[p].y == 1);
            int mz = (rma[p].z == 1), mw = (rma[p].w == 1);
            cnt[p] += mx + my + mz + mw;
            uint2 t;
            t.x = packh2(mx ? rva[p].x : 0.f, my ? rva[p].y : 0.f);
            t.y = packh2(mz ? rva[p].z : 0.f, mw ? rva[p].w : 0.f);
            *(uint2*)&Ash[buf][row][ax * 2] = t;
        }
#pragma unroll
        for (int p = 0; p < 4; p++)
            *(uint4*)&Bsh[buf][p * 16 + by][bx * 4] = rb[p];
    };

    ldA(0); stA(0);
    if (nIter > 1) ldA(1);
    __syncthreads();

    for (int it = 0; it < nIter; it++) {
        const int cur = it & 1;
        if (it + 1 < nIter) stA(cur ^ 1);
        if (it + 2 < nIter) ldA(it + 2);
#pragma unroll
        for (int ks = 0; ks < BK / 16; ks++) {         // 4 k16 steps
            unsigned af[2][4], bf[4][2];
#pragma unroll
            for (int mt = 0; mt < 2; mt++) {
                int rr = wm * 32 + mt * 16 + gid;
                af[mt][0] = Ash[cur][rr    ][ks * 8 + tig];
                af[mt][1] = Ash[cur][rr + 8][ks * 8 + tig];
                af[mt][2] = Ash[cur][rr    ][ks * 8 + tig + 4];
                af[mt][3] = Ash[cur][rr + 8][ks * 8 + tig + 4];
            }
#pragma unroll
            for (int nt = 0; nt < 4; nt++) {
                int cc = wn * 32 + nt * 8 + gid;
                bf[nt][0] = Bsh[cur][cc][ks * 8 + tig];
                bf[nt][1] = Bsh[cur][cc][ks * 8 + tig + 4];
            }
#pragma unroll
            for (int mt = 0; mt < 2; mt++)
#pragma unroll
                for (int nt = 0; nt < 4; nt++)
                    mma16h(acc[mt][nt], af[mt], bf[nt]);
        }
        __syncthreads();
    }

#pragma unroll
    for (int p = 0; p < 8; p++) atomicAdd(&sdeg[p * 8 + ay], cnt[p]);
    __syncthreads();

    float* aout = aggp + ((size_t)z * KC + kc) * 4096 * 64;
    int*   dout = degp + ((size_t)z * KC + kc) * 4096;
    if (tid < 64) dout[m0 + tid] = sdeg[tid];
#pragma unroll
    for (int mt = 0; mt < 2; mt++)
#pragma unroll
        for (int nt = 0; nt < 4; nt++) {
            size_t row = m0 + wm * 32 + mt * 16 + gid;
            size_t col = wn * 32 + nt * 8 + tig * 2;
#pragma unroll
            for (int e = 0; e < 4; e++) {
                size_t r = row + (size_t)(e >> 1) * 8;
                size_t c = col + (size_t)(e & 1);
                aout[r * 64 + c] = acc[mt][nt][e];
            }
        }
}

// ============================================================================
// Classifier stage 1, fused with aggregation finish — WIDE grid.
// ============================================================================
__global__ void __launch_bounds__(128)
clf_partial(const float* __restrict__ aggp, const int* __restrict__ degp,
            const float* __restrict__ HA, const float* __restrict__ HB,
            const float* __restrict__ Wp,
            const float* __restrict__ w, float* __restrict__ part)
{
    const int L = 4096 * 64;
    const int TOT = 2 * L;
    const int chunk = 256;
    int base = blockIdx.x * chunk;
    const float W00 = Wp[0];
    float s0 = 0.f, s1 = 0.f;
#pragma unroll
    for (int q = 0; q < 2; q++) {
        int i = base + threadIdx.x + q * 128;
        int z = i >= L;
        int li = i - z * L;
        int r = li >> 6;
        const float* ap = aggp + (size_t)z * KC * L;
        const int* dp = degp + (size_t)z * KC * 4096;
        float s = 0.f; int d = 0;
#pragma unroll
        for (int kc = 0; kc < KC; kc++) {
            s += ap[(size_t)kc * L + li];
            d += dp[kc * 4096 + r];
        }
        const float* H = z ? HB : HA;
        float v = d ? s * W00 / (float)d + H[li] : 0.f;
        s0 += v * w[i];
        s1 += v * w[TOT + i];
    }
    __shared__ float sm[4][2];
#pragma unroll
    for (int o = 16; o; o >>= 1) {
        s0 += __shfl_down_sync(0xffffffffu, s0, o);
        s1 += __shfl_down_sync(0xffffffffu, s1, o);
    }
    if ((threadIdx.x & 31) == 0) { sm[threadIdx.x >> 5][0] = s0; sm[threadIdx.x >> 5][1] = s1; }
    __syncthreads();
    if (threadIdx.x == 0) {
        float a = 0.f, b = 0.f;
        for (int i = 0; i < 4; i++) { a += sm[i][0]; b += sm[i][1]; }
        part[blockIdx.x * 2 + 0] = a;
        part[blockIdx.x * 2 + 1] = b;
    }
}

__global__ void clf_final(const float* __restrict__ part, const float* __restrict__ bias,
                          float* __restrict__ out, int nb)
{
    float s0 = 0.f, s1 = 0.f;
    for (int i = threadIdx.x; i < nb; i += blockDim.x) { s0 += part[i * 2]; s1 += part[i * 2 + 1]; }
    __shared__ float sm[8][2];
#pragma unroll
    for (int o = 16; o; o >>= 1) {
        s0 += __shfl_down_sync(0xffffffffu, s0, o);
        s1 += __shfl_down_sync(0xffffffffu, s1, o);
    }
    if ((threadIdx.x & 31) == 0) { sm[threadIdx.x >> 5][0] = s0; sm[threadIdx.x >> 5][1] = s1; }
    __syncthreads();
    if (threadIdx.x == 0) {
        float a = 0.f, b = 0.f;
        for (int i = 0; i < (int)(blockDim.x >> 5); i++) { a += sm[i][0]; b += sm[i][1]; }
        out[0] = a + bias[0];
        out[1] = b + bias[1];
    }
}

// ============================================================================
extern "C" void kernel_launch(void* const* d_in, const int* in_sizes, int n_in,
                              void* d_out, int out_size)
{
    const float* x1    = (const float*)d_in[0];
    const float* x2    = (const float*)d_in[1];
    const int*   adj1  = (const int*)d_in[2];
    const int*   adj2  = (const int*)d_in[3];
    const float* e1_w1 = (const float*)d_in[4];
    const float* e1_b1 = (const float*)d_in[5];
    const float* e1_w2 = (const float*)d_in[6];
    const float* e1_b2 = (const float*)d_in[7];
    const float* e1_w3 = (const float*)d_in[8];
    const float* e1_b3 = (const float*)d_in[9];
    const float* e2_w1 = (const float*)d_in[10];
    const float* e2_b1 = (const float*)d_in[11];
    const float* e2_w2 = (const float*)d_in[12];
    const float* e2_b2 = (const float*)d_in[13];
    const float* e2_w3 = (const float*)d_in[14];
    const float* e2_b3 = (const float*)d_in[15];
    const float* W     = (const float*)d_in[16];
    const float* alpha = (const float*)d_in[17];
    const float* clf_w = (const float*)d_in[18];
    const float* clf_b = (const float*)d_in[19];

    float *fc1p, *fc2p, *hp, *partp, *aggpp;
    __half *w1hp, *hthp;
    int *degpp;
    cudaGetSymbolAddress((void**)&fc1p,  g_fc1);
    cudaGetSymbolAddress((void**)&fc2p,  g_fc2);
    cudaGetSymbolAddress((void**)&hp,    g_h);
    cudaGetSymbolAddress((void**)&hthp,  g_hth);
    cudaGetSymbolAddress((void**)&partp, g_part);
    cudaGetSymbolAddress((void**)&aggpp, g_aggp);
    cudaGetSymbolAddress((void**)&degpp, g_degp);
    cudaGetSymbolAddress((void**)&w1hp,  g_w1h);

    const int FC1_SMEM = (2 * 128 * LDH + 2 * 128 * LDH) * 4;   // 73728 B
    cudaFuncSetAttribute(fc1_h, cudaFuncAttributeMaxDynamicSharedMemorySize, FC1_SMEM);

    // pre-pass: w1 -> RNE fp16
    cvt_w1h<<<2048, 256>>>(e1_w1, e2_w1, w1hp);

    // fc1 (fp16 HMMA, BK=64): grid (nt=2, mt=32, z=2) = 128 CTAs
    fc1_h<<<dim3(2, 32, 2), 256, FC1_SMEM>>>(
        x1, x2, w1hp, e1_b1, e2_b1, fc1p);

    // fc2: [4096,256] x [128,256]^T -> [4096,128]     (split-tf32)
    gemm_tn<64, 64, 32, 2, false, false><<<dim3(64, 2, 2), 128>>>(
        fc1p, fc1p + 4096 * 256, e1_w2, e2_w2, e1_b2, e2_b2,
        fc2p, fc2p + 4096 * 128, nullptr, nullptr, 4096, 128, 256);

    // fc3+relu: [4096,128] x [64,128]^T -> [4096,64] (+ fp16 transpose for agg)
    gemm_tn<64, 64, 32, 2, true, true><<<dim3(64, 1, 2), 128>>>(
        fc2p, fc2p + 4096 * 128, e1_w3, e2_w3, e1_b3, e2_b3,
        hp, hp + 4096 * 64, hthp, hthp + 64 * 4096, 4096, 64, 128);

    // split-K masked aggregation (fp16 HMMA, BK=64)
    agg_part_h<<<dim3(64, KC, 2), 128>>>(
        adj1, adj2, alpha, hthp, hthp + 64 * 4096, aggpp, degpp, 4096);

    // classifier stage 1 (fused agg-finish, wide grid) + final
    clf_partial<<<2048, 128>>>(aggpp, degpp, hp, hp + 4096 * 64, W, clf_w, partp);
    clf_final<<<1, 256>>>(partp, clf_b, (float*)d_out, 2048);

    (void)in_sizes; (void)n_in; (void)out_size;
}

// round 13
// speedup vs baseline: 1.4402x; 1.0291x over previous
#include <cuda_runtime.h>
#include <cuda_fp16.h>
#include <cstdint>

#define DI __device__ __forceinline__

DI unsigned f2t(float x) { unsigned u; asm("cvt.rna.tf32.f32 %0, %1;" : "=r"(u) : "f"(x)); return u; }

DI void mma8(float c[4], const unsigned a[4], const unsigned b[2]) {
    asm("mma.sync.aligned.m16n8k8.row.col.f32.tf32.tf32.f32 "
        "{%0,%1,%2,%3}, {%4,%5,%6,%7}, {%8,%9}, {%0,%1,%2,%3};"
        : "+f"(c[0]), "+f"(c[1]), "+f"(c[2]), "+f"(c[3])
        : "r"(a[0]), "r"(a[1]), "r"(a[2]), "r"(a[3]), "r"(b[0]), "r"(b[1]));
}

DI void mma16h(float c[4], const unsigned a[4], const unsigned b[2]) {
    asm("mma.sync.aligned.m16n8k16.row.col.f32.f16.f16.f32 "
        "{%0,%1,%2,%3}, {%4,%5,%6,%7}, {%8,%9}, {%0,%1,%2,%3};"
        : "+f"(c[0]), "+f"(c[1]), "+f"(c[2]), "+f"(c[3])
        : "r"(a[0]), "r"(a[1]), "r"(a[2]), "r"(a[3]), "r"(b[0]), "r"(b[1]));
}

DI unsigned packh2(float lo, float hi) {
    __half2 h = __floats2half2_rn(lo, hi);
    return *(unsigned*)&h;
}

// ---- scratch (device globals; no allocations allowed) ----
#define KC 8
__device__ float  g_fc1[2][4096 * 256];
__device__ float  g_fc2[2][4096 * 128];
__device__ float  g_h  [2][4096 * 64];
__device__ __half g_hth[2 * 64 * 4096];
__device__ __half g_aggp[2][KC][4096 * 64];
__device__ int    g_degp[2][KC][4096];
__device__ float  g_part[4096];
__device__ __half g_w1h[2 * 256 * 4096];

// ============================================================================
// Pre-pass: w1 -> RNE fp16.
// ============================================================================
__global__ void cvt_w1h(const float* __restrict__ w0, const float* __restrict__ w1,
                        __half* __restrict__ out)
{
    int idx = blockIdx.x * blockDim.x + threadIdx.x;
    int z = idx >= 262144;
    int li = idx - z * 262144;
    float4 v = ((const float4*)(z ? w1 : w0))[li];
    uint2 u;
    u.x = packh2(v.x, v.y);
    u.y = packh2(v.z, v.w);
    ((uint2*)out)[idx] = u;
}

// ============================================================================
// fc1 via FP16 HMMA, BK=64 (R12 best config — unchanged).
// ============================================================================
#define LDH 36
#define ASH(s, r, c) hsm[(s) * (128 * LDH) + (r) * LDH + (c)]
#define BSH(s, r, c) hsm[2 * 128 * LDH + (s) * (128 * LDH) + (r) * LDH + (c)]

__global__ void __launch_bounds__(256)
fc1_h(const float* __restrict__ A0, const float* __restrict__ A1,
      const __half* __restrict__ Bh,
      const float* __restrict__ bias0, const float* __restrict__ bias1,
      float* __restrict__ C)
{
    extern __shared__ unsigned hsm[];
    constexpr int K = 4096, BK = 64;
    const int tid = threadIdx.x, warp = tid >> 5, lane = tid & 31;
    const int wm = warp & 3, wn = warp >> 2;
    const int gid = lane >> 2, tig = lane & 3;
    const int z = blockIdx.z;
    const size_t m0 = (size_t)blockIdx.y * 128;
    const size_t n0 = (size_t)blockIdx.x * 128;
    const int ax = tid & 15, ay = tid >> 4;
    const int bx = tid & 7,  by = tid >> 3;

    const float*  A = (z ? A1 : A0) + (m0 + ay) * (size_t)K + ax * 4;
    const __half* B = Bh + (size_t)z * 256 * 4096 + (n0 + by) * (size_t)K + bx * 8;
    const float* bias = z ? bias1 : bias0;
    float* Cb = C + (size_t)z * 4096 * 256;

    float acc[2][8][4];
#pragma unroll
    for (int i = 0; i < 2; i++)
#pragma unroll
        for (int j = 0; j < 8; j++)
#pragma unroll
            for (int e = 0; e < 4; e++) acc[i][j][e] = 0.f;

    float4 ra[8]; uint4 rb[4];
    const int nIter = K / BK;

    auto ldT = [&](int it) {
        const size_t ko = (size_t)it * BK;
#pragma unroll
        for (int p = 0; p < 8; p++)
            ra[p] = *(const float4*)(A + (size_t)p * 16 * K + ko);
#pragma unroll
        for (int p = 0; p < 4; p++)
            rb[p] = *(const uint4*)(B + (size_t)p * 32 * K + ko);
    };
    auto stT = [&](int s) {
#pragma unroll
        for (int p = 0; p < 8; p++) {
            uint2 t;
            t.x = packh2(ra[p].x, ra[p].y);
            t.y = packh2(ra[p].z, ra[p].w);
            *(uint2*)&ASH(s, p * 16 + ay, ax * 2) = t;
        }
#pragma unroll
        for (int p = 0; p < 4; p++)
            *(uint4*)&BSH(s, p * 32 + by, bx * 4) = rb[p];
    };

    ldT(0); stT(0);
    ldT(1);
    __syncthreads();

    for (int it = 0; it < nIter; it++) {
        const int cur = it & 1;
        if (it + 1 < nIter) stT(cur ^ 1);
        if (it + 2 < nIter) ldT(it + 2);
#pragma unroll
        for (int ks = 0; ks < BK / 16; ks++) {
            unsigned af[2][4], bf[8][2];
#pragma unroll
            for (int mt = 0; mt < 2; mt++) {
                int rr = wm * 32 + mt * 16 + gid;
                af[mt][0] = ASH(cur, rr,     ks * 8 + tig);
                af[mt][1] = ASH(cur, rr + 8, ks * 8 + tig);
                af[mt][2] = ASH(cur, rr,     ks * 8 + tig + 4);
                af[mt][3] = ASH(cur, rr + 8, ks * 8 + tig + 4);
            }
#pragma unroll
            for (int nt = 0; nt < 8; nt++) {
                int cc = wn * 64 + nt * 8 + gid;
                bf[nt][0] = BSH(cur, cc, ks * 8 + tig);
                bf[nt][1] = BSH(cur, cc, ks * 8 + tig + 4);
            }
#pragma unroll
            for (int mt = 0; mt < 2; mt++)
#pragma unroll
                for (int nt = 0; nt < 8; nt++)
                    mma16h(acc[mt][nt], af[mt], bf[nt]);
        }
        __syncthreads();
    }

#pragma unroll
    for (int mt = 0; mt < 2; mt++)
#pragma unroll
        for (int nt = 0; nt < 8; nt++) {
            size_t row = m0 + wm * 32 + mt * 16 + gid;
            size_t col = n0 + wn * 64 + nt * 8 + tig * 2;
#pragma unroll
            for (int e = 0; e < 4; e++) {
                size_t r = row + (size_t)(e >> 1) * 8;
                size_t c = col + (size_t)(e & 1);
                Cb[r * 256 + c] = acc[mt][nt][e] + bias[c];
            }
        }
}

// ============================================================================
// Single-buffered split-tf32 GEMM for fc2/fc3 (unchanged).
// ============================================================================
template<int BM, int BN, int BK, int NS, bool RELU, bool WT>
__global__ void __launch_bounds__((BM / 32) * (BN / 32) * 32)
gemm_tn(const float* __restrict__ A0, const float* __restrict__ A1,
        const float* __restrict__ B0, const float* __restrict__ B1,
        const float* __restrict__ bias0, const float* __restrict__ bias1,
        float* __restrict__ C0, float* __restrict__ C1,
        __half* __restrict__ T0, __half* __restrict__ T1,
        int M, int N, int K)
{
    constexpr int WM = BM / 32, WN = BN / 32, NW = WM * WN, NT = NW * 32;
    constexpr int LD = BK + 4;
    constexpr int F4 = BK / 4, RA = NT / F4, PA = BM / RA, PB = BN / RA;

    const int z = blockIdx.z;
    const float* A = z ? A1 : A0;
    const float* B = z ? B1 : B0;
    const float* bias = z ? bias1 : bias0;
    float* C = z ? C1 : C0;
    __half* T = z ? T1 : T0;

    __shared__ unsigned As[NS][BM][LD];
    __shared__ unsigned Bs[NS][BN][LD];

    const int tid = threadIdx.x, warp = tid >> 5, lane = tid & 31;
    const int wm = warp % WM, wn = warp / WM;
    const int gid = lane >> 2, tig = lane & 3;
    const size_t m0 = (size_t)blockIdx.x * BM;
    const size_t n0 = (size_t)blockIdx.y * BN;
    const int ax = tid % F4, ay = tid / F4;

    float acc[2][4][4];
#pragma unroll
    for (int i = 0; i < 2; i++)
#pragma unroll
        for (int j = 0; j < 4; j++)
#pragma unroll
            for (int e = 0; e < 4; e++) acc[i][j][e] = 0.f;

    float4 ra[PA], rb[PB];
#pragma unroll
    for (int p = 0; p < PA; p++)
        ra[p] = *(const float4*)(A + (m0 + p * RA + ay) * K + ax * 4);
#pragma unroll
    for (int p = 0; p < PB; p++)
        rb[p] = *(const float4*)(B + (n0 + p * RA + ay) * K + ax * 4);

    for (int k0 = 0; k0 < K; k0 += BK) {
#pragma unroll
        for (int p = 0; p < PA; p++) {
            int row = p * RA + ay;
            unsigned h0 = f2t(ra[p].x), h1 = f2t(ra[p].y), h2 = f2t(ra[p].z), h3 = f2t(ra[p].w);
            As[0][row][ax * 4 + 0] = h0; As[0][row][ax * 4 + 1] = h1;
            As[0][row][ax * 4 + 2] = h2; As[0][row][ax * 4 + 3] = h3;
            if (NS == 2) {
                As[NS - 1][row][ax * 4 + 0] = f2t(ra[p].x - __uint_as_float(h0));
                As[NS - 1][row][ax * 4 + 1] = f2t(ra[p].y - __uint_as_float(h1));
                As[NS - 1][row][ax * 4 + 2] = f2t(ra[p].z - __uint_as_float(h2));
                As[NS - 1][row][ax * 4 + 3] = f2t(ra[p].w - __uint_as_float(h3));
            }
        }
#pragma unroll
        for (int p = 0; p < PB; p++) {
            int row = p * RA + ay;
            unsigned h0 = f2t(rb[p].x), h1 = f2t(rb[p].y), h2 = f2t(rb[p].z), h3 = f2t(rb[p].w);
            Bs[0][row][ax * 4 + 0] = h0; Bs[0][row][ax * 4 + 1] = h1;
            Bs[0][row][ax * 4 + 2] = h2; Bs[0][row][ax * 4 + 3] = h3;
            if (NS == 2) {
                Bs[NS - 1][row][ax * 4 + 0] = f2t(rb[p].x - __uint_as_float(h0));
                Bs[NS - 1][row][ax * 4 + 1] = f2t(rb[p].y - __uint_as_float(h1));
                Bs[NS - 1][row][ax * 4 + 2] = f2t(rb[p].z - __uint_as_float(h2));
                Bs[NS - 1][row][ax * 4 + 3] = f2t(rb[p].w - __uint_as_float(h3));
            }
        }
        __syncthreads();

        if (k0 + BK < K) {
#pragma unroll
            for (int p = 0; p < PA; p++)
                ra[p] = *(const float4*)(A + (m0 + p * RA + ay) * K + (k0 + BK) + ax * 4);
#pragma unroll
            for (int p = 0; p < PB; p++)
                rb[p] = *(const float4*)(B + (n0 + p * RA + ay) * K + (k0 + BK) + ax * 4);
        }

#pragma unroll
        for (int ks = 0; ks < BK / 8; ks++) {
            unsigned af[NS][2][4], bf[NS][4][2];
#pragma unroll
            for (int s = 0; s < NS; s++) {
#pragma unroll
                for (int mt = 0; mt < 2; mt++) {
                    int rr = wm * 32 + mt * 16 + gid;
                    af[s][mt][0] = As[s][rr    ][ks * 8 + tig];
                    af[s][mt][1] = As[s][rr + 8][ks * 8 + tig];
                    af[s][mt][2] = As[s][rr    ][ks * 8 + tig + 4];
                    af[s][mt][3] = As[s][rr + 8][ks * 8 + tig + 4];
                }
#pragma unroll
                for (int nt = 0; nt < 4; nt++) {
                    int cc = wn * 32 + nt * 8 + gid;
                    bf[s][nt][0] = Bs[s][cc][ks * 8 + tig];
                    bf[s][nt][1] = Bs[s][cc][ks * 8 + tig + 4];
                }
            }
#pragma unroll
            for (int mt = 0; mt < 2; mt++)
#pragma unroll
                for (int nt = 0; nt < 4; nt++) {
                    mma8(acc[mt][nt], af[0][mt], bf[0][nt]);
                    if (NS == 2) {
                        mma8(acc[mt][nt], af[0][mt], bf[NS - 1][nt]);
                        mma8(acc[mt][nt], af[NS - 1][mt], bf[0][nt]);
                    }
                }
        }
        __syncthreads();
    }

#pragma unroll
    for (int mt = 0; mt < 2; mt++) {
#pragma unroll
        for (int nt = 0; nt < 4; nt++) {
            size_t row = m0 + wm * 32 + mt * 16 + gid;
            size_t col = n0 + wn * 32 + nt * 8 + tig * 2;
#pragma unroll
            for (int e = 0; e < 4; e++) {
                size_t r = row + (size_t)(e >> 1) * 8;
                size_t c = col + (size_t)(e & 1);
                float v = acc[mt][nt][e] + bias[c];
                if (RELU) v = fmaxf(v, 0.f);
                C[r * N + c] = v;
                if (WT) T[c * (size_t)M + r] = __float2half_rn(v);
            }
        }
    }
}

// ============================================================================
// Split-K masked aggregation partial — FP16 HMMA, BK=64.
// GRID REORDERED: x = z (fastest) so (z=0,z=1) CTA pairs with identical
// (m-tile, kc) run adjacently and share alpha reads in L2 (alpha is the SAME
// buffer for both graphs). Partials stored fp16 (agg term ~2% of output).
// ============================================================================
#define LDA 36
__global__ void __launch_bounds__(128)
agg_part_h(const int* __restrict__ adjA, const int* __restrict__ adjB,
           const float* __restrict__ alpha,
           const __half* __restrict__ HtA, const __half* __restrict__ HtB,
           __half* __restrict__ aggp, int* __restrict__ degp, int K)
{
    constexpr int BK = 64;
    __shared__ unsigned Ash[2][64][LDA];
    __shared__ unsigned Bsh[2][64][LDA];
    __shared__ int sdeg[64];

    const int tid = threadIdx.x, warp = tid >> 5, lane = tid & 31;
    const int wm = warp & 1, wn = warp >> 1;
    const int gid = lane >> 2, tig = lane & 3;
    const int z = blockIdx.x;                          // FASTEST axis
    const int kc = blockIdx.z;
    const int* adj = z ? adjB : adjA;
    const __half* Ht = z ? HtB : HtA;
    const int KCH = K / KC;                            // 512
    const size_t kbase = (size_t)kc * KCH;
    const size_t m0 = (size_t)blockIdx.y * 64;
    const int ax = tid & 15, ay = tid >> 4;
    const int bx = tid & 7,  by = tid >> 3;

    if (tid < 64) sdeg[tid] = 0;

    float acc[2][4][4];
#pragma unroll
    for (int i = 0; i < 2; i++)
#pragma unroll
        for (int j = 0; j < 4; j++)
#pragma unroll
            for (int e = 0; e < 4; e++) acc[i][j][e] = 0.f;

    int cnt[8];
#pragma unroll
    for (int p = 0; p < 8; p++) cnt[p] = 0;

    int4 rma[8]; float4 rva[8]; uint4 rb[4];
    const int nIter = KCH / BK;                        // 8

    auto ldA = [&](int it) {
        const size_t ko = kbase + (size_t)it * BK;
#pragma unroll
        for (int p = 0; p < 8; p++) {
            size_t g = (m0 + p * 8 + ay) * (size_t)K + ko + ax * 4;
            rma[p] = *(const int4*)(adj + g);
            rva[p] = *(const float4*)(alpha + g);
        }
#pragma unroll
        for (int p = 0; p < 4; p++)
            rb[p] = *(const uint4*)(Ht + (size_t)(p * 16 + by) * K + ko + bx * 8);
    };
    auto stA = [&](int buf) {
#pragma unroll
        for (int p = 0; p < 8; p++) {
            int row = p * 8 + ay;
            int mx = (rma[p].x == 1), my = (rma[p].y == 1);
            int mz = (rma[p].z == 1), mw = (rma[p].w == 1);
            cnt[p] += mx + my + mz + mw;
            uint2 t;
            t.x = packh2(mx ? rva[p].x : 0.f, my ? rva[p].y : 0.f);
            t.y = packh2(mz ? rva[p].z : 0.f, mw ? rva[p].w : 0.f);
            *(uint2*)&Ash[buf][row][ax * 2] = t;
        }
#pragma unroll
        for (int p = 0; p < 4; p++)
            *(uint4*)&Bsh[buf][p * 16 + by][bx * 4] = rb[p];
    };

    ldA(0); stA(0);
    if (nIter > 1) ldA(1);
    __syncthreads();

    for (int it = 0; it < nIter; it++) {
        const int cur = it & 1;
        if (it + 1 < nIter) stA(cur ^ 1);
        if (it + 2 < nIter) ldA(it + 2);
#pragma unroll
        for (int ks = 0; ks < BK / 16; ks++) {
            unsigned af[2][4], bf[4][2];
#pragma unroll
            for (int mt = 0; mt < 2; mt++) {
                int rr = wm * 32 + mt * 16 + gid;
                af[mt][0] = Ash[cur][rr    ][ks * 8 + tig];
                af[mt][1] = Ash[cur][rr + 8][ks * 8 + tig];
                af[mt][2] = Ash[cur][rr    ][ks * 8 + tig + 4];
                af[mt][3] = Ash[cur][rr + 8][ks * 8 + tig + 4];
            }
#pragma unroll
            for (int nt = 0; nt < 4; nt++) {
                int cc = wn * 32 + nt * 8 + gid;
                bf[nt][0] = Bsh[cur][cc][ks * 8 + tig];
                bf[nt][1] = Bsh[cur][cc][ks * 8 + tig + 4];
            }
#pragma unroll
            for (int mt = 0; mt < 2; mt++)
#pragma unroll
                for (int nt = 0; nt < 4; nt++)
                    mma16h(acc[mt][nt], af[mt], bf[nt]);
        }
        __syncthreads();
    }

#pragma unroll
    for (int p = 0; p < 8; p++) atomicAdd(&sdeg[p * 8 + ay], cnt[p]);
    __syncthreads();

    __half* aout = aggp + ((size_t)z * KC + kc) * 4096 * 64;
    int*    dout = degp + ((size_t)z * KC + kc) * 4096;
    if (tid < 64) dout[m0 + tid] = sdeg[tid];
#pragma unroll
    for (int mt = 0; mt < 2; mt++)
#pragma unroll
        for (int nt = 0; nt < 4; nt++) {
            size_t row = m0 + wm * 32 + mt * 16 + gid;
            size_t col = wn * 32 + nt * 8 + tig * 2;
#pragma unroll
            for (int e = 0; e < 4; e++) {
                size_t r = row + (size_t)(e >> 1) * 8;
                size_t c = col + (size_t)(e & 1);
                aout[r * 64 + c] = __float2half_rn(acc[mt][nt][e]);
            }
        }
}

// ============================================================================
// Classifier stage 1, fused with aggregation finish — WIDE grid; aggp fp16.
// ============================================================================
__global__ void __launch_bounds__(128)
clf_partial(const __half* __restrict__ aggp, const int* __restrict__ degp,
            const float* __restrict__ HA, const float* __restrict__ HB,
            const float* __restrict__ Wp,
            const float* __restrict__ w, float* __restrict__ part)
{
    const int L = 4096 * 64;
    const int TOT = 2 * L;
    const int chunk = 256;
    int base = blockIdx.x * chunk;
    const float W00 = Wp[0];
    float s0 = 0.f, s1 = 0.f;
#pragma unroll
    for (int q = 0; q < 2; q++) {
        int i = base + threadIdx.x + q * 128;
        int z = i >= L;
        int li = i - z * L;
        int r = li >> 6;
        const __half* ap = aggp + (size_t)z * KC * L;
        const int* dp = degp + (size_t)z * KC * 4096;
        float s = 0.f; int d = 0;
#pragma unroll
        for (int kc = 0; kc < KC; kc++) {
            s += __half2float(ap[(size_t)kc * L + li]);
            d += dp[kc * 4096 + r];
        }
        const float* H = z ? HB : HA;
        float v = d ? s * W00 / (float)d + H[li] : 0.f;
        s0 += v * w[i];
        s1 += v * w[TOT + i];
    }
    __shared__ float sm[4][2];
#pragma unroll
    for (int o = 16; o; o >>= 1) {
        s0 += __shfl_down_sync(0xffffffffu, s0, o);
        s1 += __shfl_down_sync(0xffffffffu, s1, o);
    }
    if ((threadIdx.x & 31) == 0) { sm[threadIdx.x >> 5][0] = s0; sm[threadIdx.x >> 5][1] = s1; }
    __syncthreads();
    if (threadIdx.x == 0) {
        float a = 0.f, b = 0.f;
        for (int i = 0; i < 4; i++) { a += sm[i][0]; b += sm[i][1]; }
        part[blockIdx.x * 2 + 0] = a;
        part[blockIdx.x * 2 + 1] = b;
    }
}

__global__ void clf_final(const float* __restrict__ part, const float* __restrict__ bias,
                          float* __restrict__ out, int nb)
{
    float s0 = 0.f, s1 = 0.f;
    for (int i = threadIdx.x; i < nb; i += blockDim.x) { s0 += part[i * 2]; s1 += part[i * 2 + 1]; }
    __shared__ float sm[8][2];
#pragma unroll
    for (int o = 16; o; o >>= 1) {
        s0 += __shfl_down_sync(0xffffffffu, s0, o);
        s1 += __shfl_down_sync(0xffffffffu, s1, o);
    }
    if ((threadIdx.x & 31) == 0) { sm[threadIdx.x >> 5][0] = s0; sm[threadIdx.x >> 5][1] = s1; }
    __syncthreads();
    if (threadIdx.x == 0) {
        float a = 0.f, b = 0.f;
        for (int i = 0; i < (int)(blockDim.x >> 5); i++) { a += sm[i][0]; b += sm[i][1]; }
        out[0] = a + bias[0];
        out[1] = b + bias[1];
    }
}

// ============================================================================
extern "C" void kernel_launch(void* const* d_in, const int* in_sizes, int n_in,
                              void* d_out, int out_size)
{
    const float* x1    = (const float*)d_in[0];
    const float* x2    = (const float*)d_in[1];
    const int*   adj1  = (const int*)d_in[2];
    const int*   adj2  = (const int*)d_in[3];
    const float* e1_w1 = (const float*)d_in[4];
    const float* e1_b1 = (const float*)d_in[5];
    const float* e1_w2 = (const float*)d_in[6];
    const float* e1_b2 = (const float*)d_in[7];
    const float* e1_w3 = (const float*)d_in[8];
    const float* e1_b3 = (const float*)d_in[9];
    const float* e2_w1 = (const float*)d_in[10];
    const float* e2_b1 = (const float*)d_in[11];
    const float* e2_w2 = (const float*)d_in[12];
    const float* e2_b2 = (const float*)d_in[13];
    const float* e2_w3 = (const float*)d_in[14];
    const float* e2_b3 = (const float*)d_in[15];
    const float* W     = (const float*)d_in[16];
    const float* alpha = (const float*)d_in[17];
    const float* clf_w = (const float*)d_in[18];
    const float* clf_b = (const float*)d_in[19];

    float *fc1p, *fc2p, *hp, *partp;
    __half *w1hp, *hthp, *aggpp;
    int *degpp;
    cudaGetSymbolAddress((void**)&fc1p,  g_fc1);
    cudaGetSymbolAddress((void**)&fc2p,  g_fc2);
    cudaGetSymbolAddress((void**)&hp,    g_h);
    cudaGetSymbolAddress((void**)&hthp,  g_hth);
    cudaGetSymbolAddress((void**)&partp, g_part);
    cudaGetSymbolAddress((void**)&aggpp, g_aggp);
    cudaGetSymbolAddress((void**)&degpp, g_degp);
    cudaGetSymbolAddress((void**)&w1hp,  g_w1h);

    const int FC1_SMEM = (2 * 128 * LDH + 2 * 128 * LDH) * 4;   // 73728 B
    cudaFuncSetAttribute(fc1_h, cudaFuncAttributeMaxDynamicSharedMemorySize, FC1_SMEM);

    // pre-pass: w1 -> RNE fp16
    cvt_w1h<<<2048, 256>>>(e1_w1, e2_w1, w1hp);

    // fc1 (fp16 HMMA, BK=64): grid (nt=2, mt=32, z=2) = 128 CTAs
    fc1_h<<<dim3(2, 32, 2), 256, FC1_SMEM>>>(
        x1, x2, w1hp, e1_b1, e2_b1, fc1p);

    // fc2: [4096,256] x [128,256]^T -> [4096,128]     (split-tf32)
    gemm_tn<64, 64, 32, 2, false, false><<<dim3(64, 2, 2), 128>>>(
        fc1p, fc1p + 4096 * 256, e1_w2, e2_w2, e1_b2, e2_b2,
        fc2p, fc2p + 4096 * 128, nullptr, nullptr, 4096, 128, 256);

    // fc3+relu: [4096,128] x [64,128]^T -> [4096,64] (+ fp16 transpose for agg)
    gemm_tn<64, 64, 32, 2, true, true><<<dim3(64, 1, 2), 128>>>(
        fc2p, fc2p + 4096 * 128, e1_w3, e2_w3, e1_b3, e2_b3,
        hp, hp + 4096 * 64, hthp, hthp + 64 * 4096, 4096, 64, 128);

    // split-K masked aggregation (fp16 HMMA, BK=64)
    // grid: x = z (FASTEST -> alpha L2 sharing between graphs), y = m-tile, z = kc
    agg_part_h<<<dim3(2, 64, KC), 128>>>(
        adj1, adj2, alpha, hthp, hthp + 64 * 4096, aggpp, degpp, 4096);

    // classifier stage 1 (fused agg-finish, wide grid) + final
    clf_partial<<<2048, 128>>>(aggpp, degpp, hp, hp + 4096 * 64, W, clf_w, partp);
    clf_final<<<1, 256>>>(partp, clf_b, (float*)d_out, 2048);

    (void)in_sizes; (void)n_in; (void)out_size;
}

// round 14
// speedup vs baseline: 1.4571x; 1.0118x over previous
#include <cuda_runtime.h>
#include <cuda_fp16.h>
#include <cstdint>

#define DI __device__ __forceinline__

DI unsigned f2t(float x) { unsigned u; asm("cvt.rna.tf32.f32 %0, %1;" : "=r"(u) : "f"(x)); return u; }

DI void mma8(float c[4], const unsigned a[4], const unsigned b[2]) {
    asm("mma.sync.aligned.m16n8k8.row.col.f32.tf32.tf32.f32 "
        "{%0,%1,%2,%3}, {%4,%5,%6,%7}, {%8,%9}, {%0,%1,%2,%3};"
        : "+f"(c[0]), "+f"(c[1]), "+f"(c[2]), "+f"(c[3])
        : "r"(a[0]), "r"(a[1]), "r"(a[2]), "r"(a[3]), "r"(b[0]), "r"(b[1]));
}

DI void mma16h(float c[4], const unsigned a[4], const unsigned b[2]) {
    asm("mma.sync.aligned.m16n8k16.row.col.f32.f16.f16.f32 "
        "{%0,%1,%2,%3}, {%4,%5,%6,%7}, {%8,%9}, {%0,%1,%2,%3};"
        : "+f"(c[0]), "+f"(c[1]), "+f"(c[2]), "+f"(c[3])
        : "r"(a[0]), "r"(a[1]), "r"(a[2]), "r"(a[3]), "r"(b[0]), "r"(b[1]));
}

DI unsigned packh2(float lo, float hi) {
    __half2 h = __floats2half2_rn(lo, hi);
    return *(unsigned*)&h;
}

// ---- scratch (device globals; no allocations allowed) ----
#define KC 8
__device__ float  g_fc1[2][4096 * 256];
__device__ float  g_h  [2][4096 * 64];
__device__ __half g_hth[2 * 64 * 4096];
__device__ __half g_aggp[2][KC][4096 * 64];
__device__ int    g_degp[2][KC][4096];
__device__ float  g_part[4096];
__device__ __half g_w1h[2 * 256 * 4096];

// ============================================================================
// Pre-pass: w1 -> RNE fp16.
// ============================================================================
__global__ void cvt_w1h(const float* __restrict__ w0, const float* __restrict__ w1,
                        __half* __restrict__ out)
{
    int idx = blockIdx.x * blockDim.x + threadIdx.x;
    int z = idx >= 262144;
    int li = idx - z * 262144;
    float4 v = ((const float4*)(z ? w1 : w0))[li];
    uint2 u;
    u.x = packh2(v.x, v.y);
    u.y = packh2(v.z, v.w);
    ((uint2*)out)[idx] = u;
}

// ============================================================================
// fc1 via FP16 HMMA, BK=64 (R12 best config — unchanged).
// ============================================================================
#define LDH 36
#define ASH(s, r, c) hsm[(s) * (128 * LDH) + (r) * LDH + (c)]
#define BSH(s, r, c) hsm[2 * 128 * LDH + (s) * (128 * LDH) + (r) * LDH + (c)]

__global__ void __launch_bounds__(256)
fc1_h(const float* __restrict__ A0, const float* __restrict__ A1,
      const __half* __restrict__ Bh,
      const float* __restrict__ bias0, const float* __restrict__ bias1,
      float* __restrict__ C)
{
    extern __shared__ unsigned hsm[];
    constexpr int K = 4096, BK = 64;
    const int tid = threadIdx.x, warp = tid >> 5, lane = tid & 31;
    const int wm = warp & 3, wn = warp >> 2;
    const int gid = lane >> 2, tig = lane & 3;
    const int z = blockIdx.z;
    const size_t m0 = (size_t)blockIdx.y * 128;
    const size_t n0 = (size_t)blockIdx.x * 128;
    const int ax = tid & 15, ay = tid >> 4;
    const int bx = tid & 7,  by = tid >> 3;

    const float*  A = (z ? A1 : A0) + (m0 + ay) * (size_t)K + ax * 4;
    const __half* B = Bh + (size_t)z * 256 * 4096 + (n0 + by) * (size_t)K + bx * 8;
    const float* bias = z ? bias1 : bias0;
    float* Cb = C + (size_t)z * 4096 * 256;

    float acc[2][8][4];
#pragma unroll
    for (int i = 0; i < 2; i++)
#pragma unroll
        for (int j = 0; j < 8; j++)
#pragma unroll
            for (int e = 0; e < 4; e++) acc[i][j][e] = 0.f;

    float4 ra[8]; uint4 rb[4];
    const int nIter = K / BK;

    auto ldT = [&](int it) {
        const size_t ko = (size_t)it * BK;
#pragma unroll
        for (int p = 0; p < 8; p++)
            ra[p] = *(const float4*)(A + (size_t)p * 16 * K + ko);
#pragma unroll
        for (int p = 0; p < 4; p++)
            rb[p] = *(const uint4*)(B + (size_t)p * 32 * K + ko);
    };
    auto stT = [&](int s) {
#pragma unroll
        for (int p = 0; p < 8; p++) {
            uint2 t;
            t.x = packh2(ra[p].x, ra[p].y);
            t.y = packh2(ra[p].z, ra[p].w);
            *(uint2*)&ASH(s, p * 16 + ay, ax * 2) = t;
        }
#pragma unroll
        for (int p = 0; p < 4; p++)
            *(uint4*)&BSH(s, p * 32 + by, bx * 4) = rb[p];
    };

    ldT(0); stT(0);
    ldT(1);
    __syncthreads();

    for (int it = 0; it < nIter; it++) {
        const int cur = it & 1;
        if (it + 1 < nIter) stT(cur ^ 1);
        if (it + 2 < nIter) ldT(it + 2);
#pragma unroll
        for (int ks = 0; ks < BK / 16; ks++) {
            unsigned af[2][4], bf[8][2];
#pragma unroll
            for (int mt = 0; mt < 2; mt++) {
                int rr = wm * 32 + mt * 16 + gid;
                af[mt][0] = ASH(cur, rr,     ks * 8 + tig);
                af[mt][1] = ASH(cur, rr + 8, ks * 8 + tig);
                af[mt][2] = ASH(cur, rr,     ks * 8 + tig + 4);
                af[mt][3] = ASH(cur, rr + 8, ks * 8 + tig + 4);
            }
#pragma unroll
            for (int nt = 0; nt < 8; nt++) {
                int cc = wn * 64 + nt * 8 + gid;
                bf[nt][0] = BSH(cur, cc, ks * 8 + tig);
                bf[nt][1] = BSH(cur, cc, ks * 8 + tig + 4);
            }
#pragma unroll
            for (int mt = 0; mt < 2; mt++)
#pragma unroll
                for (int nt = 0; nt < 8; nt++)
                    mma16h(acc[mt][nt], af[mt], bf[nt]);
        }
        __syncthreads();
    }

#pragma unroll
    for (int mt = 0; mt < 2; mt++)
#pragma unroll
        for (int nt = 0; nt < 8; nt++) {
            size_t row = m0 + wm * 32 + mt * 16 + gid;
            size_t col = n0 + wn * 64 + nt * 8 + tig * 2;
#pragma unroll
            for (int e = 0; e < 4; e++) {
                size_t r = row + (size_t)(e >> 1) * 8;
                size_t c = col + (size_t)(e & 1);
                Cb[r * 256 + c] = acc[mt][nt][e] + bias[c];
            }
        }
}

// ============================================================================
// FUSED fc2+fc3 (+relu, +fp16 transpose): per CTA, 64-row slab.
//   phase 1: fc2[64,128] = A[64,256] @ w2^T + b2      (split-tf32, K=256)
//   phase 2: fc3[64,64]  = fc2 @ w3^T + b3, relu      (split-tf32, K=128,
//            fc2 result staged in smem as tf32 hi/lo)
// 128 thr (4 warps). grid (mt=64, 1, z=2) = 128 CTAs.
// ============================================================================
#define P1LD 68
#define P2LD 132
#define AS1(s, r, c) fsm[(s) * (64 * P1LD) + (r) * P1LD + (c)]
#define BS1(s, r, c) fsm[2 * 64 * P1LD + (s) * (128 * P1LD) + (r) * P1LD + (c)]
#define A2(s, r, c)  fsm[(s) * (64 * P2LD) + (r) * P2LD + (c)]
#define B2(s, r, c)  fsm[2 * 64 * P2LD + (s) * (64 * P2LD) + (r) * P2LD + (c)]

__global__ void __launch_bounds__(128)
fc23(const float* __restrict__ C1in,                    // fc1 out, both graphs
     const float* __restrict__ w2a, const float* __restrict__ w2b,
     const float* __restrict__ b2a, const float* __restrict__ b2b,
     const float* __restrict__ w3a, const float* __restrict__ w3b,
     const float* __restrict__ b3a, const float* __restrict__ b3b,
     float* __restrict__ H, __half* __restrict__ Hth)
{
    extern __shared__ unsigned fsm[];
    const int tid = threadIdx.x, warp = tid >> 5, lane = tid & 31;
    const int wm = warp & 1, wn = warp >> 1;           // 2m x 2n warps
    const int gid = lane >> 2, tig = lane & 3;
    const int z = blockIdx.z;
    const size_t m0 = (size_t)blockIdx.x * 64;

    const float* A  = C1in + (size_t)z * 4096 * 256;
    const float* w2 = z ? w2b : w2a;
    const float* b2 = z ? b2b : b2a;
    const float* w3 = z ? w3b : w3a;
    const float* b3 = z ? b3b : b3a;
    float*  Hc  = H   + (size_t)z * 4096 * 64;
    __half* Htc = Hth + (size_t)z * 64 * 4096;

    const int ax = tid & 15, ay = tid >> 4;            // 16 float4/row, 8 rows/pass

    // ---------------- phase 1: fc2, warp tile 32x64, K=256, BK=64 ----------
    float acc1[2][8][4];
#pragma unroll
    for (int i = 0; i < 2; i++)
#pragma unroll
        for (int j = 0; j < 8; j++)
#pragma unroll
            for (int e = 0; e < 4; e++) acc1[i][j][e] = 0.f;

    for (int k0 = 0; k0 < 256; k0 += 64) {
#pragma unroll
        for (int p = 0; p < 8; p++) {                  // A: 64 rows
            int row = p * 8 + ay;
            float4 v = *(const float4*)(A + (m0 + row) * 256 + k0 + ax * 4);
            unsigned h0 = f2t(v.x), h1 = f2t(v.y), h2 = f2t(v.z), h3 = f2t(v.w);
            AS1(0, row, ax * 4 + 0) = h0; AS1(0, row, ax * 4 + 1) = h1;
            AS1(0, row, ax * 4 + 2) = h2; AS1(0, row, ax * 4 + 3) = h3;
            AS1(1, row, ax * 4 + 0) = f2t(v.x - __uint_as_float(h0));
            AS1(1, row, ax * 4 + 1) = f2t(v.y - __uint_as_float(h1));
            AS1(1, row, ax * 4 + 2) = f2t(v.z - __uint_as_float(h2));
            AS1(1, row, ax * 4 + 3) = f2t(v.w - __uint_as_float(h3));
        }
#pragma unroll
        for (int p = 0; p < 16; p++) {                 // B: 128 rows of w2
            int row = p * 8 + ay;
            float4 v = *(const float4*)(w2 + (size_t)row * 256 + k0 + ax * 4);
            unsigned h0 = f2t(v.x), h1 = f2t(v.y), h2 = f2t(v.z), h3 = f2t(v.w);
            BS1(0, row, ax * 4 + 0) = h0; BS1(0, row, ax * 4 + 1) = h1;
            BS1(0, row, ax * 4 + 2) = h2; BS1(0, row, ax * 4 + 3) = h3;
            BS1(1, row, ax * 4 + 0) = f2t(v.x - __uint_as_float(h0));
            BS1(1, row, ax * 4 + 1) = f2t(v.y - __uint_as_float(h1));
            BS1(1, row, ax * 4 + 2) = f2t(v.z - __uint_as_float(h2));
            BS1(1, row, ax * 4 + 3) = f2t(v.w - __uint_as_float(h3));
        }
        __syncthreads();

#pragma unroll
        for (int ks = 0; ks < 8; ks++) {
            unsigned af[2][2][4], bf[2][8][2];
#pragma unroll
            for (int s = 0; s < 2; s++) {
#pragma unroll
                for (int mt = 0; mt < 2; mt++) {
                    int rr = wm * 32 + mt * 16 + gid;
                    af[s][mt][0] = AS1(s, rr,     ks * 8 + tig);
                    af[s][mt][1] = AS1(s, rr + 8, ks * 8 + tig);
                    af[s][mt][2] = AS1(s, rr,     ks * 8 + tig + 4);
                    af[s][mt][3] = AS1(s, rr + 8, ks * 8 + tig + 4);
                }
#pragma unroll
                for (int nt = 0; nt < 8; nt++) {
                    int cc = wn * 64 + nt * 8 + gid;
                    bf[s][nt][0] = BS1(s, cc, ks * 8 + tig);
                    bf[s][nt][1] = BS1(s, cc, ks * 8 + tig + 4);
                }
            }
#pragma unroll
            for (int mt = 0; mt < 2; mt++)
#pragma unroll
                for (int nt = 0; nt < 8; nt++) {
                    mma8(acc1[mt][nt], af[0][mt], bf[0][nt]);
                    mma8(acc1[mt][nt], af[0][mt], bf[1][nt]);
                    mma8(acc1[mt][nt], af[1][mt], bf[0][nt]);
                }
        }
        __syncthreads();
    }

    // ---------------- stage fc2 result (+b2) into smem as tf32 hi/lo -------
#pragma unroll
    for (int mt = 0; mt < 2; mt++)
#pragma unroll
        for (int nt = 0; nt < 8; nt++) {
#pragma unroll
            for (int e = 0; e < 4; e++) {
                int r = wm * 32 + mt * 16 + gid + (e >> 1) * 8;
                int c = wn * 64 + nt * 8 + tig * 2 + (e & 1);
                float v = acc1[mt][nt][e] + b2[c];
                unsigned hi = f2t(v);
                A2(0, r, c) = hi;
                A2(1, r, c) = f2t(v - __uint_as_float(hi));
            }
        }
    // load w3 [64,128] -> hi/lo smem (32 float4/row, 4 rows/pass, 16 passes)
    {
        const int bx4 = tid & 31, byy = tid >> 5;
#pragma unroll
        for (int p = 0; p < 16; p++) {
            int row = p * 4 + byy;
            float4 v = *(const float4*)(w3 + (size_t)row * 128 + bx4 * 4);
            unsigned h0 = f2t(v.x), h1 = f2t(v.y), h2 = f2t(v.z), h3 = f2t(v.w);
            B2(0, row, bx4 * 4 + 0) = h0; B2(0, row, bx4 * 4 + 1) = h1;
            B2(0, row, bx4 * 4 + 2) = h2; B2(0, row, bx4 * 4 + 3) = h3;
            B2(1, row, bx4 * 4 + 0) = f2t(v.x - __uint_as_float(h0));
            B2(1, row, bx4 * 4 + 1) = f2t(v.y - __uint_as_float(h1));
            B2(1, row, bx4 * 4 + 2) = f2t(v.z - __uint_as_float(h2));
            B2(1, row, bx4 * 4 + 3) = f2t(v.w - __uint_as_float(h3));
        }
    }
    __syncthreads();

    // ---------------- phase 2: fc3, warp tile 32x32, K=128 -----------------
    float acc2[2][4][4];
#pragma unroll
    for (int i = 0; i < 2; i++)
#pragma unroll
        for (int j = 0; j < 4; j++)
#pragma unroll
            for (int e = 0; e < 4; e++) acc2[i][j][e] = 0.f;

#pragma unroll
    for (int ks = 0; ks < 16; ks++) {
        unsigned af[2][2][4], bf[2][4][2];
#pragma unroll
        for (int s = 0; s < 2; s++) {
#pragma unroll
            for (int mt = 0; mt < 2; mt++) {
                int rr = wm * 32 + mt * 16 + gid;
                af[s][mt][0] = A2(s, rr,     ks * 8 + tig);
                af[s][mt][1] = A2(s, rr + 8, ks * 8 + tig);
                af[s][mt][2] = A2(s, rr,     ks * 8 + tig + 4);
                af[s][mt][3] = A2(s, rr + 8, ks * 8 + tig + 4);
            }
#pragma unroll
            for (int nt = 0; nt < 4; nt++) {
                int cc = wn * 32 + nt * 8 + gid;
                bf[s][nt][0] = B2(s, cc, ks * 8 + tig);
                bf[s][nt][1] = B2(s, cc, ks * 8 + tig + 4);
            }
        }
#pragma unroll
        for (int mt = 0; mt < 2; mt++)
#pragma unroll
            for (int nt = 0; nt < 4; nt++) {
                mma8(acc2[mt][nt], af[0][mt], bf[0][nt]);
                mma8(acc2[mt][nt], af[0][mt], bf[1][nt]);
                mma8(acc2[mt][nt], af[1][mt], bf[0][nt]);
            }
    }

    // epilogue: relu, write H (fp32) and transposed fp16 Hth
#pragma unroll
    for (int mt = 0; mt < 2; mt++)
#pragma unroll
        for (int nt = 0; nt < 4; nt++) {
#pragma unroll
            for (int e = 0; e < 4; e++) {
                size_t r = m0 + wm * 32 + mt * 16 + gid + (e >> 1) * 8;
                int c = wn * 32 + nt * 8 + tig * 2 + (e & 1);
                float v = fmaxf(acc2[mt][nt][e] + b3[c], 0.f);
                Hc[r * 64 + c] = v;
                Htc[(size_t)c * 4096 + r] = __float2half_rn(v);
            }
        }
}

// ============================================================================
// Split-K masked aggregation partial — FP16 HMMA, BK=64 (R13 config).
// ============================================================================
#define LDA 36
__global__ void __launch_bounds__(128)
agg_part_h(const int* __restrict__ adjA, const int* __restrict__ adjB,
           const float* __restrict__ alpha,
           const __half* __restrict__ HtA, const __half* __restrict__ HtB,
           __half* __restrict__ aggp, int* __restrict__ degp, int K)
{
    constexpr int BK = 64;
    __shared__ unsigned Ash[2][64][LDA];
    __shared__ unsigned Bsh[2][64][LDA];
    __shared__ int sdeg[64];

    const int tid = threadIdx.x, warp = tid >> 5, lane = tid & 31;
    const int wm = warp & 1, wn = warp >> 1;
    const int gid = lane >> 2, tig = lane & 3;
    const int z = blockIdx.x;                          // FASTEST axis (alpha L2 share)
    const int kc = blockIdx.z;
    const int* adj = z ? adjB : adjA;
    const __half* Ht = z ? HtB : HtA;
    const int KCH = K / KC;
    const size_t kbase = (size_t)kc * KCH;
    const size_t m0 = (size_t)blockIdx.y * 64;
    const int ax = tid & 15, ay = tid >> 4;
    const int bx = tid & 7,  by = tid >> 3;

    if (tid < 64) sdeg[tid] = 0;

    float acc[2][4][4];
#pragma unroll
    for (int i = 0; i < 2; i++)
#pragma unroll
        for (int j = 0; j < 4; j++)
#pragma unroll
            for (int e = 0; e < 4; e++) acc[i][j][e] = 0.f;

    int cnt[8];
#pragma unroll
    for (int p = 0; p < 8; p++) cnt[p] = 0;

    int4 rma[8]; float4 rva[8]; uint4 rb[4];
    const int nIter = KCH / BK;

    auto ldA = [&](int it) {
        const size_t ko = kbase + (size_t)it * BK;
#pragma unroll
        for (int p = 0; p < 8; p++) {
            size_t g = (m0 + p * 8 + ay) * (size_t)K + ko + ax * 4;
            rma[p] = *(const int4*)(adj + g);
            rva[p] = *(const float4*)(alpha + g);
        }
#pragma unroll
        for (int p = 0; p < 4; p++)
            rb[p] = *(const uint4*)(Ht + (size_t)(p * 16 + by) * K + ko + bx * 8);
    };
    auto stA = [&](int buf) {
#pragma unroll
        for (int p = 0; p < 8; p++) {
            int row = p * 8 + ay;
            int mx = (rma[p].x == 1), my = (rma[p].y == 1);
            int mz = (rma[p].z == 1), mw = (rma[p].w == 1);
            cnt[p] += mx + my + mz + mw;
            uint2 t;
            t.x = packh2(mx ? rva[p].x : 0.f, my ? rva[p].y : 0.f);
            t.y = packh2(mz ? rva[p].z : 0.f, mw ? rva[p].w : 0.f);
            *(uint2*)&Ash[buf][row][ax * 2] = t;
        }
#pragma unroll
        for (int p = 0; p < 4; p++)
            *(uint4*)&Bsh[buf][p * 16 + by][bx * 4] = rb[p];
    };

    ldA(0); stA(0);
    if (nIter > 1) ldA(1);
    __syncthreads();

    for (int it = 0; it < nIter; it++) {
        const int cur = it & 1;
        if (it + 1 < nIter) stA(cur ^ 1);
        if (it + 2 < nIter) ldA(it + 2);
#pragma unroll
        for (int ks = 0; ks < BK / 16; ks++) {
            unsigned af[2][4], bf[4][2];
#pragma unroll
            for (int mt = 0; mt < 2; mt++) {
                int rr = wm * 32 + mt * 16 + gid;
                af[mt][0] = Ash[cur][rr    ][ks * 8 + tig];
                af[mt][1] = Ash[cur][rr + 8][ks * 8 + tig];
                af[mt][2] = Ash[cur][rr    ][ks * 8 + tig + 4];
                af[mt][3] = Ash[cur][rr + 8][ks * 8 + tig + 4];
            }
#pragma unroll
            for (int nt = 0; nt < 4; nt++) {
                int cc = wn * 32 + nt * 8 + gid;
                bf[nt][0] = Bsh[cur][cc][ks * 8 + tig];
                bf[nt][1] = Bsh[cur][cc][ks * 8 + tig + 4];
            }
#pragma unroll
            for (int mt = 0; mt < 2; mt++)
#pragma unroll
                for (int nt = 0; nt < 4; nt++)
                    mma16h(acc[mt][nt], af[mt], bf[nt]);
        }
        __syncthreads();
    }

#pragma unroll
    for (int p = 0; p < 8; p++) atomicAdd(&sdeg[p * 8 + ay], cnt[p]);
    __syncthreads();

    __half* aout = aggp + ((size_t)z * KC + kc) * 4096 * 64;
    int*    dout = degp + ((size_t)z * KC + kc) * 4096;
    if (tid < 64) dout[m0 + tid] = sdeg[tid];
#pragma unroll
    for (int mt = 0; mt < 2; mt++)
#pragma unroll
        for (int nt = 0; nt < 4; nt++) {
            size_t row = m0 + wm * 32 + mt * 16 + gid;
            size_t col = wn * 32 + nt * 8 + tig * 2;
#pragma unroll
            for (int e = 0; e < 4; e++) {
                size_t r = row + (size_t)(e >> 1) * 8;
                size_t c = col + (size_t)(e & 1);
                aout[r * 64 + c] = __float2half_rn(acc[mt][nt][e]);
            }
        }
}

// ============================================================================
// Classifier stage 1, fused with aggregation finish — WIDE grid; aggp fp16.
// ============================================================================
__global__ void __launch_bounds__(128)
clf_partial(const __half* __restrict__ aggp, const int* __restrict__ degp,
            const float* __restrict__ HA, const float* __restrict__ HB,
            const float* __restrict__ Wp,
            const float* __restrict__ w, float* __restrict__ part)
{
    const int L = 4096 * 64;
    const int TOT = 2 * L;
    const int chunk = 256;
    int base = blockIdx.x * chunk;
    const float W00 = Wp[0];
    float s0 = 0.f, s1 = 0.f;
#pragma unroll
    for (int q = 0; q < 2; q++) {
        int i = base + threadIdx.x + q * 128;
        int z = i >= L;
        int li = i - z * L;
        int r = li >> 6;
        const __half* ap = aggp + (size_t)z * KC * L;
        const int* dp = degp + (size_t)z * KC * 4096;
        float s = 0.f; int d = 0;
#pragma unroll
        for (int kc = 0; kc < KC; kc++) {
            s += __half2float(ap[(size_t)kc * L + li]);
            d += dp[kc * 4096 + r];
        }
        const float* H = z ? HB : HA;
        float v = d ? s * W00 / (float)d + H[li] : 0.f;
        s0 += v * w[i];
        s1 += v * w[TOT + i];
    }
    __shared__ float sm[4][2];
#pragma unroll
    for (int o = 16; o; o >>= 1) {
        s0 += __shfl_down_sync(0xffffffffu, s0, o);
        s1 += __shfl_down_sync(0xffffffffu, s1, o);
    }
    if ((threadIdx.x & 31) == 0) { sm[threadIdx.x >> 5][0] = s0; sm[threadIdx.x >> 5][1] = s1; }
    __syncthreads();
    if (threadIdx.x == 0) {
        float a = 0.f, b = 0.f;
        for (int i = 0; i < 4; i++) { a += sm[i][0]; b += sm[i][1]; }
        part[blockIdx.x * 2 + 0] = a;
        part[blockIdx.x * 2 + 1] = b;
    }
}

__global__ void clf_final(const float* __restrict__ part, const float* __restrict__ bias,
                          float* __restrict__ out, int nb)
{
    float s0 = 0.f, s1 = 0.f;
    for (int i = threadIdx.x; i < nb; i += blockDim.x) { s0 += part[i * 2]; s1 += part[i * 2 + 1]; }
    __shared__ float sm[8][2];
#pragma unroll
    for (int o = 16; o; o >>= 1) {
        s0 += __shfl_down_sync(0xffffffffu, s0, o);
        s1 += __shfl_down_sync(0xffffffffu, s1, o);
    }
    if ((threadIdx.x & 31) == 0) { sm[threadIdx.x >> 5][0] = s0; sm[threadIdx.x >> 5][1] = s1; }
    __syncthreads();
    if (threadIdx.x == 0) {
        float a = 0.f, b = 0.f;
        for (int i = 0; i < (int)(blockDim.x >> 5); i++) { a += sm[i][0]; b += sm[i][1]; }
        out[0] = a + bias[0];
        out[1] = b + bias[1];
    }
}

// ============================================================================
extern "C" void kernel_launch(void* const* d_in, const int* in_sizes, int n_in,
                              void* d_out, int out_size)
{
    const float* x1    = (const float*)d_in[0];
    const float* x2    = (const float*)d_in[1];
    const int*   adj1  = (const int*)d_in[2];
    const int*   adj2  = (const int*)d_in[3];
    const float* e1_w1 = (const float*)d_in[4];
    const float* e1_b1 = (const float*)d_in[5];
    const float* e1_w2 = (const float*)d_in[6];
    const float* e1_b2 = (const float*)d_in[7];
    const float* e1_w3 = (const float*)d_in[8];
    const float* e1_b3 = (const float*)d_in[9];
    const float* e2_w1 = (const float*)d_in[10];
    const float* e2_b1 = (const float*)d_in[11];
    const float* e2_w2 = (const float*)d_in[12];
    const float* e2_b2 = (const float*)d_in[13];
    const float* e2_w3 = (const float*)d_in[14];
    const float* e2_b3 = (const float*)d_in[15];
    const float* W     = (const float*)d_in[16];
    const float* alpha = (const float*)d_in[17];
    const float* clf_w = (const float*)d_in[18];
    const float* clf_b = (const float*)d_in[19];

    float *fc1p, *hp, *partp;
    __half *w1hp, *hthp, *aggpp;
    int *degpp;
    cudaGetSymbolAddress((void**)&fc1p,  g_fc1);
    cudaGetSymbolAddress((void**)&hp,    g_h);
    cudaGetSymbolAddress((void**)&hthp,  g_hth);
    cudaGetSymbolAddress((void**)&partp, g_part);
    cudaGetSymbolAddress((void**)&aggpp, g_aggp);
    cudaGetSymbolAddress((void**)&degpp, g_degp);
    cudaGetSymbolAddress((void**)&w1hp,  g_w1h);

    const int FC1_SMEM  = (2 * 128 * LDH + 2 * 128 * LDH) * 4;          // 73728 B
    const int FC23_SMEM = (2 * 64 * P2LD + 2 * 64 * P2LD) * 4;          // 135168 B
    cudaFuncSetAttribute(fc1_h, cudaFuncAttributeMaxDynamicSharedMemorySize, FC1_SMEM);
    cudaFuncSetAttribute(fc23,  cudaFuncAttributeMaxDynamicSharedMemorySize, FC23_SMEM);

    // pre-pass: w1 -> RNE fp16
    cvt_w1h<<<2048, 256>>>(e1_w1, e2_w1, w1hp);

    // fc1 (fp16 HMMA, BK=64): grid (nt=2, mt=32, z=2) = 128 CTAs
    fc1_h<<<dim3(2, 32, 2), 256, FC1_SMEM>>>(
        x1, x2, w1hp, e1_b1, e2_b1, fc1p);

    // fused fc2+fc3+relu+transpose: grid (mt=64, 1, z=2) = 128 CTAs
    fc23<<<dim3(64, 1, 2), 128, FC23_SMEM>>>(
        fc1p, e1_w2, e2_w2, e1_b2, e2_b2, e1_w3, e2_w3, e1_b3, e2_b3,
        hp, hthp);

    // split-K masked aggregation (fp16 HMMA, BK=64), z fastest
    agg_part_h<<<dim3(2, 64, KC), 128>>>(
        adj1, adj2, alpha, hthp, hthp + 64 * 4096, aggpp, degpp, 4096);

    // classifier stage 1 (fused agg-finish, wide grid) + final
    clf_partial<<<2048, 128>>>(aggpp, degpp, hp, hp + 4096 * 64, W, clf_w, partp);
    clf_final<<<1, 256>>>(partp, clf_b, (float*)d_out, 2048);

    (void)in_sizes; (void)n_in; (void)out_size;
}

// round 15
// speedup vs baseline: 1.4960x; 1.0267x over previous
#include <cuda_runtime.h>
#include <cuda_fp16.h>
#include <cstdint>

#define DI __device__ __forceinline__

DI unsigned f2t(float x) { unsigned u; asm("cvt.rna.tf32.f32 %0, %1;" : "=r"(u) : "f"(x)); return u; }

DI void mma8(float c[4], const unsigned a[4], const unsigned b[2]) {
    asm("mma.sync.aligned.m16n8k8.row.col.f32.tf32.tf32.f32 "
        "{%0,%1,%2,%3}, {%4,%5,%6,%7}, {%8,%9}, {%0,%1,%2,%3};"
        : "+f"(c[0]), "+f"(c[1]), "+f"(c[2]), "+f"(c[3])
        : "r"(a[0]), "r"(a[1]), "r"(a[2]), "r"(a[3]), "r"(b[0]), "r"(b[1]));
}

DI void mma16h(float c[4], const unsigned a[4], const unsigned b[2]) {
    asm("mma.sync.aligned.m16n8k16.row.col.f32.f16.f16.f32 "
        "{%0,%1,%2,%3}, {%4,%5,%6,%7}, {%8,%9}, {%0,%1,%2,%3};"
        : "+f"(c[0]), "+f"(c[1]), "+f"(c[2]), "+f"(c[3])
        : "r"(a[0]), "r"(a[1]), "r"(a[2]), "r"(a[3]), "r"(b[0]), "r"(b[1]));
}

DI unsigned packh2(float lo, float hi) {
    __half2 h = __floats2half2_rn(lo, hi);
    return *(unsigned*)&h;
}

// ---- scratch (device globals; no allocations allowed) ----
#define KC 8
__device__ float  g_fc1[2][4096 * 256];
__device__ float  g_h  [2][4096 * 64];
__device__ __half g_hth[2 * 64 * 4096];
__device__ __half g_aggp[2][KC][4096 * 64];
__device__ int    g_degp[2][KC][4096];
__device__ float  g_part[4096];
__device__ __half g_w1h[2 * 256 * 4096];

// ============================================================================
// Pre-pass: w1 -> RNE fp16.
// ============================================================================
__global__ void cvt_w1h(const float* __restrict__ w0, const float* __restrict__ w1,
                        __half* __restrict__ out)
{
    int idx = blockIdx.x * blockDim.x + threadIdx.x;
    int z = idx >= 262144;
    int li = idx - z * 262144;
    float4 v = ((const float4*)(z ? w1 : w0))[li];
    uint2 u;
    u.x = packh2(v.x, v.y);
    u.y = packh2(v.z, v.w);
    ((uint2*)out)[idx] = u;
}

// ============================================================================
// fc1 via FP16 HMMA, BK=64.  RETILED: BM=64, BN=256 (full output width per
// CTA -> X read from DRAM exactly ONCE; w1h re-read served by L2).
// 256 thr: 8 warps = 2m x 4n, warp tile 32x64.  Double-buffered.
// grid (mt=64, z=2) = 128 CTAs.
// ============================================================================
#define LDH 36
#define ASH(s, r, c) hsm[(s) * (64 * LDH) + (r) * LDH + (c)]
#define BSH(s, r, c) hsm[2 * 64 * LDH + (s) * (256 * LDH) + (r) * LDH + (c)]

__global__ void __launch_bounds__(256)
fc1_h(const float* __restrict__ A0, const float* __restrict__ A1,
      const __half* __restrict__ Bh,
      const float* __restrict__ bias0, const float* __restrict__ bias1,
      float* __restrict__ C)
{
    extern __shared__ unsigned hsm[];
    constexpr int K = 4096, BK = 64;
    const int tid = threadIdx.x, warp = tid >> 5, lane = tid & 31;
    const int wm = warp & 1, wn = warp >> 1;          // 2 m-warps x 4 n-warps
    const int gid = lane >> 2, tig = lane & 3;
    const int z = blockIdx.y;
    const size_t m0 = (size_t)blockIdx.x * 64;
    const int ax = tid & 15, ay = tid >> 4;           // A: 16 float4/row, 16 rows/pass
    const int bx = tid & 7,  by = tid >> 3;           // B: 8 uint4/row, 32 rows/pass

    const float*  A = (z ? A1 : A0) + (m0 + ay) * (size_t)K + ax * 4;
    const __half* B = Bh + (size_t)z * 256 * 4096 + (size_t)by * K + bx * 8;
    const float* bias = z ? bias1 : bias0;
    float* Cb = C + (size_t)z * 4096 * 256;

    float acc[2][8][4];
#pragma unroll
    for (int i = 0; i < 2; i++)
#pragma unroll
        for (int j = 0; j < 8; j++)
#pragma unroll
            for (int e = 0; e < 4; e++) acc[i][j][e] = 0.f;

    float4 ra[4]; uint4 rb[8];
    const int nIter = K / BK;                          // 64

    auto ldT = [&](int it) {
        const size_t ko = (size_t)it * BK;
#pragma unroll
        for (int p = 0; p < 4; p++)
            ra[p] = *(const float4*)(A + (size_t)p * 16 * K + ko);
#pragma unroll
        for (int p = 0; p < 8; p++)
            rb[p] = *(const uint4*)(B + (size_t)p * 32 * K + ko);
    };
    auto stT = [&](int s) {
#pragma unroll
        for (int p = 0; p < 4; p++) {
            uint2 t;
            t.x = packh2(ra[p].x, ra[p].y);
            t.y = packh2(ra[p].z, ra[p].w);
            *(uint2*)&ASH(s, p * 16 + ay, ax * 2) = t;
        }
#pragma unroll
        for (int p = 0; p < 8; p++)
            *(uint4*)&BSH(s, p * 32 + by, bx * 4) = rb[p];
    };

    ldT(0); stT(0);
    ldT(1);
    __syncthreads();

    for (int it = 0; it < nIter; it++) {
        const int cur = it & 1;
        if (it + 1 < nIter) stT(cur ^ 1);
        if (it + 2 < nIter) ldT(it + 2);
#pragma unroll
        for (int ks = 0; ks < BK / 16; ks++) {         // 4 k16 steps
            unsigned af[2][4], bf[8][2];
#pragma unroll
            for (int mt = 0; mt < 2; mt++) {
                int rr = wm * 32 + mt * 16 + gid;
                af[mt][0] = ASH(cur, rr,     ks * 8 + tig);
                af[mt][1] = ASH(cur, rr + 8, ks * 8 + tig);
                af[mt][2] = ASH(cur, rr,     ks * 8 + tig + 4);
                af[mt][3] = ASH(cur, rr + 8, ks * 8 + tig + 4);
            }
#pragma unroll
            for (int nt = 0; nt < 8; nt++) {
                int cc = wn * 64 + nt * 8 + gid;
                bf[nt][0] = BSH(cur, cc, ks * 8 + tig);
                bf[nt][1] = BSH(cur, cc, ks * 8 + tig + 4);
            }
#pragma unroll
            for (int mt = 0; mt < 2; mt++)
#pragma unroll
                for (int nt = 0; nt < 8; nt++)
                    mma16h(acc[mt][nt], af[mt], bf[nt]);
        }
        __syncthreads();
    }

#pragma unroll
    for (int mt = 0; mt < 2; mt++)
#pragma unroll
        for (int nt = 0; nt < 8; nt++) {
            size_t row = m0 + wm * 32 + mt * 16 + gid;
            size_t col = wn * 64 + nt * 8 + tig * 2;
#pragma unroll
            for (int e = 0; e < 4; e++) {
                size_t r = row + (size_t)(e >> 1) * 8;
                size_t c = col + (size_t)(e & 1);
                Cb[r * 256 + c] = acc[mt][nt][e] + bias[c];
            }
        }
}

// ============================================================================
// FUSED fc2+fc3 (+relu, +fp16 transpose) — R14 config, unchanged.
// ============================================================================
#define P1LD 68
#define P2LD 132
#define AS1(s, r, c) fsm[(s) * (64 * P1LD) + (r) * P1LD + (c)]
#define BS1(s, r, c) fsm[2 * 64 * P1LD + (s) * (128 * P1LD) + (r) * P1LD + (c)]
#define A2(s, r, c)  fsm[(s) * (64 * P2LD) + (r) * P2LD + (c)]
#define B2(s, r, c)  fsm[2 * 64 * P2LD + (s) * (64 * P2LD) + (r) * P2LD + (c)]

__global__ void __launch_bounds__(128)
fc23(const float* __restrict__ C1in,
     const float* __restrict__ w2a, const float* __restrict__ w2b,
     const float* __restrict__ b2a, const float* __restrict__ b2b,
     const float* __restrict__ w3a, const float* __restrict__ w3b,
     const float* __restrict__ b3a, const float* __restrict__ b3b,
     float* __restrict__ H, __half* __restrict__ Hth)
{
    extern __shared__ unsigned fsm[];
    const int tid = threadIdx.x, warp = tid >> 5, lane = tid & 31;
    const int wm = warp & 1, wn = warp >> 1;
    const int gid = lane >> 2, tig = lane & 3;
    const int z = blockIdx.z;
    const size_t m0 = (size_t)blockIdx.x * 64;

    const float* A  = C1in + (size_t)z * 4096 * 256;
    const float* w2 = z ? w2b : w2a;
    const float* b2 = z ? b2b : b2a;
    const float* w3 = z ? w3b : w3a;
    const float* b3 = z ? b3b : b3a;
    float*  Hc  = H   + (size_t)z * 4096 * 64;
    __half* Htc = Hth + (size_t)z * 64 * 4096;

    const int ax = tid & 15, ay = tid >> 4;

    float acc1[2][8][4];
#pragma unroll
    for (int i = 0; i < 2; i++)
#pragma unroll
        for (int j = 0; j < 8; j++)
#pragma unroll
            for (int e = 0; e < 4; e++) acc1[i][j][e] = 0.f;

    for (int k0 = 0; k0 < 256; k0 += 64) {
#pragma unroll
        for (int p = 0; p < 8; p++) {
            int row = p * 8 + ay;
            float4 v = *(const float4*)(A + (m0 + row) * 256 + k0 + ax * 4);
            unsigned h0 = f2t(v.x), h1 = f2t(v.y), h2 = f2t(v.z), h3 = f2t(v.w);
            AS1(0, row, ax * 4 + 0) = h0; AS1(0, row, ax * 4 + 1) = h1;
            AS1(0, row, ax * 4 + 2) = h2; AS1(0, row, ax * 4 + 3) = h3;
            AS1(1, row, ax * 4 + 0) = f2t(v.x - __uint_as_float(h0));
            AS1(1, row, ax * 4 + 1) = f2t(v.y - __uint_as_float(h1));
            AS1(1, row, ax * 4 + 2) = f2t(v.z - __uint_as_float(h2));
            AS1(1, row, ax * 4 + 3) = f2t(v.w - __uint_as_float(h3));
        }
#pragma unroll
        for (int p = 0; p < 16; p++) {
            int row = p * 8 + ay;
            float4 v = *(const float4*)(w2 + (size_t)row * 256 + k0 + ax * 4);
            unsigned h0 = f2t(v.x), h1 = f2t(v.y), h2 = f2t(v.z), h3 = f2t(v.w);
            BS1(0, row, ax * 4 + 0) = h0; BS1(0, row, ax * 4 + 1) = h1;
            BS1(0, row, ax * 4 + 2) = h2; BS1(0, row, ax * 4 + 3) = h3;
            BS1(1, row, ax * 4 + 0) = f2t(v.x - __uint_as_float(h0));
            BS1(1, row, ax * 4 + 1) = f2t(v.y - __uint_as_float(h1));
            BS1(1, row, ax * 4 + 2) = f2t(v.z - __uint_as_float(h2));
            BS1(1, row, ax * 4 + 3) = f2t(v.w - __uint_as_float(h3));
        }
        __syncthreads();

#pragma unroll
        for (int ks = 0; ks < 8; ks++) {
            unsigned af[2][2][4], bf[2][8][2];
#pragma unroll
            for (int s = 0; s < 2; s++) {
#pragma unroll
                for (int mt = 0; mt < 2; mt++) {
                    int rr = wm * 32 + mt * 16 + gid;
                    af[s][mt][0] = AS1(s, rr,     ks * 8 + tig);
                    af[s][mt][1] = AS1(s, rr + 8, ks * 8 + tig);
                    af[s][mt][2] = AS1(s, rr,     ks * 8 + tig + 4);
                    af[s][mt][3] = AS1(s, rr + 8, ks * 8 + tig + 4);
                }
#pragma unroll
                for (int nt = 0; nt < 8; nt++) {
                    int cc = wn * 64 + nt * 8 + gid;
                    bf[s][nt][0] = BS1(s, cc, ks * 8 + tig);
                    bf[s][nt][1] = BS1(s, cc, ks * 8 + tig + 4);
                }
            }
#pragma unroll
            for (int mt = 0; mt < 2; mt++)
#pragma unroll
                for (int nt = 0; nt < 8; nt++) {
                    mma8(acc1[mt][nt], af[0][mt], bf[0][nt]);
                    mma8(acc1[mt][nt], af[0][mt], bf[1][nt]);
                    mma8(acc1[mt][nt], af[1][mt], bf[0][nt]);
                }
        }
        __syncthreads();
    }

#pragma unroll
    for (int mt = 0; mt < 2; mt++)
#pragma unroll
        for (int nt = 0; nt < 8; nt++) {
#pragma unroll
            for (int e = 0; e < 4; e++) {
                int r = wm * 32 + mt * 16 + gid + (e >> 1) * 8;
                int c = wn * 64 + nt * 8 + tig * 2 + (e & 1);
                float v = acc1[mt][nt][e] + b2[c];
                unsigned hi = f2t(v);
                A2(0, r, c) = hi;
                A2(1, r, c) = f2t(v - __uint_as_float(hi));
            }
        }
    {
        const int bx4 = tid & 31, byy = tid >> 5;
#pragma unroll
        for (int p = 0; p < 16; p++) {
            int row = p * 4 + byy;
            float4 v = *(const float4*)(w3 + (size_t)row * 128 + bx4 * 4);
            unsigned h0 = f2t(v.x), h1 = f2t(v.y), h2 = f2t(v.z), h3 = f2t(v.w);
            B2(0, row, bx4 * 4 + 0) = h0; B2(0, row, bx4 * 4 + 1) = h1;
            B2(0, row, bx4 * 4 + 2) = h2; B2(0, row, bx4 * 4 + 3) = h3;
            B2(1, row, bx4 * 4 + 0) = f2t(v.x - __uint_as_float(h0));
            B2(1, row, bx4 * 4 + 1) = f2t(v.y - __uint_as_float(h1));
            B2(1, row, bx4 * 4 + 2) = f2t(v.z - __uint_as_float(h2));
            B2(1, row, bx4 * 4 + 3) = f2t(v.w - __uint_as_float(h3));
        }
    }
    __syncthreads();

    float acc2[2][4][4];
#pragma unroll
    for (int i = 0; i < 2; i++)
#pragma unroll
        for (int j = 0; j < 4; j++)
#pragma unroll
            for (int e = 0; e < 4; e++) acc2[i][j][e] = 0.f;

#pragma unroll
    for (int ks = 0; ks < 16; ks++) {
        unsigned af[2][2][4], bf[2][4][2];
#pragma unroll
        for (int s = 0; s < 2; s++) {
#pragma unroll
            for (int mt = 0; mt < 2; mt++) {
                int rr = wm * 32 + mt * 16 + gid;
                af[s][mt][0] = A2(s, rr,     ks * 8 + tig);
                af[s][mt][1] = A2(s, rr + 8, ks * 8 + tig);
                af[s][mt][2] = A2(s, rr,     ks * 8 + tig + 4);
                af[s][mt][3] = A2(s, rr + 8, ks * 8 + tig + 4);
            }
#pragma unroll
            for (int nt = 0; nt < 4; nt++) {
                int cc = wn * 32 + nt * 8 + gid;
                bf[s][nt][0] = B2(s, cc, ks * 8 + tig);
                bf[s][nt][1] = B2(s, cc, ks * 8 + tig + 4);
            }
        }
#pragma unroll
        for (int mt = 0; mt < 2; mt++)
#pragma unroll
            for (int nt = 0; nt < 4; nt++) {
                mma8(acc2[mt][nt], af[0][mt], bf[0][nt]);
                mma8(acc2[mt][nt], af[0][mt], bf[1][nt]);
                mma8(acc2[mt][nt], af[1][mt], bf[0][nt]);
            }
    }

#pragma unroll
    for (int mt = 0; mt < 2; mt++)
#pragma unroll
        for (int nt = 0; nt < 4; nt++) {
#pragma unroll
            for (int e = 0; e < 4; e++) {
                size_t r = m0 + wm * 32 + mt * 16 + gid + (e >> 1) * 8;
                int c = wn * 32 + nt * 8 + tig * 2 + (e & 1);
                float v = fmaxf(acc2[mt][nt][e] + b3[c], 0.f);
                Hc[r * 64 + c] = v;
                Htc[(size_t)c * 4096 + r] = __float2half_rn(v);
            }
        }
}

// ============================================================================
// Split-K masked aggregation partial — FP16 HMMA, BK=64 (R13 config).
// ============================================================================
#define LDA 36
__global__ void __launch_bounds__(128)
agg_part_h(const int* __restrict__ adjA, const int* __restrict__ adjB,
           const float* __restrict__ alpha,
           const __half* __restrict__ HtA, const __half* __restrict__ HtB,
           __half* __restrict__ aggp, int* __restrict__ degp, int K)
{
    constexpr int BK = 64;
    __shared__ unsigned Ash[2][64][LDA];
    __shared__ unsigned Bsh[2][64][LDA];
    __shared__ int sdeg[64];

    const int tid = threadIdx.x, warp = tid >> 5, lane = tid & 31;
    const int wm = warp & 1, wn = warp >> 1;
    const int gid = lane >> 2, tig = lane & 3;
    const int z = blockIdx.x;
    const int kc = blockIdx.z;
    const int* adj = z ? adjB : adjA;
    const __half* Ht = z ? HtB : HtA;
    const int KCH = K / KC;
    const size_t kbase = (size_t)kc * KCH;
    const size_t m0 = (size_t)blockIdx.y * 64;
    const int ax = tid & 15, ay = tid >> 4;
    const int bx = tid & 7,  by = tid >> 3;

    if (tid < 64) sdeg[tid] = 0;

    float acc[2][4][4];
#pragma unroll
    for (int i = 0; i < 2; i++)
#pragma unroll
        for (int j = 0; j < 4; j++)
#pragma unroll
            for (int e = 0; e < 4; e++) acc[i][j][e] = 0.f;

    int cnt[8];
#pragma unroll
    for (int p = 0; p < 8; p++) cnt[p] = 0;

    int4 rma[8]; float4 rva[8]; uint4 rb[4];
    const int nIter = KCH / BK;

    auto ldA = [&](int it) {
        const size_t ko = kbase + (size_t)it * BK;
#pragma unroll
        for (int p = 0; p < 8; p++) {
            size_t g = (m0 + p * 8 + ay) * (size_t)K + ko + ax * 4;
            rma[p] = *(const int4*)(adj + g);
            rva[p] = *(const float4*)(alpha + g);
        }
#pragma unroll
        for (int p = 0; p < 4; p++)
            rb[p] = *(const uint4*)(Ht + (size_t)(p * 16 + by) * K + ko + bx * 8);
    };
    auto stA = [&](int buf) {
#pragma unroll
        for (int p = 0; p < 8; p++) {
            int row = p * 8 + ay;
            int mx = (rma[p].x == 1), my = (rma[p].y == 1);
            int mz = (rma[p].z == 1), mw = (rma[p].w == 1);
            cnt[p] += mx + my + mz + mw;
            uint2 t;
            t.x = packh2(mx ? rva[p].x : 0.f, my ? rva[p].y : 0.f);
            t.y = packh2(mz ? rva[p].z : 0.f, mw ? rva[p].w : 0.f);
            *(uint2*)&Ash[buf][row][ax * 2] = t;
        }
#pragma unroll
        for (int p = 0; p < 4; p++)
            *(uint4*)&Bsh[buf][p * 16 + by][bx * 4] = rb[p];
    };

    ldA(0); stA(0);
    if (nIter > 1) ldA(1);
    __syncthreads();

    for (int it = 0; it < nIter; it++) {
        const int cur = it & 1;
        if (it + 1 < nIter) stA(cur ^ 1);
        if (it + 2 < nIter) ldA(it + 2);
#pragma unroll
        for (int ks = 0; ks < BK / 16; ks++) {
            unsigned af[2][4], bf[4][2];
#pragma unroll
            for (int mt = 0; mt < 2; mt++) {
                int rr = wm * 32 + mt * 16 + gid;
                af[mt][0] = Ash[cur][rr    ][ks * 8 + tig];
                af[mt][1] = Ash[cur][rr + 8][ks * 8 + tig];
                af[mt][2] = Ash[cur][rr    ][ks * 8 + tig + 4];
                af[mt][3] = Ash[cur][rr + 8][ks * 8 + tig + 4];
            }
#pragma unroll
            for (int nt = 0; nt < 4; nt++) {
                int cc = wn * 32 + nt * 8 + gid;
                bf[nt][0] = Bsh[cur][cc][ks * 8 + tig];
                bf[nt][1] = Bsh[cur][cc][ks * 8 + tig + 4];
            }
#pragma unroll
            for (int mt = 0; mt < 2; mt++)
#pragma unroll
                for (int nt = 0; nt < 4; nt++)
                    mma16h(acc[mt][nt], af[mt], bf[nt]);
        }
        __syncthreads();
    }

#pragma unroll
    for (int p = 0; p < 8; p++) atomicAdd(&sdeg[p * 8 + ay], cnt[p]);
    __syncthreads();

    __half* aout = aggp + ((size_t)z * KC + kc) * 4096 * 64;
    int*    dout = degp + ((size_t)z * KC + kc) * 4096;
    if (tid < 64) dout[m0 + tid] = sdeg[tid];
#pragma unroll
    for (int mt = 0; mt < 2; mt++)
#pragma unroll
        for (int nt = 0; nt < 4; nt++) {
            size_t row = m0 + wm * 32 + mt * 16 + gid;
            size_t col = wn * 32 + nt * 8 + tig * 2;
#pragma unroll
            for (int e = 0; e < 4; e++) {
                size_t r = row + (size_t)(e >> 1) * 8;
                size_t c = col + (size_t)(e & 1);
                aout[r * 64 + c] = __float2half_rn(acc[mt][nt][e]);
            }
        }
}

// ============================================================================
// Classifier stage 1, fused with aggregation finish — WIDE grid; aggp fp16.
// ============================================================================
__global__ void __launch_bounds__(128)
clf_partial(const __half* __restrict__ aggp, const int* __restrict__ degp,
            const float* __restrict__ HA, const float* __restrict__ HB,
            const float* __restrict__ Wp,
            const float* __restrict__ w, float* __restrict__ part)
{
    const int L = 4096 * 64;
    const int TOT = 2 * L;
    const int chunk = 256;
    int base = blockIdx.x * chunk;
    const float W00 = Wp[0];
    float s0 = 0.f, s1 = 0.f;
#pragma unroll
    for (int q = 0; q < 2; q++) {
        int i = base + threadIdx.x + q * 128;
        int z = i >= L;
        int li = i - z * L;
        int r = li >> 6;
        const __half* ap = aggp + (size_t)z * KC * L;
        const int* dp = degp + (size_t)z * KC * 4096;
        float s = 0.f; int d = 0;
#pragma unroll
        for (int kc = 0; kc < KC; kc++) {
            s += __half2float(ap[(size_t)kc * L + li]);
            d += dp[kc * 4096 + r];
        }
        const float* H = z ? HB : HA;
        float v = d ? s * W00 / (float)d + H[li] : 0.f;
        s0 += v * w[i];
        s1 += v * w[TOT + i];
    }
    __shared__ float sm[4][2];
#pragma unroll
    for (int o = 16; o; o >>= 1) {
        s0 += __shfl_down_sync(0xffffffffu, s0, o);
        s1 += __shfl_down_sync(0xffffffffu, s1, o);
    }
    if ((threadIdx.x & 31) == 0) { sm[threadIdx.x >> 5][0] = s0; sm[threadIdx.x >> 5][1] = s1; }
    __syncthreads();
    if (threadIdx.x == 0) {
        float a = 0.f, b = 0.f;
        for (int i = 0; i < 4; i++) { a += sm[i][0]; b += sm[i][1]; }
        part[blockIdx.x * 2 + 0] = a;
        part[blockIdx.x * 2 + 1] = b;
    }
}

__global__ void clf_final(const float* __restrict__ part, const float* __restrict__ bias,
                          float* __restrict__ out, int nb)
{
    float s0 = 0.f, s1 = 0.f;
    for (int i = threadIdx.x; i < nb; i += blockDim.x) { s0 += part[i * 2]; s1 += part[i * 2 + 1]; }
    __shared__ float sm[8][2];
#pragma unroll
    for (int o = 16; o; o >>= 1) {
        s0 += __shfl_down_sync(0xffffffffu, s0, o);
        s1 += __shfl_down_sync(0xffffffffu, s1, o);
    }
    if ((threadIdx.x & 31) == 0) { sm[threadIdx.x >> 5][0] = s0; sm[threadIdx.x >> 5][1] = s1; }
    __syncthreads();
    if (threadIdx.x == 0) {
        float a = 0.f, b = 0.f;
        for (int i = 0; i < (int)(blockDim.x >> 5); i++) { a += sm[i][0]; b += sm[i][1]; }
        out[0] = a + bias[0];
        out[1] = b + bias[1];
    }
}

// ============================================================================
extern "C" void kernel_launch(void* const* d_in, const int* in_sizes, int n_in,
                              void* d_out, int out_size)
{
    const float* x1    = (const float*)d_in[0];
    const float* x2    = (const float*)d_in[1];
    const int*   adj1  = (const int*)d_in[2];
    const int*   adj2  = (const int*)d_in[3];
    const float* e1_w1 = (const float*)d_in[4];
    const float* e1_b1 = (const float*)d_in[5];
    const float* e1_w2 = (const float*)d_in[6];
    const float* e1_b2 = (const float*)d_in[7];
    const float* e1_w3 = (const float*)d_in[8];
    const float* e1_b3 = (const float*)d_in[9];
    const float* e2_w1 = (const float*)d_in[10];
    const float* e2_b1 = (const float*)d_in[11];
    const float* e2_w2 = (const float*)d_in[12];
    const float* e2_b2 = (const float*)d_in[13];
    const float* e2_w3 = (const float*)d_in[14];
    const float* e2_b3 = (const float*)d_in[15];
    const float* W     = (const float*)d_in[16];
    const float* alpha = (const float*)d_in[17];
    const float* clf_w = (const float*)d_in[18];
    const float* clf_b = (const float*)d_in[19];

    float *fc1p, *hp, *partp;
    __half *w1hp, *hthp, *aggpp;
    int *degpp;
    cudaGetSymbolAddress((void**)&fc1p,  g_fc1);
    cudaGetSymbolAddress((void**)&hp,    g_h);
    cudaGetSymbolAddress((void**)&hthp,  g_hth);
    cudaGetSymbolAddress((void**)&partp, g_part);
    cudaGetSymbolAddress((void**)&aggpp, g_aggp);
    cudaGetSymbolAddress((void**)&degpp, g_degp);
    cudaGetSymbolAddress((void**)&w1hp,  g_w1h);

    const int FC1_SMEM  = (2 * 64 * LDH + 2 * 256 * LDH) * 4;           // 92160 B
    const int FC23_SMEM = (2 * 64 * P2LD + 2 * 64 * P2LD) * 4;          // 135168 B
    cudaFuncSetAttribute(fc1_h, cudaFuncAttributeMaxDynamicSharedMemorySize, FC1_SMEM);
    cudaFuncSetAttribute(fc23,  cudaFuncAttributeMaxDynamicSharedMemorySize, FC23_SMEM);

    // pre-pass: w1 -> RNE fp16
    cvt_w1h<<<2048, 256>>>(e1_w1, e2_w1, w1hp);

    // fc1 (fp16 HMMA, BK=64, BN=256 full-width): grid (mt=64, z=2) = 128 CTAs
    fc1_h<<<dim3(64, 2), 256, FC1_SMEM>>>(
        x1, x2, w1hp, e1_b1, e2_b1, fc1p);

    // fused fc2+fc3+relu+transpose: grid (mt=64, 1, z=2) = 128 CTAs
    fc23<<<dim3(64, 1, 2), 128, FC23_SMEM>>>(
        fc1p, e1_w2, e2_w2, e1_b2, e2_b2, e1_w3, e2_w3, e1_b3, e2_b3,
        hp, hthp);

    // split-K masked aggregation (fp16 HMMA, BK=64), z fastest
    agg_part_h<<<dim3(2, 64, KC), 128>>>(
        adj1, adj2, alpha, hthp, hthp + 64 * 4096, aggpp, degpp, 4096);

    // classifier stage 1 (fused agg-finish, wide grid) + final
    clf_partial<<<2048, 128>>>(aggpp, degpp, hp, hp + 4096 * 64, W, clf_w, partp);
    clf_final<<<1, 256>>>(partp, clf_b, (float*)d_out, 2048);

    (void)in_sizes; (void)n_in; (void)out_size;
}